// round 9
// baseline (speedup 1.0000x reference)
#include <cuda_runtime.h>
#include <cuda_bf16.h>
#include <math.h>
#include <stdint.h>

#define HIDC   3072
#define HEADSC 24
#define HDC    128
#define LC     2048
#define LIMGC  1920
#define FFNC   384
#define MLPDC  12288
#define W1N    21504
#define W2K    15360
#define MODN   9216
#define NAUD   128

// ---------------- scratch ----------------
__device__ float d_mod[MODN];
__device__ float d_trm[MODN];
__device__ float d_modp[8][MODN];
__device__ float d_trmp[8][MODN];
__device__ float d_h[(size_t)LC * W1N];
__device__ float d_cat[(size_t)LC * W2K];
__device__ float d_aqkv[(size_t)NAUD * MODN];
__device__ float d_gp[(size_t)3 * LC * HIDC];
__device__ __align__(16) __nv_bfloat16 d_a_hi[(size_t)LC * HIDC];
__device__ __align__(16) __nv_bfloat16 d_a_lo[(size_t)LC * HIDC];
__device__ __align__(16) __nv_bfloat16 d_an_hi[(size_t)NAUD * HIDC];
__device__ __align__(16) __nv_bfloat16 d_an_lo[(size_t)NAUD * HIDC];
__device__ __align__(16) __nv_bfloat16 d_cat_hi[(size_t)LC * W2K];
__device__ __align__(16) __nv_bfloat16 d_cat_lo[(size_t)LC * W2K];
__device__ __align__(16) __nv_bfloat16 d_w1t_hi[(size_t)W1N * HIDC];
__device__ __align__(16) __nv_bfloat16 d_w1t_lo[(size_t)W1N * HIDC];
__device__ __align__(16) __nv_bfloat16 d_w2t_hi[(size_t)HIDC * W2K];
__device__ __align__(16) __nv_bfloat16 d_w2t_lo[(size_t)HIDC * W2K];
__device__ __align__(16) __nv_bfloat16 d_awt_hi[(size_t)MODN * HIDC];
__device__ __align__(16) __nv_bfloat16 d_awt_lo[(size_t)MODN * HIDC];
__device__ __align__(16) __nv_bfloat16 d_q_hi[(size_t)LC * HIDC];
__device__ __align__(16) __nv_bfloat16 d_q_lo[(size_t)LC * HIDC];
__device__ __align__(16) __nv_bfloat16 d_k_hi[(size_t)LC * HIDC];
__device__ __align__(16) __nv_bfloat16 d_k_lo[(size_t)LC * HIDC];
__device__ __align__(16) __nv_bfloat16 d_v_hi[(size_t)LC * HIDC];
__device__ __align__(16) __nv_bfloat16 d_v_lo[(size_t)LC * HIDC];

// ---------------- helpers ----------------
__device__ __forceinline__ uint32_t smem_u32(const void* p) {
    uint32_t a;
    asm("{ .reg .u64 t; cvta.to.shared.u64 t, %1; cvt.u32.u64 %0, t; }" : "=r"(a) : "l"(p));
    return a;
}
__device__ __forceinline__ void ldm_x4(uint32_t* r, uint32_t addr) {
    asm volatile("ldmatrix.sync.aligned.m8n8.x4.shared.b16 {%0,%1,%2,%3}, [%4];"
        : "=r"(r[0]), "=r"(r[1]), "=r"(r[2]), "=r"(r[3]) : "r"(addr));
}
__device__ __forceinline__ void ldm_x4_t(uint32_t* r, uint32_t addr) {
    asm volatile("ldmatrix.sync.aligned.m8n8.x4.trans.shared.b16 {%0,%1,%2,%3}, [%4];"
        : "=r"(r[0]), "=r"(r[1]), "=r"(r[2]), "=r"(r[3]) : "r"(addr));
}
__device__ __forceinline__ void mma16816(float* d, const uint32_t* a, const uint32_t* b) {
    asm volatile("mma.sync.aligned.m16n8k16.row.col.f32.bf16.bf16.f32 "
        "{%0,%1,%2,%3}, {%4,%5,%6,%7}, {%8,%9}, {%0,%1,%2,%3};"
        : "+f"(d[0]), "+f"(d[1]), "+f"(d[2]), "+f"(d[3])
        : "r"(a[0]), "r"(a[1]), "r"(a[2]), "r"(a[3]), "r"(b[0]), "r"(b[1]));
}
__device__ __forceinline__ void cp16(uint32_t dst, const void* src) {
    asm volatile("cp.async.cg.shared.global [%0], [%1], 16;" :: "r"(dst), "l"(src));
}
#define CP_COMMIT() asm volatile("cp.async.commit_group;" ::: "memory")
#define CP_WAIT(n)  asm volatile("cp.async.wait_group %0;" :: "n"(n) : "memory")

__device__ __forceinline__ uint32_t packbf(float a, float b) {
    __nv_bfloat162 t = __floats2bfloat162_rn(a, b);
    return *reinterpret_cast<uint32_t*>(&t);
}
__device__ __forceinline__ uint32_t packlo(float a, float b, uint32_t hi) {
    __nv_bfloat162 h = *reinterpret_cast<__nv_bfloat162*>(&hi);
    return packbf(a - __bfloat162float(h.x), b - __bfloat162float(h.y));
}
__device__ __forceinline__ float gelu_tanh(float x) {
    float x3 = x * x * x;
    return 0.5f * x * (1.f + tanhf(0.7978845608028654f * (x + 0.044715f * x3)));
}
__device__ __forceinline__ void block_reduce2(float& s, float& s2, float* buf) {
    int tid = threadIdx.x, lane = tid & 31, w = tid >> 5;
#pragma unroll
    for (int o = 16; o > 0; o >>= 1) {
        s  += __shfl_xor_sync(0xffffffffu, s,  o);
        s2 += __shfl_xor_sync(0xffffffffu, s2, o);
    }
    if (lane == 0) { buf[w] = s; buf[32 + w] = s2; }
    __syncthreads();
    if (tid == 0) {
        float a = 0.f, b = 0.f;
#pragma unroll
        for (int i = 0; i < 8; i++) { a += buf[i]; b += buf[32 + i]; }
        buf[0] = a; buf[32] = b;
    }
    __syncthreads();
    s = buf[0]; s2 = buf[32];
}
// vectorized hi/lo split stores
__device__ __forceinline__ void split_store4(__nv_bfloat16* hi, __nv_bfloat16* lo, size_t i, float4 v) {
    __nv_bfloat162 h0 = __floats2bfloat162_rn(v.x, v.y);
    __nv_bfloat162 h1 = __floats2bfloat162_rn(v.z, v.w);
    *(uint2*)&hi[i] = make_uint2(*(uint32_t*)&h0, *(uint32_t*)&h1);
    __nv_bfloat162 l0 = __floats2bfloat162_rn(v.x - __bfloat162float(h0.x), v.y - __bfloat162float(h0.y));
    __nv_bfloat162 l1 = __floats2bfloat162_rn(v.z - __bfloat162float(h1.x), v.w - __bfloat162float(h1.y));
    *(uint2*)&lo[i] = make_uint2(*(uint32_t*)&l0, *(uint32_t*)&l1);
}
__device__ __forceinline__ void split_store2(__nv_bfloat16* hi, __nv_bfloat16* lo, size_t i, float a, float b) {
    __nv_bfloat162 h = __floats2bfloat162_rn(a, b);
    *(uint32_t*)&hi[i] = *(uint32_t*)&h;
    __nv_bfloat162 l = __floats2bfloat162_rn(a - __bfloat162float(h.x), b - __bfloat162float(h.y));
    *(uint32_t*)&lo[i] = *(uint32_t*)&l;
}

// ---------------- transpose + bf16 split: W[K,N] -> out[N,K]; block (8,32) ----------------
__global__ void transpose_conv(const float* __restrict__ W, __nv_bfloat16* __restrict__ hi,
                               __nv_bfloat16* __restrict__ lo, int K, int N) {
    __shared__ float t[32][36];
    int n0 = blockIdx.x * 32, k0 = blockIdx.y * 32;
    int tx = threadIdx.x;   // 0..7
    int ty = threadIdx.y;   // 0..31
    float4 v = *(const float4*)&W[(size_t)(k0 + ty) * N + n0 + tx * 4];
    t[ty][tx * 4 + 0] = v.x; t[ty][tx * 4 + 1] = v.y;
    t[ty][tx * 4 + 2] = v.z; t[ty][tx * 4 + 3] = v.w;
    __syncthreads();
    float4 o = make_float4(t[tx * 4 + 0][ty], t[tx * 4 + 1][ty],
                           t[tx * 4 + 2][ty], t[tx * 4 + 3][ty]);
    split_store4(hi, lo, (size_t)(n0 + ty) * K + k0 + tx * 4, o);
}

// ---------------- mod partials ----------------
__global__ void mod_part(const float* __restrict__ vec, const float* __restrict__ trv,
                         const float* __restrict__ mw) {
    __shared__ float sv[384], st[384];
    __shared__ float part[2][4][128];
    int tid = threadIdx.x, by = blockIdx.y;
    if (tid < 384) {
        int k = by * 384 + tid;
        float a = vec[k]; sv[tid] = a / (1.f + expf(-a));
        float b = trv[k]; st[tid] = b / (1.f + expf(-b));
    }
    __syncthreads();
    int jl = tid & 127, sl = tid >> 7;
    int j = blockIdx.x * 128 + jl;
    float a0 = 0.f, a1 = 0.f;
    int kend = (sl + 1) * 96;
    for (int kl = sl * 96; kl < kend; kl++) {
        float w = mw[(size_t)(by * 384 + kl) * MODN + j];
        a0 = fmaf(sv[kl], w, a0);
        a1 = fmaf(st[kl], w, a1);
    }
    part[0][sl][jl] = a0; part[1][sl][jl] = a1;
    __syncthreads();
    if (tid < 128) {
        int jj = blockIdx.x * 128 + tid;
        d_modp[by][jj] = part[0][0][tid] + part[0][1][tid] + part[0][2][tid] + part[0][3][tid];
    } else if (tid < 256) {
        int t = tid - 128, jj = blockIdx.x * 128 + t;
        d_trmp[by][jj] = part[1][0][t] + part[1][1][t] + part[1][2][t] + part[1][3][t];
    }
}
__global__ void mod_reduce(const float* __restrict__ mb) {
    int j = blockIdx.x * 256 + threadIdx.x;
    float s0 = mb[j], s1 = mb[j];
#pragma unroll
    for (int p = 0; p < 8; p++) { s0 += d_modp[p][j]; s1 += d_trmp[p][j]; }
    d_mod[j] = s0; d_trm[j] = s1;
}

// ---------------- LN + modulate -> bf16 hi/lo ----------------
__global__ void ln_mod_kernel(const float* __restrict__ x) {
    int row = blockIdx.x, tid = threadIdx.x;
    const float* xr = x + (size_t)row * HIDC;
    float s = 0.f, s2 = 0.f;
    for (int j = tid * 4; j < HIDC; j += 1024) {
        float4 v = *(const float4*)&xr[j];
        s  += v.x + v.y + v.z + v.w;
        s2 += v.x*v.x + v.y*v.y + v.z*v.z + v.w*v.w;
    }
    __shared__ float buf[64];
    block_reduce2(s, s2, buf);
    float mean = s * (1.f / HIDC);
    float inv = rsqrtf(s2 * (1.f / HIDC) - mean * mean + 1e-6f);
    const float* mv = (row < FFNC) ? d_trm : d_mod;
    for (int j = tid * 4; j < HIDC; j += 1024) {
        float4 v  = *(const float4*)&xr[j];
        float4 sc = *(const float4*)&mv[HIDC + j];
        float4 sh = *(const float4*)&mv[j];
        float4 o;
        o.x = (v.x - mean) * inv * (1.f + sc.x) + sh.x;
        o.y = (v.y - mean) * inv * (1.f + sc.y) + sh.y;
        o.z = (v.z - mean) * inv * (1.f + sc.z) + sh.z;
        o.w = (v.w - mean) * inv * (1.f + sc.w) + sh.w;
        split_store4(d_a_hi, d_a_lo, (size_t)row * HIDC + j, o);
    }
}

// ---------------- audio LN -> bf16 hi/lo ----------------
__global__ void ln_plain_kernel(const float* __restrict__ a) {
    int row = blockIdx.x, tid = threadIdx.x;
    const float* xr = a + (size_t)row * HIDC;
    float s = 0.f, s2 = 0.f;
    for (int j = tid * 4; j < HIDC; j += 1024) {
        float4 v = *(const float4*)&xr[j];
        s  += v.x + v.y + v.z + v.w;
        s2 += v.x*v.x + v.y*v.y + v.z*v.z + v.w*v.w;
    }
    __shared__ float buf[64];
    block_reduce2(s, s2, buf);
    float mean = s * (1.f / HIDC);
    float inv = rsqrtf(s2 * (1.f / HIDC) - mean * mean + 1e-6f);
    for (int j = tid * 4; j < HIDC; j += 1024) {
        float4 v = *(const float4*)&xr[j];
        float4 o = make_float4((v.x - mean) * inv, (v.y - mean) * inv,
                               (v.z - mean) * inv, (v.w - mean) * inv);
        split_store4(d_an_hi, d_an_lo, (size_t)row * HIDC + j, o);
    }
}

// ---------------- attn region of cat: fp32 -> bf16 hi/lo ----------------
__global__ void cat_conv_kernel() {
    size_t i = ((size_t)blockIdx.x * 256 + threadIdx.x) * 4;
    int row = (int)(i / HIDC), col = (int)(i % HIDC);
    size_t b = (size_t)row * W2K + col;
    float4 v = *(const float4*)&d_cat[b];
    split_store4(d_cat_hi, d_cat_lo, b, v);
}

// ---------------- GEMM2 combine ----------------
__global__ void gemm2_combine(const float* __restrict__ bias, const float* __restrict__ resid,
                              float* __restrict__ out) {
    size_t i = ((size_t)blockIdx.x * 256 + threadIdx.x) * 4;
    int m = (int)(i / HIDC), n = (int)(i % HIDC);
    const float* gv = (m < FFNC) ? d_trm : d_mod;
    float4 p0 = *(const float4*)&d_gp[i];
    float4 p1 = *(const float4*)&d_gp[(size_t)LC * HIDC + i];
    float4 p2 = *(const float4*)&d_gp[(size_t)2 * LC * HIDC + i];
    float4 bb = *(const float4*)&bias[n];
    float4 gg = *(const float4*)&gv[2 * HIDC + n];
    float4 rr = *(const float4*)&resid[i];
    float4 o;
    o.x = rr.x + (p0.x + p1.x + p2.x + bb.x) * gg.x;
    o.y = rr.y + (p0.y + p1.y + p2.y + bb.y) * gg.y;
    o.z = rr.z + (p0.z + p1.z + p2.z + bb.z) * gg.z;
    o.w = rr.w + (p0.w + p1.w + p2.w + bb.w) * gg.w;
    *(float4*)&out[i] = o;
}

// ---------------- big HMMA GEMM: 256x128 CTA, 64x64 warp, BK=64, 2 stages ----------------
template<int MODE>
__global__ void __launch_bounds__(256, 1) hmma_gemm_big(
        const __nv_bfloat16* __restrict__ Ahi, const __nv_bfloat16* __restrict__ Alo,
        const __nv_bfloat16* __restrict__ Bhi, const __nv_bfloat16* __restrict__ Blo,
        const float* __restrict__ bias, float* __restrict__ C,
        int M, int N, int K) {
    extern __shared__ char smraw[];
    const int tid = threadIdx.x;
    const int lane = tid & 31, wid = tid >> 5;
    const int bm = blockIdx.x * 256, bn = blockIdx.y * 128;
    const int wm = wid & 3, wn = wid >> 2;
    const int Kper = K / gridDim.z;
    const int ko = blockIdx.z * Kper;
    const uint32_t sbase = smem_u32(smraw);
    const __nv_bfloat16* srcs[4] = {
        Ahi + (size_t)bm * K + ko, Alo + (size_t)bm * K + ko,
        Bhi + (size_t)bn * K + ko, Blo + (size_t)bn * K + ko };

    float acc[4][8][4];
#pragma unroll
    for (int a = 0; a < 4; a++)
#pragma unroll
        for (int b = 0; b < 8; b++)
#pragma unroll
            for (int c = 0; c < 4; c++) acc[a][b][c] = 0.f;

    const int NC = Kper >> 6;
#pragma unroll
    for (int i = 0; i < 24; i++) {
        int id = tid + i * 256;
        if (id < 4096) {
            int op = id >> 11, rem = id & 2047, r = rem >> 3, q = rem & 7;
            cp16(sbase + op * 36864 + r * 144 + q * 16, srcs[op] + (size_t)r * K + q * 8);
        } else {
            int t = id - 4096, op = t >> 10, rem = t & 1023, r = rem >> 3, q = rem & 7;
            cp16(sbase + 73728 + op * 18432 + r * 144 + q * 16, srcs[2 + op] + (size_t)r * K + q * 8);
        }
    }
    CP_COMMIT();

    for (int c = 0; c < NC; c++) {
        const int stage = c & 1;
        if (c + 1 < NC) {
            const int kc = (c + 1) << 6;
            const uint32_t db = sbase + (stage ^ 1) * 110592;
#pragma unroll
            for (int i = 0; i < 24; i++) {
                int id = tid + i * 256;
                if (id < 4096) {
                    int op = id >> 11, rem = id & 2047, r = rem >> 3, q = rem & 7;
                    cp16(db + op * 36864 + r * 144 + q * 16, srcs[op] + (size_t)r * K + kc + q * 8);
                } else {
                    int t = id - 4096, op = t >> 10, rem = t & 1023, r = rem >> 3, q = rem & 7;
                    cp16(db + 73728 + op * 18432 + r * 144 + q * 16, srcs[2 + op] + (size_t)r * K + kc + q * 8);
                }
            }
            CP_COMMIT();
            CP_WAIT(1);
        } else {
            CP_WAIT(0);
        }
        __syncthreads();
        const uint32_t base = sbase + stage * 110592;
#pragma unroll
        for (int kk = 0; kk < 4; kk++) {
            uint32_t afr[2][4][4];
            uint32_t bfr[2][4][4];
            const uint32_t aoff = (uint32_t)(wm * 64 + (lane & 15)) * 144 + kk * 32 + (lane >> 4) * 16;
#pragma unroll
            for (int op = 0; op < 2; op++)
#pragma unroll
                for (int mi = 0; mi < 4; mi++)
                    ldm_x4(afr[op][mi], base + op * 36864 + aoff + mi * 16 * 144);
            const uint32_t boff = (uint32_t)(wn * 64 + ((lane >> 4) & 1) * 8 + (lane & 7)) * 144
                                  + kk * 32 + ((lane >> 3) & 1) * 16;
#pragma unroll
            for (int op = 0; op < 2; op++)
#pragma unroll
                for (int ng = 0; ng < 4; ng++)
                    ldm_x4(bfr[op][ng], base + 73728 + op * 18432 + boff + ng * 16 * 144);
#pragma unroll
            for (int cmb = 0; cmb < 3; cmb++) {
                const int ao = (cmb == 2) ? 1 : 0;
                const int bo = (cmb == 1) ? 1 : 0;
#pragma unroll
                for (int mi = 0; mi < 4; mi++)
#pragma unroll
                    for (int ng = 0; ng < 4; ng++) {
                        mma16816(acc[mi][ng * 2 + 0], afr[ao][mi], &bfr[bo][ng][0]);
                        mma16816(acc[mi][ng * 2 + 1], afr[ao][mi], &bfr[bo][ng][2]);
                    }
            }
        }
        __syncthreads();
    }
    const int gid = lane >> 2, tq = (lane & 3) << 1;
    float* Cz = (MODE == 3) ? (C + (size_t)blockIdx.z * M * N) : C;
#pragma unroll
    for (int mi = 0; mi < 4; mi++) {
#pragma unroll
        for (int half = 0; half < 2; half++) {
            const int m = bm + wm * 64 + mi * 16 + half * 8 + gid;
#pragma unroll
            for (int ni = 0; ni < 8; ni++) {
                const int n = bn + wn * 64 + ni * 8 + tq;
                if (MODE == 3) {
                    *(float2*)&Cz[(size_t)m * N + n] =
                        make_float2(acc[mi][ni][half * 2 + 0], acc[mi][ni][half * 2 + 1]);
                } else {
                    float v0 = acc[mi][ni][half * 2 + 0] + bias[n];
                    float v1 = acc[mi][ni][half * 2 + 1] + bias[n + 1];
                    if (n < 2 * HIDC) {
                        *(float2*)&Cz[(size_t)m * W1N + n] = make_float2(v0, v1);
                    } else if (n < 3 * HIDC) {
                        size_t idx = (size_t)m * HIDC + (n - 2 * HIDC);
                        split_store2(d_v_hi, d_v_lo, idx, v0, v1);
                    } else {
                        size_t idx = (size_t)m * W2K + (n - 2 * HIDC);
                        split_store2(d_cat_hi, d_cat_lo, idx, gelu_tanh(v0), gelu_tanh(v1));
                    }
                }
            }
        }
    }
}

// ---------------- small HMMA GEMM (128x128) for audio path ----------------
__global__ void __launch_bounds__(256, 1) hmma_gemm(
        const __nv_bfloat16* __restrict__ Ahi, const __nv_bfloat16* __restrict__ Alo,
        const __nv_bfloat16* __restrict__ Bhi, const __nv_bfloat16* __restrict__ Blo,
        const float* __restrict__ bias, float* __restrict__ C,
        int M, int N, int K) {
    extern __shared__ char smraw[];
    const int tid = threadIdx.x;
    const int lane = tid & 31, wid = tid >> 5;
    const int bm = blockIdx.x * 128, bn = blockIdx.y * 128;
    const int wm = wid & 3, wn = wid >> 2;
    const uint32_t sbase = smem_u32(smraw);
    const __nv_bfloat16* srcs[4] = {
        Ahi + (size_t)bm * K, Alo + (size_t)bm * K,
        Bhi + (size_t)bn * K, Blo + (size_t)bn * K };
    float acc[2][8][4];
#pragma unroll
    for (int a = 0; a < 2; a++)
#pragma unroll
        for (int b = 0; b < 8; b++)
#pragma unroll
            for (int c = 0; c < 4; c++) acc[a][b][c] = 0.f;
    const int NC = K >> 5;
    {
#pragma unroll
        for (int i = 0; i < 8; i++) {
            int id = tid + i * 256;
            int op = id >> 9, rem = id & 511;
            int r = rem >> 2, q = rem & 3;
            cp16(sbase + op * 10240 + r * 80 + q * 16, srcs[op] + (size_t)r * K + q * 8);
        }
        CP_COMMIT();
    }
    for (int c = 0; c < NC; c++) {
        const int stage = c & 1;
        if (c + 1 < NC) {
            const int kc = (c + 1) << 5;
            const uint32_t db = sbase + (stage ^ 1) * 40960;
#pragma unroll
            for (int i = 0; i < 8; i++) {
                int id = tid + i * 256;
                int op = id >> 9, rem = id & 511;
                int r = rem >> 2, q = rem & 3;
                cp16(db + op * 10240 + r * 80 + q * 16, srcs[op] + (size_t)r * K + kc + q * 8);
            }
            CP_COMMIT();
            CP_WAIT(1);
        } else {
            CP_WAIT(0);
        }
        __syncthreads();
        const uint32_t base = sbase + stage * 40960;
#pragma unroll
        for (int kk = 0; kk < 2; kk++) {
            uint32_t afr[2][2][4];
            uint32_t bfr[2][4][4];
            const uint32_t aoff = (uint32_t)(wm * 32 + (lane & 15)) * 80 + kk * 32 + (lane >> 4) * 16;
#pragma unroll
            for (int op = 0; op < 2; op++)
#pragma unroll
                for (int mi = 0; mi < 2; mi++)
                    ldm_x4(afr[op][mi], base + op * 10240 + aoff + mi * 16 * 80);
            const uint32_t boff = (uint32_t)(wn * 64 + ((lane >> 4) & 1) * 8 + (lane & 7)) * 80
                                  + kk * 32 + ((lane >> 3) & 1) * 16;
#pragma unroll
            for (int op = 0; op < 2; op++)
#pragma unroll
                for (int ng = 0; ng < 4; ng++)
                    ldm_x4(bfr[op][ng], base + 20480 + op * 10240 + boff + ng * 16 * 80);
#pragma unroll
            for (int cmb = 0; cmb < 3; cmb++) {
                const int ao = (cmb == 2) ? 1 : 0;
                const int bo = (cmb == 1) ? 1 : 0;
#pragma unroll
                for (int mi = 0; mi < 2; mi++)
#pragma unroll
                    for (int ng = 0; ng < 4; ng++) {
                        mma16816(acc[mi][ng * 2 + 0], afr[ao][mi], &bfr[bo][ng][0]);
                        mma16816(acc[mi][ng * 2 + 1], afr[ao][mi], &bfr[bo][ng][2]);
                    }
            }
        }
        __syncthreads();
    }
    const int gid = lane >> 2, tq = (lane & 3) << 1;
#pragma unroll
    for (int mi = 0; mi < 2; mi++) {
        const int m0 = bm + wm * 32 + mi * 16 + gid;
        const int m1 = m0 + 8;
#pragma unroll
        for (int ni = 0; ni < 8; ni++) {
            const int n = bn + wn * 64 + ni * 8 + tq;
            const float b0 = bias[n], b1 = bias[n + 1];
            size_t off0 = (size_t)m0 * N + n;
            size_t off1 = (size_t)m1 * N + n;
            *(float2*)&C[off0] = make_float2(acc[mi][ni][0] + b0, acc[mi][ni][1] + b1);
            *(float2*)&C[off1] = make_float2(acc[mi][ni][2] + b0, acc[mi][ni][3] + b1);
        }
    }
}

// ---------------- RMS(q,k)+RoPE ----------------
__global__ void qkv_kernel(const float* __restrict__ qw, const float* __restrict__ kw,
                           const float* __restrict__ fcos, const float* __restrict__ fsin) {
    int gwarp = blockIdx.x * 4 + (threadIdx.x >> 5);
    int lane = threadIdx.x & 31;
    int tok = gwarp / HEADSC, head = gwarp % HEADSC;
    float* base = d_h + (size_t)tok * W1N + head * HDC;
    size_t bidx = (size_t)tok * HIDC + head * HDC + lane * 4;
    bool rope = tok < LIMGC;
    float4 c = make_float4(0,0,0,0), sn = make_float4(0,0,0,0);
    if (rope) {
        c  = *(const float4*)&fcos[tok * HDC + lane * 4];
        sn = *(const float4*)&fsin[tok * HDC + lane * 4];
    }
#pragma unroll
    for (int which = 0; which < 2; which++) {
        float* p = base + which * HIDC;
        const float* w = which ? kw : qw;
        float4 v = *(float4*)&p[lane * 4];
        float ss = v.x*v.x + v.y*v.y + v.z*v.z + v.w*v.w;
#pragma unroll
        for (int o = 16; o > 0; o >>= 1) ss += __shfl_xor_sync(0xffffffffu, ss, o);
        float inv = rsqrtf(ss * (1.f / HDC) + 1e-6f);
        float4 ww = *(const float4*)&w[lane * 4];
        v.x *= inv * ww.x; v.y *= inv * ww.y; v.z *= inv * ww.z; v.w *= inv * ww.w;
        if (rope) {
            float nx = v.x * c.x - v.y * sn.x;
            float ny = v.y * c.x + v.x * sn.x;
            float nz = v.z * c.z - v.w * sn.z;
            float nw = v.w * c.z + v.z * sn.z;
            v = make_float4(nx, ny, nz, nw);
        }
        __nv_bfloat16* hi = which ? d_k_hi : d_q_hi;
        __nv_bfloat16* lo = which ? d_k_lo : d_q_lo;
        split_store4(hi, lo, bidx, v);
        if (which == 0) *(float4*)&p[lane * 4] = v;
    }
}

__global__ void akrms_kernel(const float* __restrict__ kw) {
    int gwarp = blockIdx.x * 4 + (threadIdx.x >> 5);
    int lane = threadIdx.x & 31;
    int tok = gwarp / HEADSC, head = gwarp % HEADSC;
    float* p = d_aqkv + (size_t)tok * MODN + HIDC + head * HDC;
    float4 v = *(float4*)&p[lane * 4];
    float ss = v.x*v.x + v.y*v.y + v.z*v.z + v.w*v.w;
#pragma unroll
    for (int o = 16; o > 0; o >>= 1) ss += __shfl_xor_sync(0xffffffffu, ss, o);
    float inv = rsqrtf(ss * (1.f / HDC) + 1e-6f);
    float4 ww = *(const float4*)&kw[lane * 4];
    v.x *= inv * ww.x; v.y *= inv * ww.y; v.z *= inv * ww.z; v.w *= inv * ww.w;
    *(float4*)&p[lane * 4] = v;
}

// ---------------- HMMA flash self-attention ----------------
__global__ void __launch_bounds__(256, 1) attn_hmma(const int* __restrict__ cu) {
    extern __shared__ __nv_bfloat16 smb[];
    const int tid = threadIdx.x, lane = tid & 31, wid = tid >> 5;
    const int head = blockIdx.y, q0 = blockIdx.x * 128;
    const int G = cu[1] - cu[0];
    const size_t colbase = (size_t)head * HDC;
    const uint32_t sb = smem_u32(smb);
    const float scale = 0.08838834764831845f;

    for (int i = tid; i < 2048; i += 256) {
        int r = i >> 4, c8 = (i & 15) * 8;
        size_t g = (size_t)(q0 + r) * HIDC + colbase + c8;
        *(uint4*)&smb[r * 136 + c8]          = *(const uint4*)&d_q_hi[g];
        *(uint4*)&smb[17408 + r * 136 + c8]  = *(const uint4*)&d_q_lo[g];
    }

    float accO[16][4];
#pragma unroll
    for (int nt = 0; nt < 16; nt++)
#pragma unroll
        for (int u = 0; u < 4; u++) accO[nt][u] = 0.f;
    float m0 = -INFINITY, m1 = -INFINITY, l0 = 0.f, l1 = 0.f;

    const int r0 = q0 + wid * 16 + (lane >> 2);
    const bool qg0 = r0 < G, qg1 = (r0 + 8) < G;

    for (int kt = 0; kt < LC / 64; kt++) {
        __syncthreads();
        for (int i = tid; i < 1024; i += 256) {
            int r = i >> 4, c8 = (i & 15) * 8;
            size_t g = (size_t)(kt * 64 + r) * HIDC + colbase + c8;
            int so = r * 136 + c8;
            *(uint4*)&smb[34816 + so] = *(const uint4*)&d_k_hi[g];
            *(uint4*)&smb[43520 + so] = *(const uint4*)&d_k_lo[g];
            *(uint4*)&smb[52224 + so] = *(const uint4*)&d_v_hi[g];
            *(uint4*)&smb[60928 + so] = *(const uint4*)&d_v_lo[g];
        }
        __syncthreads();

        float S[8][4];
#pragma unroll
        for (int nt = 0; nt < 8; nt++)
#pragma unroll
            for (int u = 0; u < 4; u++) S[nt][u] = 0.f;
#pragma unroll
        for (int ks = 0; ks < 8; ks++) {
            uint32_t qa[2][4], kb[2][4][4];
            uint32_t aoff = ((uint32_t)(wid * 16 + (lane & 15)) * 136 + ks * 16 + (lane >> 4) * 8) * 2;
            ldm_x4(qa[0], sb + aoff);
            ldm_x4(qa[1], sb + 34816 + aoff);
            uint32_t bo_ = ((uint32_t)(((lane >> 4) & 1) * 8 + (lane & 7)) * 136 + ks * 16 + ((lane >> 3) & 1) * 8) * 2;
#pragma unroll
            for (int ng = 0; ng < 4; ng++) {
                uint32_t ro = bo_ + ng * 16 * 136 * 2;
                ldm_x4(kb[0][ng], sb + 69632 + ro);
                ldm_x4(kb[1][ng], sb + 87040 + ro);
            }
#pragma unroll
            for (int cmb = 0; cmb < 3; cmb++) {
                const int ao = (cmb == 2) ? 1 : 0;
                const int bo = (cmb == 1) ? 1 : 0;
#pragma unroll
                for (int nt = 0; nt < 8; nt++)
                    mma16816(S[nt], qa[ao], &kb[bo][nt >> 1][(nt & 1) * 2]);
            }
        }

#pragma unroll
        for (int nt = 0; nt < 8; nt++) {
            int key0 = kt * 64 + nt * 8 + (lane & 3) * 2;
            bool k0g = key0 < G, k1g = (key0 + 1) < G;
            S[nt][0] = (k0g == qg0) ? S[nt][0] * scale : -1e9f;
            S[nt][1] = (k1g == qg0) ? S[nt][1] * scale : -1e9f;
            S[nt][2] = (k0g == qg1) ? S[nt][2] * scale : -1e9f;
            S[nt][3] = (k1g == qg1) ? S[nt][3] * scale : -1e9f;
        }
        float tm0 = -INFINITY, tm1 = -INFINITY;
#pragma unroll
        for (int nt = 0; nt < 8; nt++) {
            tm0 = fmaxf(tm0, fmaxf(S[nt][0], S[nt][1]));
            tm1 = fmaxf(tm1, fmaxf(S[nt][2], S[nt][3]));
        }
        tm0 = fmaxf(tm0, __shfl_xor_sync(0xffffffffu, tm0, 1));
        tm0 = fmaxf(tm0, __shfl_xor_sync(0xffffffffu, tm0, 2));
        tm1 = fmaxf(tm1, __shfl_xor_sync(0xffffffffu, tm1, 1));
        tm1 = fmaxf(tm1, __shfl_xor_sync(0xffffffffu, tm1, 2));
        float mn0 = fmaxf(m0, tm0), mn1 = fmaxf(m1, tm1);
        float al0 = __expf(m0 - mn0), al1 = __expf(m1 - mn1);
        float sum0 = 0.f, sum1 = 0.f;
#pragma unroll
        for (int nt = 0; nt < 8; nt++) {
            S[nt][0] = __expf(S[nt][0] - mn0);
            S[nt][1] = __expf(S[nt][1] - mn0);
            S[nt][2] = __expf(S[nt][2] - mn1);
            S[nt][3] = __expf(S[nt][3] - mn1);
            sum0 += S[nt][0] + S[nt][1];
            sum1 += S[nt][2] + S[nt][3];
        }
        sum0 += __shfl_xor_sync(0xffffffffu, sum0, 1);
        sum0 += __shfl_xor_sync(0xffffffffu, sum0, 2);
        sum1 += __shfl_xor_sync(0xffffffffu, sum1, 1);
        sum1 += __shfl_xor_sync(0xffffffffu, sum1, 2);
        l0 = l0 * al0 + sum0;
        l1 = l1 * al1 + sum1;
        m0 = mn0; m1 = mn1;
#pragma unroll
        for (int nt = 0; nt < 16; nt++) {
            accO[nt][0] *= al0; accO[nt][1] *= al0;
            accO[nt][2] *= al1; accO[nt][3] *= al1;
        }

#pragma unroll
        for (int pk = 0; pk < 4; pk++) {
            uint32_t ph[4], pl[4];
            ph[0] = packbf(S[2*pk][0], S[2*pk][1]);   pl[0] = packlo(S[2*pk][0], S[2*pk][1], ph[0]);
            ph[1] = packbf(S[2*pk][2], S[2*pk][3]);   pl[1] = packlo(S[2*pk][2], S[2*pk][3], ph[1]);
            ph[2] = packbf(S[2*pk+1][0], S[2*pk+1][1]); pl[2] = packlo(S[2*pk+1][0], S[2*pk+1][1], ph[2]);
            ph[3] = packbf(S[2*pk+1][2], S[2*pk+1][3]); pl[3] = packlo(S[2*pk+1][2], S[2*pk+1][3], ph[3]);
            uint32_t vo = ((uint32_t)(pk * 16 + (lane & 15)) * 136 + (lane >> 4) * 8) * 2;
#pragma unroll
            for (int ng4 = 0; ng4 < 8; ng4++) {
                uint32_t co = vo + ng4 * 16 * 2;
                uint32_t vh[4], vl[4];
                ldm_x4_t(vh, sb + 104448 + co);
                ldm_x4_t(vl, sb + 121856 + co);
                mma16816(accO[ng4*2],   ph, &vh[0]);
                mma16816(accO[ng4*2+1], ph, &vh[2]);
                mma16816(accO[ng4*2],   ph, &vl[0]);
                mma16816(accO[ng4*2+1], ph, &vl[2]);
                mma16816(accO[ng4*2],   pl, &vh[0]);
                mma16816(accO[ng4*2+1], pl, &vh[2]);
            }
        }
    }

    float inv0 = 1.f / l0, inv1 = 1.f / l1;
#pragma unroll
    for (int nt = 0; nt < 16; nt++) {
        int col = head * HDC + nt * 8 + (lane & 3) * 2;
        *(float2*)&d_cat[(size_t)r0 * W2K + col]       = make_float2(accO[nt][0] * inv0, accO[nt][1] * inv0);
        *(float2*)&d_cat[(size_t)(r0 + 8) * W2K + col] = make_float2(accO[nt][2] * inv1, accO[nt][3] * inv1);
    }
}

// ---------------- audio cross-attention (fp32) ----------------
__global__ void xattn_kernel(const float* __restrict__ fmask, const float* __restrict__ ascale) {
    extern __shared__ float sm[];
    float* Qs = sm;
    float* Ks = sm + 64 * 132;
    float* Vs = sm + 2 * 64 * 132;
    float* S  = sm + 3 * 64 * 132;
    float* Mr = S + 64 * 65;
    float* Lr = Mr + 64;
    float* Ar = Lr + 64;
    const int tid = threadIdx.x;
    const int head = blockIdx.y;
    const int q0 = blockIdx.x * 64;
    for (int idx = tid * 4; idx < 64 * 128; idx += 1024) {
        int r = idx >> 7, d = idx & 127;
        *(float4*)&Qs[r * 132 + d] = *(const float4*)&d_h[(size_t)(q0 + r) * W1N + head * HDC + d];
    }
    if (tid < 64) { Mr[tid] = -INFINITY; Lr[tid] = 0.f; }
    float o[4][8];
#pragma unroll
    for (int i = 0; i < 4; i++)
#pragma unroll
        for (int j = 0; j < 8; j++) o[i][j] = 0.f;
    const int tr4 = (tid >> 4) << 2;
    const int tc4 = (tid & 15) << 2;
    const int tc8 = (tid & 15) << 3;
    const float scale = 0.08838834764831845f;
    __syncthreads();
    for (int kt = 0; kt < 2; kt++) {
        for (int idx = tid * 4; idx < 64 * 128; idx += 1024) {
            int r = idx >> 7, d = idx & 127;
            size_t base = (size_t)(kt * 64 + r) * MODN + HIDC + head * HDC + d;
            *(float4*)&Ks[r * 132 + d] = *(const float4*)&d_aqkv[base];
            *(float4*)&Vs[r * 132 + d] = *(const float4*)&d_aqkv[base + HIDC];
        }
        __syncthreads();
        float s[4][4] = {};
        for (int d = 0; d < 128; d += 4) {
            float4 qv[4], kv[4];
#pragma unroll
            for (int i = 0; i < 4; i++) qv[i] = *(const float4*)&Qs[(tr4 + i) * 132 + d];
#pragma unroll
            for (int j = 0; j < 4; j++) kv[j] = *(const float4*)&Ks[(tc4 + j) * 132 + d];
#pragma unroll
            for (int i = 0; i < 4; i++)
#pragma unroll
                for (int j = 0; j < 4; j++)
                    s[i][j] += qv[i].x*kv[j].x + qv[i].y*kv[j].y + qv[i].z*kv[j].z + qv[i].w*kv[j].w;
        }
#pragma unroll
        for (int i = 0; i < 4; i++)
#pragma unroll
            for (int j = 0; j < 4; j++)
                S[(tr4 + i) * 65 + tc4 + j] = s[i][j] * scale;
        __syncthreads();
        if (tid < 64) {
            float* Sr = S + tid * 65;
            float mo = Mr[tid], tm = -INFINITY;
            for (int cq = 0; cq < 64; cq++) tm = fmaxf(tm, Sr[cq]);
            float mn = fmaxf(mo, tm);
            float al = __expf(mo - mn);
            float sum = 0.f;
            for (int cq = 0; cq < 64; cq++) { float p = __expf(Sr[cq] - mn); Sr[cq] = p; sum += p; }
            Mr[tid] = mn; Ar[tid] = al; Lr[tid] = Lr[tid] * al + sum;
        }
        __syncthreads();
        {
            float a0 = Ar[tr4], a1 = Ar[tr4+1], a2 = Ar[tr4+2], a3 = Ar[tr4+3];
#pragma unroll
            for (int j = 0; j < 8; j++) { o[0][j]*=a0; o[1][j]*=a1; o[2][j]*=a2; o[3][j]*=a3; }
        }
#pragma unroll 4
        for (int j = 0; j < 64; j++) {
            float p[4];
#pragma unroll
            for (int i = 0; i < 4; i++) p[i] = S[(tr4 + i) * 65 + j];
            float4 v0 = *(const float4*)&Vs[j * 132 + tc8];
            float4 v1 = *(const float4*)&Vs[j * 132 + tc8 + 4];
#pragma unroll
            for (int i = 0; i < 4; i++) {
                o[i][0] = fmaf(p[i], v0.x, o[i][0]); o[i][1] = fmaf(p[i], v0.y, o[i][1]);
                o[i][2] = fmaf(p[i], v0.z, o[i][2]); o[i][3] = fmaf(p[i], v0.w, o[i][3]);
                o[i][4] = fmaf(p[i], v1.x, o[i][4]); o[i][5] = fmaf(p[i], v1.y, o[i][5]);
                o[i][6] = fmaf(p[i], v1.z, o[i][6]); o[i][7] = fmaf(p[i], v1.w, o[i][7]);
            }
        }
        __syncthreads();
    }
    float as = fminf(ascale[0], 2.0f);
#pragma unroll
    for (int i = 0; i < 4; i++) {
        int tok = q0 + tr4 + i;
        int t = tok / 384, rem = tok % 384;
        int gh = rem / 16, gw = rem % 16;
        float fm = fmask[t * 1536 + gh * 2 * 32 + gw * 2];
        float m = (1.f / Lr[tr4 + i]) * fm * as;
        size_t off = (size_t)tok * W2K + head * HDC + tc8;
        float4 c0 = *(const float4*)&d_cat[off];
        float4 c1 = *(const float4*)&d_cat[off + 4];
        c0.x += o[i][0]*m; c0.y += o[i][1]*m; c0.z += o[i][2]*m; c0.w += o[i][3]*m;
        c1.x += o[i][4]*m; c1.y += o[i][5]*m; c1.z += o[i][6]*m; c1.w += o[i][7]*m;
        *(float4*)&d_cat[off]     = c0;
        *(float4*)&d_cat[off + 4] = c1;
    }
}

extern "C" void kernel_launch(void* const* d_in, const int* in_sizes, int n_in,
                              void* d_out, int out_size) {
    const float* x     = (const float*)d_in[0];
    const float* vec   = (const float*)d_in[1];
    const float* trv   = (const float*)d_in[2];
    const float* fcos  = (const float*)d_in[3];
    const float* fsin  = (const float*)d_in[4];
    const float* aemb  = (const float*)d_in[5];
    const float* fmask = (const float*)d_in[6];
    const int*   cu    = (const int*)d_in[7];
    const float* mw    = (const float*)d_in[10];
    const float* mb    = (const float*)d_in[11];
    const float* w1    = (const float*)d_in[12];
    const float* b1    = (const float*)d_in[13];
    const float* qnw   = (const float*)d_in[14];
    const float* knw   = (const float*)d_in[15];
    const float* w2    = (const float*)d_in[16];
    const float* b2    = (const float*)d_in[17];
    const float* aqw   = (const float*)d_in[18];
    const float* aqb   = (const float*)d_in[19];
    const float* aknw  = (const float*)d_in[21];
    const float* ascale= (const float*)d_in[22];
    float* out = (float*)d_out;

    float* h    = nullptr; cudaGetSymbolAddress((void**)&h,    d_h);
    float* aqkv = nullptr; cudaGetSymbolAddress((void**)&aqkv, d_aqkv);
    float* gp   = nullptr; cudaGetSymbolAddress((void**)&gp,   d_gp);
    __nv_bfloat16 *ahi, *alo, *anhi, *anlo, *chi, *clo;
    __nv_bfloat16 *w1h, *w1l, *w2h, *w2l, *awh, *awl;
    cudaGetSymbolAddress((void**)&ahi,  d_a_hi);  cudaGetSymbolAddress((void**)&alo,  d_a_lo);
    cudaGetSymbolAddress((void**)&anhi, d_an_hi); cudaGetSymbolAddress((void**)&anlo, d_an_lo);
    cudaGetSymbolAddress((void**)&chi,  d_cat_hi);cudaGetSymbolAddress((void**)&clo,  d_cat_lo);
    cudaGetSymbolAddress((void**)&w1h,  d_w1t_hi);cudaGetSymbolAddress((void**)&w1l,  d_w1t_lo);
    cudaGetSymbolAddress((void**)&w2h,  d_w2t_hi);cudaGetSymbolAddress((void**)&w2l,  d_w2t_lo);
    cudaGetSymbolAddress((void**)&awh,  d_awt_hi);cudaGetSymbolAddress((void**)&awl,  d_awt_lo);

    const int XATTN_SMEM = (3 * 64 * 132 + 64 * 65 + 3 * 64) * 4;
    cudaFuncSetAttribute(xattn_kernel, cudaFuncAttributeMaxDynamicSharedMemorySize, XATTN_SMEM);
    const int ATTN_SMEM = 139264;
    cudaFuncSetAttribute(attn_hmma, cudaFuncAttributeMaxDynamicSharedMemorySize, ATTN_SMEM);
    const int GEMM_SMEM = 81920;
    cudaFuncSetAttribute(hmma_gemm, cudaFuncAttributeMaxDynamicSharedMemorySize, GEMM_SMEM);
    const int GEMM_SMEM2 = 221184;
    cudaFuncSetAttribute(hmma_gemm_big<2>, cudaFuncAttributeMaxDynamicSharedMemorySize, GEMM_SMEM2);
    cudaFuncSetAttribute(hmma_gemm_big<3>, cudaFuncAttributeMaxDynamicSharedMemorySize, GEMM_SMEM2);

    mod_part<<<dim3(MODN / 128, 8), 512>>>(vec, trv, mw);
    mod_reduce<<<MODN / 256, 256>>>(mb);
    transpose_conv<<<dim3(W1N / 32, HIDC / 32), dim3(8, 32)>>>(w1, w1h, w1l, HIDC, W1N);
    ln_mod_kernel<<<LC, 256>>>(x);
    hmma_gemm_big<2><<<dim3(LC / 256, W1N / 128, 1), 256, GEMM_SMEM2>>>(ahi, alo, w1h, w1l, b1, h, LC, W1N, HIDC);
    transpose_conv<<<dim3(HIDC / 32, W2K / 32), dim3(8, 32)>>>(w2, w2h, w2l, W2K, HIDC);
    transpose_conv<<<dim3(MODN / 32, HIDC / 32), dim3(8, 32)>>>(aqw, awh, awl, HIDC, MODN);
    qkv_kernel<<<(LC * HEADSC) / 4, 128>>>(qnw, knw, fcos, fsin);
    attn_hmma<<<dim3(LC / 128, HEADSC), 256, ATTN_SMEM>>>(cu);
    ln_plain_kernel<<<NAUD, 256>>>(aemb);
    hmma_gemm<<<dim3(NAUD / 128, MODN / 128), 256, GEMM_SMEM>>>(anhi, anlo, awh, awl, aqb, aqkv, NAUD, MODN, HIDC);
    akrms_kernel<<<(NAUD * HEADSC) / 4, 128>>>(aknw);
    xattn_kernel<<<dim3(LIMGC / 64, HEADSC), 256, XATTN_SMEM>>>(fmask, ascale);
    cat_conv_kernel<<<(int)(((size_t)LC * HIDC / 4) / 256), 256>>>();
    hmma_gemm_big<3><<<dim3(LC / 256, HIDC / 128, 3), 256, GEMM_SMEM2>>>(chi, clo, w2h, w2l, b2, gp, LC, HIDC, W2K);
    gemm2_combine<<<(int)(((size_t)LC * HIDC / 4) / 256), 256>>>(b2, x, out);
}

// round 11
// speedup vs baseline: 1.0184x; 1.0184x over previous
#include <cuda_runtime.h>
#include <cuda_bf16.h>
#include <math.h>
#include <stdint.h>

#define HIDC   3072
#define HEADSC 24
#define HDC    128
#define LC     2048
#define LIMGC  1920
#define FFNC   384
#define MLPDC  12288
#define W1N    21504
#define W2K    15360
#define MODN   9216
#define NAUD   128

// ---------------- scratch ----------------
__device__ float d_mod[MODN];
__device__ float d_trm[MODN];
__device__ float d_modp[8][MODN];
__device__ float d_trmp[8][MODN];
__device__ float d_h[(size_t)LC * W1N];
__device__ float d_cat[(size_t)LC * W2K];
__device__ float d_aqkv[(size_t)NAUD * MODN];
__device__ float d_gp[(size_t)3 * LC * HIDC];
__device__ __align__(16) __nv_bfloat16 d_a_hi[(size_t)LC * HIDC];
__device__ __align__(16) __nv_bfloat16 d_a_lo[(size_t)LC * HIDC];
__device__ __align__(16) __nv_bfloat16 d_an_hi[(size_t)NAUD * HIDC];
__device__ __align__(16) __nv_bfloat16 d_an_lo[(size_t)NAUD * HIDC];
__device__ __align__(16) __nv_bfloat16 d_cat_hi[(size_t)LC * W2K];
__device__ __align__(16) __nv_bfloat16 d_cat_lo[(size_t)LC * W2K];
__device__ __align__(16) __nv_bfloat16 d_w1t_hi[(size_t)W1N * HIDC];
__device__ __align__(16) __nv_bfloat16 d_w1t_lo[(size_t)W1N * HIDC];
__device__ __align__(16) __nv_bfloat16 d_w2t_hi[(size_t)HIDC * W2K];
__device__ __align__(16) __nv_bfloat16 d_w2t_lo[(size_t)HIDC * W2K];
__device__ __align__(16) __nv_bfloat16 d_awt_hi[(size_t)MODN * HIDC];
__device__ __align__(16) __nv_bfloat16 d_awt_lo[(size_t)MODN * HIDC];
__device__ __align__(16) __nv_bfloat16 d_q_hi[(size_t)LC * HIDC];
__device__ __align__(16) __nv_bfloat16 d_q_lo[(size_t)LC * HIDC];
__device__ __align__(16) __nv_bfloat16 d_k_hi[(size_t)LC * HIDC];
__device__ __align__(16) __nv_bfloat16 d_k_lo[(size_t)LC * HIDC];
__device__ __align__(16) __nv_bfloat16 d_v_hi[(size_t)LC * HIDC];
__device__ __align__(16) __nv_bfloat16 d_v_lo[(size_t)LC * HIDC];

// ---------------- helpers ----------------
__device__ __forceinline__ uint32_t smem_u32(const void* p) {
    uint32_t a;
    asm("{ .reg .u64 t; cvta.to.shared.u64 t, %1; cvt.u32.u64 %0, t; }" : "=r"(a) : "l"(p));
    return a;
}
__device__ __forceinline__ void ldm_x4(uint32_t* r, uint32_t addr) {
    asm volatile("ldmatrix.sync.aligned.m8n8.x4.shared.b16 {%0,%1,%2,%3}, [%4];"
        : "=r"(r[0]), "=r"(r[1]), "=r"(r[2]), "=r"(r[3]) : "r"(addr));
}
__device__ __forceinline__ void ldm_x4_t(uint32_t* r, uint32_t addr) {
    asm volatile("ldmatrix.sync.aligned.m8n8.x4.trans.shared.b16 {%0,%1,%2,%3}, [%4];"
        : "=r"(r[0]), "=r"(r[1]), "=r"(r[2]), "=r"(r[3]) : "r"(addr));
}
__device__ __forceinline__ void mma16816(float* d, const uint32_t* a, const uint32_t* b) {
    asm volatile("mma.sync.aligned.m16n8k16.row.col.f32.bf16.bf16.f32 "
        "{%0,%1,%2,%3}, {%4,%5,%6,%7}, {%8,%9}, {%0,%1,%2,%3};"
        : "+f"(d[0]), "+f"(d[1]), "+f"(d[2]), "+f"(d[3])
        : "r"(a[0]), "r"(a[1]), "r"(a[2]), "r"(a[3]), "r"(b[0]), "r"(b[1]));
}
__device__ __forceinline__ void cp16(uint32_t dst, const void* src) {
    asm volatile("cp.async.cg.shared.global [%0], [%1], 16;" :: "r"(dst), "l"(src));
}
#define CP_COMMIT() asm volatile("cp.async.commit_group;" ::: "memory")
#define CP_WAIT(n)  asm volatile("cp.async.wait_group %0;" :: "n"(n) : "memory")

__device__ __forceinline__ uint32_t packbf(float a, float b) {
    __nv_bfloat162 t = __floats2bfloat162_rn(a, b);
    return *reinterpret_cast<uint32_t*>(&t);
}
__device__ __forceinline__ uint32_t packlo(float a, float b, uint32_t hi) {
    __nv_bfloat162 h = *reinterpret_cast<__nv_bfloat162*>(&hi);
    return packbf(a - __bfloat162float(h.x), b - __bfloat162float(h.y));
}
__device__ __forceinline__ float gelu_tanh(float x) {
    float x3 = x * x * x;
    return 0.5f * x * (1.f + tanhf(0.7978845608028654f * (x + 0.044715f * x3)));
}
__device__ __forceinline__ void block_reduce2(float& s, float& s2, float* buf) {
    int tid = threadIdx.x, lane = tid & 31, w = tid >> 5;
#pragma unroll
    for (int o = 16; o > 0; o >>= 1) {
        s  += __shfl_xor_sync(0xffffffffu, s,  o);
        s2 += __shfl_xor_sync(0xffffffffu, s2, o);
    }
    if (lane == 0) { buf[w] = s; buf[32 + w] = s2; }
    __syncthreads();
    if (tid == 0) {
        float a = 0.f, b = 0.f;
#pragma unroll
        for (int i = 0; i < 8; i++) { a += buf[i]; b += buf[32 + i]; }
        buf[0] = a; buf[32] = b;
    }
    __syncthreads();
    s = buf[0]; s2 = buf[32];
}
__device__ __forceinline__ void split_store4(__nv_bfloat16* hi, __nv_bfloat16* lo, size_t i, float4 v) {
    __nv_bfloat162 h0 = __floats2bfloat162_rn(v.x, v.y);
    __nv_bfloat162 h1 = __floats2bfloat162_rn(v.z, v.w);
    *(uint2*)&hi[i] = make_uint2(*(uint32_t*)&h0, *(uint32_t*)&h1);
    __nv_bfloat162 l0 = __floats2bfloat162_rn(v.x - __bfloat162float(h0.x), v.y - __bfloat162float(h0.y));
    __nv_bfloat162 l1 = __floats2bfloat162_rn(v.z - __bfloat162float(h1.x), v.w - __bfloat162float(h1.y));
    *(uint2*)&lo[i] = make_uint2(*(uint32_t*)&l0, *(uint32_t*)&l1);
}
__device__ __forceinline__ void split_store2(__nv_bfloat16* hi, __nv_bfloat16* lo, size_t i, float a, float b) {
    __nv_bfloat162 h = __floats2bfloat162_rn(a, b);
    *(uint32_t*)&hi[i] = *(uint32_t*)&h;
    __nv_bfloat162 l = __floats2bfloat162_rn(a - __bfloat162float(h.x), b - __bfloat162float(h.y));
    *(uint32_t*)&lo[i] = *(uint32_t*)&l;
}

// ---------------- transpose + bf16 split ----------------
__global__ void transpose_conv(const float* __restrict__ W, __nv_bfloat16* __restrict__ hi,
                               __nv_bfloat16* __restrict__ lo, int K, int N) {
    __shared__ float t[32][36];
    int n0 = blockIdx.x * 32, k0 = blockIdx.y * 32;
    int tx = threadIdx.x;
    int ty = threadIdx.y;
    float4 v = *(const float4*)&W[(size_t)(k0 + ty) * N + n0 + tx * 4];
    t[ty][tx * 4 + 0] = v.x; t[ty][tx * 4 + 1] = v.y;
    t[ty][tx * 4 + 2] = v.z; t[ty][tx * 4 + 3] = v.w;
    __syncthreads();
    float4 o = make_float4(t[tx * 4 + 0][ty], t[tx * 4 + 1][ty],
                           t[tx * 4 + 2][ty], t[tx * 4 + 3][ty]);
    split_store4(hi, lo, (size_t)(n0 + ty) * K + k0 + tx * 4, o);
}

// ---------------- mod partials ----------------
__global__ void mod_part(const float* __restrict__ vec, const float* __restrict__ trv,
                         const float* __restrict__ mw) {
    __shared__ float sv[384], st[384];
    __shared__ float part[2][4][128];
    int tid = threadIdx.x, by = blockIdx.y;
    if (tid < 384) {
        int k = by * 384 + tid;
        float a = vec[k]; sv[tid] = a / (1.f + expf(-a));
        float b = trv[k]; st[tid] = b / (1.f + expf(-b));
    }
    __syncthreads();
    int jl = tid & 127, sl = tid >> 7;
    int j = blockIdx.x * 128 + jl;
    float a0 = 0.f, a1 = 0.f;
    int kend = (sl + 1) * 96;
    for (int kl = sl * 96; kl < kend; kl++) {
        float w = mw[(size_t)(by * 384 + kl) * MODN + j];
        a0 = fmaf(sv[kl], w, a0);
        a1 = fmaf(st[kl], w, a1);
    }
    part[0][sl][jl] = a0; part[1][sl][jl] = a1;
    __syncthreads();
    if (tid < 128) {
        int jj = blockIdx.x * 128 + tid;
        d_modp[by][jj] = part[0][0][tid] + part[0][1][tid] + part[0][2][tid] + part[0][3][tid];
    } else if (tid < 256) {
        int t = tid - 128, jj = blockIdx.x * 128 + t;
        d_trmp[by][jj] = part[1][0][t] + part[1][1][t] + part[1][2][t] + part[1][3][t];
    }
}
__global__ void mod_reduce(const float* __restrict__ mb) {
    int j = blockIdx.x * 256 + threadIdx.x;
    float s0 = mb[j], s1 = mb[j];
#pragma unroll
    for (int p = 0; p < 8; p++) { s0 += d_modp[p][j]; s1 += d_trmp[p][j]; }
    d_mod[j] = s0; d_trm[j] = s1;
}

// ---------------- LN + modulate -> bf16 hi/lo ----------------
__global__ void ln_mod_kernel(const float* __restrict__ x) {
    int row = blockIdx.x, tid = threadIdx.x;
    const float* xr = x + (size_t)row * HIDC;
    float s = 0.f, s2 = 0.f;
    for (int j = tid * 4; j < HIDC; j += 1024) {
        float4 v = *(const float4*)&xr[j];
        s  += v.x + v.y + v.z + v.w;
        s2 += v.x*v.x + v.y*v.y + v.z*v.z + v.w*v.w;
    }
    __shared__ float buf[64];
    block_reduce2(s, s2, buf);
    float mean = s * (1.f / HIDC);
    float inv = rsqrtf(s2 * (1.f / HIDC) - mean * mean + 1e-6f);
    const float* mv = (row < FFNC) ? d_trm : d_mod;
    for (int j = tid * 4; j < HIDC; j += 1024) {
        float4 v  = *(const float4*)&xr[j];
        float4 sc = *(const float4*)&mv[HIDC + j];
        float4 sh = *(const float4*)&mv[j];
        float4 o;
        o.x = (v.x - mean) * inv * (1.f + sc.x) + sh.x;
        o.y = (v.y - mean) * inv * (1.f + sc.y) + sh.y;
        o.z = (v.z - mean) * inv * (1.f + sc.z) + sh.z;
        o.w = (v.w - mean) * inv * (1.f + sc.w) + sh.w;
        split_store4(d_a_hi, d_a_lo, (size_t)row * HIDC + j, o);
    }
}

// ---------------- audio LN -> bf16 hi/lo ----------------
__global__ void ln_plain_kernel(const float* __restrict__ a) {
    int row = blockIdx.x, tid = threadIdx.x;
    const float* xr = a + (size_t)row * HIDC;
    float s = 0.f, s2 = 0.f;
    for (int j = tid * 4; j < HIDC; j += 1024) {
        float4 v = *(const float4*)&xr[j];
        s  += v.x + v.y + v.z + v.w;
        s2 += v.x*v.x + v.y*v.y + v.z*v.z + v.w*v.w;
    }
    __shared__ float buf[64];
    block_reduce2(s, s2, buf);
    float mean = s * (1.f / HIDC);
    float inv = rsqrtf(s2 * (1.f / HIDC) - mean * mean + 1e-6f);
    for (int j = tid * 4; j < HIDC; j += 1024) {
        float4 v = *(const float4*)&xr[j];
        float4 o = make_float4((v.x - mean) * inv, (v.y - mean) * inv,
                               (v.z - mean) * inv, (v.w - mean) * inv);
        split_store4(d_an_hi, d_an_lo, (size_t)row * HIDC + j, o);
    }
}

// ---------------- attn region of cat: fp32 -> bf16 hi/lo ----------------
__global__ void cat_conv_kernel() {
    size_t i = ((size_t)blockIdx.x * 256 + threadIdx.x) * 4;
    int row = (int)(i / HIDC), col = (int)(i % HIDC);
    size_t b = (size_t)row * W2K + col;
    float4 v = *(const float4*)&d_cat[b];
    split_store4(d_cat_hi, d_cat_lo, b, v);
}

// ---------------- GEMM2 combine ----------------
__global__ void gemm2_combine(const float* __restrict__ bias, const float* __restrict__ resid,
                              float* __restrict__ out) {
    size_t i = ((size_t)blockIdx.x * 256 + threadIdx.x) * 4;
    int m = (int)(i / HIDC), n = (int)(i % HIDC);
    const float* gv = (m < FFNC) ? d_trm : d_mod;
    float4 p0 = *(const float4*)&d_gp[i];
    float4 p1 = *(const float4*)&d_gp[(size_t)LC * HIDC + i];
    float4 p2 = *(const float4*)&d_gp[(size_t)2 * LC * HIDC + i];
    float4 bb = *(const float4*)&bias[n];
    float4 gg = *(const float4*)&gv[2 * HIDC + n];
    float4 rr = *(const float4*)&resid[i];
    float4 o;
    o.x = rr.x + (p0.x + p1.x + p2.x + bb.x) * gg.x;
    o.y = rr.y + (p0.y + p1.y + p2.y + bb.y) * gg.y;
    o.z = rr.z + (p0.z + p1.z + p2.z + bb.z) * gg.z;
    o.w = rr.w + (p0.w + p1.w + p2.w + bb.w) * gg.w;
    *(float4*)&out[i] = o;
}

// ---------------- big HMMA GEMM: 256x128 CTA, 64x64 warp, BK=64, 2 stages ----------------
template<int MODE>
__global__ void __launch_bounds__(256, 1) hmma_gemm_big(
        const __nv_bfloat16* __restrict__ Ahi, const __nv_bfloat16* __restrict__ Alo,
        const __nv_bfloat16* __restrict__ Bhi, const __nv_bfloat16* __restrict__ Blo,
        const float* __restrict__ bias, float* __restrict__ C,
        int M, int N, int K) {
    extern __shared__ char smraw[];
    const int tid = threadIdx.x;
    const int lane = tid & 31, wid = tid >> 5;
    const int bm = blockIdx.x * 256, bn = blockIdx.y * 128;
    const int wm = wid & 3, wn = wid >> 2;
    const int Kper = K / gridDim.z;
    const int ko = blockIdx.z * Kper;
    const uint32_t sbase = smem_u32(smraw);
    const __nv_bfloat16* srcs[4] = {
        Ahi + (size_t)bm * K + ko, Alo + (size_t)bm * K + ko,
        Bhi + (size_t)bn * K + ko, Blo + (size_t)bn * K + ko };

    float acc[4][8][4];
#pragma unroll
    for (int a = 0; a < 4; a++)
#pragma unroll
        for (int b = 0; b < 8; b++)
#pragma unroll
            for (int c = 0; c < 4; c++) acc[a][b][c] = 0.f;

    const int NC = Kper >> 6;
#pragma unroll
    for (int i = 0; i < 24; i++) {
        int id = tid + i * 256;
        if (id < 4096) {
            int op = id >> 11, rem = id & 2047, r = rem >> 3, q = rem & 7;
            cp16(sbase + op * 36864 + r * 144 + q * 16, srcs[op] + (size_t)r * K + q * 8);
        } else {
            int t = id - 4096, op = t >> 10, rem = t & 1023, r = rem >> 3, q = rem & 7;
            cp16(sbase + 73728 + op * 18432 + r * 144 + q * 16, srcs[2 + op] + (size_t)r * K + q * 8);
        }
    }
    CP_COMMIT();

    for (int c = 0; c < NC; c++) {
        const int stage = c & 1;
        if (c + 1 < NC) {
            const int kc = (c + 1) << 6;
            const uint32_t db = sbase + (stage ^ 1) * 110592;
#pragma unroll
            for (int i = 0; i < 24; i++) {
                int id = tid + i * 256;
                if (id < 4096) {
                    int op = id >> 11, rem = id & 2047, r = rem >> 3, q = rem & 7;
                    cp16(db + op * 36864 + r * 144 + q * 16, srcs[op] + (size_t)r * K + kc + q * 8);
                } else {
                    int t = id - 4096, op = t >> 10, rem = t & 1023, r = rem >> 3, q = rem & 7;
                    cp16(db + 73728 + op * 18432 + r * 144 + q * 16, srcs[2 + op] + (size_t)r * K + kc + q * 8);
                }
            }
            CP_COMMIT();
            CP_WAIT(1);
        } else {
            CP_WAIT(0);
        }
        __syncthreads();
        const uint32_t base = sbase + stage * 110592;
#pragma unroll
        for (int kk = 0; kk < 4; kk++) {
            uint32_t afr[2][4][4];
            uint32_t bfr[2][4][4];
            const uint32_t aoff = (uint32_t)(wm * 64 + (lane & 15)) * 144 + kk * 32 + (lane >> 4) * 16;
#pragma unroll
            for (int op = 0; op < 2; op++)
#pragma unroll
                for (int mi = 0; mi < 4; mi++)
                    ldm_x4(afr[op][mi], base + op * 36864 + aoff + mi * 16 * 144);
            const uint32_t boff = (uint32_t)(wn * 64 + ((lane >> 4) & 1) * 8 + (lane & 7)) * 144
                                  + kk * 32 + ((lane >> 3) & 1) * 16;
#pragma unroll
            for (int op = 0; op < 2; op++)
#pragma unroll
                for (int ng = 0; ng < 4; ng++)
                    ldm_x4(bfr[op][ng], base + 73728 + op * 18432 + boff + ng * 16 * 144);
#pragma unroll
            for (int cmb = 0; cmb < 3; cmb++) {
                const int ao = (cmb == 2) ? 1 : 0;
                const int bo = (cmb == 1) ? 1 : 0;
#pragma unroll
                for (int mi = 0; mi < 4; mi++)
#pragma unroll
                    for (int ng = 0; ng < 4; ng++) {
                        mma16816(acc[mi][ng * 2 + 0], afr[ao][mi], &bfr[bo][ng][0]);
                        mma16816(acc[mi][ng * 2 + 1], afr[ao][mi], &bfr[bo][ng][2]);
                    }
            }
        }
        __syncthreads();
    }
    const int gid = lane >> 2, tq = (lane & 3) << 1;
    float* Cz = (MODE == 3) ? (C + (size_t)blockIdx.z * M * N) : C;
#pragma unroll
    for (int mi = 0; mi < 4; mi++) {
#pragma unroll
        for (int half = 0; half < 2; half++) {
            const int m = bm + wm * 64 + mi * 16 + half * 8 + gid;
#pragma unroll
            for (int ni = 0; ni < 8; ni++) {
                const int n = bn + wn * 64 + ni * 8 + tq;
                if (MODE == 3) {
                    *(float2*)&Cz[(size_t)m * N + n] =
                        make_float2(acc[mi][ni][half * 2 + 0], acc[mi][ni][half * 2 + 1]);
                } else {
                    float v0 = acc[mi][ni][half * 2 + 0] + bias[n];
                    float v1 = acc[mi][ni][half * 2 + 1] + bias[n + 1];
                    if (n < 2 * HIDC) {
                        *(float2*)&Cz[(size_t)m * W1N + n] = make_float2(v0, v1);
                    } else if (n < 3 * HIDC) {
                        size_t idx = (size_t)m * HIDC + (n - 2 * HIDC);
                        split_store2(d_v_hi, d_v_lo, idx, v0, v1);
                    } else {
                        size_t idx = (size_t)m * W2K + (n - 2 * HIDC);
                        split_store2(d_cat_hi, d_cat_lo, idx, gelu_tanh(v0), gelu_tanh(v1));
                    }
                }
            }
        }
    }
}

// ---------------- small HMMA GEMM (128x128) for audio path ----------------
__global__ void __launch_bounds__(256, 1) hmma_gemm(
        const __nv_bfloat16* __restrict__ Ahi, const __nv_bfloat16* __restrict__ Alo,
        const __nv_bfloat16* __restrict__ Bhi, const __nv_bfloat16* __restrict__ Blo,
        const float* __restrict__ bias, float* __restrict__ C,
        int M, int N, int K) {
    extern __shared__ char smraw[];
    const int tid = threadIdx.x;
    const int lane = tid & 31, wid = tid >> 5;
    const int bm = blockIdx.x * 128, bn = blockIdx.y * 128;
    const int wm = wid & 3, wn = wid >> 2;
    const uint32_t sbase = smem_u32(smraw);
    const __nv_bfloat16* srcs[4] = {
        Ahi + (size_t)bm * K, Alo + (size_t)bm * K,
        Bhi + (size_t)bn * K, Blo + (size_t)bn * K };
    float acc[2][8][4];
#pragma unroll
    for (int a = 0; a < 2; a++)
#pragma unroll
        for (int b = 0; b < 8; b++)
#pragma unroll
            for (int c = 0; c < 4; c++) acc[a][b][c] = 0.f;
    const int NC = K >> 5;
    {
#pragma unroll
        for (int i = 0; i < 8; i++) {
            int id = tid + i * 256;
            int op = id >> 9, rem = id & 511;
            int r = rem >> 2, q = rem & 3;
            cp16(sbase + op * 10240 + r * 80 + q * 16, srcs[op] + (size_t)r * K + q * 8);
        }
        CP_COMMIT();
    }
    for (int c = 0; c < NC; c++) {
        const int stage = c & 1;
        if (c + 1 < NC) {
            const int kc = (c + 1) << 5;
            const uint32_t db = sbase + (stage ^ 1) * 40960;
#pragma unroll
            for (int i = 0; i < 8; i++) {
                int id = tid + i * 256;
                int op = id >> 9, rem = id & 511;
                int r = rem >> 2, q = rem & 3;
                cp16(db + op * 10240 + r * 80 + q * 16, srcs[op] + (size_t)r * K + kc + q * 8);
            }
            CP_COMMIT();
            CP_WAIT(1);
        } else {
            CP_WAIT(0);
        }
        __syncthreads();
        const uint32_t base = sbase + stage * 40960;
#pragma unroll
        for (int kk = 0; kk < 2; kk++) {
            uint32_t afr[2][2][4];
            uint32_t bfr[2][4][4];
            const uint32_t aoff = (uint32_t)(wm * 32 + (lane & 15)) * 80 + kk * 32 + (lane >> 4) * 16;
#pragma unroll
            for (int op = 0; op < 2; op++)
#pragma unroll
                for (int mi = 0; mi < 2; mi++)
                    ldm_x4(afr[op][mi], base + op * 10240 + aoff + mi * 16 * 80);
            const uint32_t boff = (uint32_t)(wn * 64 + ((lane >> 4) & 1) * 8 + (lane & 7)) * 80
                                  + kk * 32 + ((lane >> 3) & 1) * 16;
#pragma unroll
            for (int op = 0; op < 2; op++)
#pragma unroll
                for (int ng = 0; ng < 4; ng++)
                    ldm_x4(bfr[op][ng], base + 20480 + op * 10240 + boff + ng * 16 * 80);
#pragma unroll
            for (int cmb = 0; cmb < 3; cmb++) {
                const int ao = (cmb == 2) ? 1 : 0;
                const int bo = (cmb == 1) ? 1 : 0;
#pragma unroll
                for (int mi = 0; mi < 2; mi++)
#pragma unroll
                    for (int ng = 0; ng < 4; ng++) {
                        mma16816(acc[mi][ng * 2 + 0], afr[ao][mi], &bfr[bo][ng][0]);
                        mma16816(acc[mi][ng * 2 + 1], afr[ao][mi], &bfr[bo][ng][2]);
                    }
            }
        }
        __syncthreads();
    }
    const int gid = lane >> 2, tq = (lane & 3) << 1;
#pragma unroll
    for (int mi = 0; mi < 2; mi++) {
        const int m0 = bm + wm * 32 + mi * 16 + gid;
        const int m1 = m0 + 8;
#pragma unroll
        for (int ni = 0; ni < 8; ni++) {
            const int n = bn + wn * 64 + ni * 8 + tq;
            const float b0 = bias[n], b1 = bias[n + 1];
            size_t off0 = (size_t)m0 * N + n;
            size_t off1 = (size_t)m1 * N + n;
            *(float2*)&C[off0] = make_float2(acc[mi][ni][0] + b0, acc[mi][ni][1] + b1);
            *(float2*)&C[off1] = make_float2(acc[mi][ni][2] + b0, acc[mi][ni][3] + b1);
        }
    }
}

// ---------------- RMS(q,k)+RoPE ----------------
__global__ void qkv_kernel(const float* __restrict__ qw, const float* __restrict__ kw,
                           const float* __restrict__ fcos, const float* __restrict__ fsin) {
    int gwarp = blockIdx.x * 4 + (threadIdx.x >> 5);
    int lane = threadIdx.x & 31;
    int tok = gwarp / HEADSC, head = gwarp % HEADSC;
    float* base = d_h + (size_t)tok * W1N + head * HDC;
    size_t bidx = (size_t)tok * HIDC + head * HDC + lane * 4;
    bool rope = tok < LIMGC;
    float4 c = make_float4(0,0,0,0), sn = make_float4(0,0,0,0);
    if (rope) {
        c  = *(const float4*)&fcos[tok * HDC + lane * 4];
        sn = *(const float4*)&fsin[tok * HDC + lane * 4];
    }
#pragma unroll
    for (int which = 0; which < 2; which++) {
        float* p = base + which * HIDC;
        const float* w = which ? kw : qw;
        float4 v = *(float4*)&p[lane * 4];
        float ss = v.x*v.x + v.y*v.y + v.z*v.z + v.w*v.w;
#pragma unroll
        for (int o = 16; o > 0; o >>= 1) ss += __shfl_xor_sync(0xffffffffu, ss, o);
        float inv = rsqrtf(ss * (1.f / HDC) + 1e-6f);
        float4 ww = *(const float4*)&w[lane * 4];
        v.x *= inv * ww.x; v.y *= inv * ww.y; v.z *= inv * ww.z; v.w *= inv * ww.w;
        if (rope) {
            float nx = v.x * c.x - v.y * sn.x;
            float ny = v.y * c.x + v.x * sn.x;
            float nz = v.z * c.z - v.w * sn.z;
            float nw = v.w * c.z + v.z * sn.z;
            v = make_float4(nx, ny, nz, nw);
        }
        __nv_bfloat16* hi = which ? d_k_hi : d_q_hi;
        __nv_bfloat16* lo = which ? d_k_lo : d_q_lo;
        split_store4(hi, lo, bidx, v);
        if (which == 0) *(float4*)&p[lane * 4] = v;
    }
}

__global__ void akrms_kernel(const float* __restrict__ kw) {
    int gwarp = blockIdx.x * 4 + (threadIdx.x >> 5);
    int lane = threadIdx.x & 31;
    int tok = gwarp / HEADSC, head = gwarp % HEADSC;
    float* p = d_aqkv + (size_t)tok * MODN + HIDC + head * HDC;
    float4 v = *(float4*)&p[lane * 4];
    float ss = v.x*v.x + v.y*v.y + v.z*v.z + v.w*v.w;
#pragma unroll
    for (int o = 16; o > 0; o >>= 1) ss += __shfl_xor_sync(0xffffffffu, ss, o);
    float inv = rsqrtf(ss * (1.f / HDC) + 1e-6f);
    float4 ww = *(const float4*)&kw[lane * 4];
    v.x *= inv * ww.x; v.y *= inv * ww.y; v.z *= inv * ww.z; v.w *= inv * ww.w;
    *(float4*)&p[lane * 4] = v;
}

// ---------------- HMMA flash self-attention, 128q x 128k tiles ----------------
// smem (bf16 elems): Qh 0, Ql 17408, Kh 34816, Kl 52224, Vh 69632, Vl 87040; total 104448*2B = 208896B.
__global__ void __launch_bounds__(256, 1) attn_hmma(const int* __restrict__ cu) {
    extern __shared__ __nv_bfloat16 smb[];
    const int tid = threadIdx.x, lane = tid & 31, wid = tid >> 5;
    const int head = blockIdx.y, q0 = blockIdx.x * 128;
    const int G = cu[1] - cu[0];
    const size_t colbase = (size_t)head * HDC;
    const uint32_t sb = smem_u32(smb);
    const float scale = 0.08838834764831845f;

    for (int i = tid; i < 2048; i += 256) {
        int r = i >> 4, c8 = (i & 15) * 8;
        size_t g = (size_t)(q0 + r) * HIDC + colbase + c8;
        *(uint4*)&smb[r * 136 + c8]          = *(const uint4*)&d_q_hi[g];
        *(uint4*)&smb[17408 + r * 136 + c8]  = *(const uint4*)&d_q_lo[g];
    }

    float accO[16][4];
#pragma unroll
    for (int nt = 0; nt < 16; nt++)
#pragma unroll
        for (int u = 0; u < 4; u++) accO[nt][u] = 0.f;
    float m0 = -INFINITY, m1 = -INFINITY, l0 = 0.f, l1 = 0.f;

    const int r0 = q0 + wid * 16 + (lane >> 2);
    const bool qg0 = r0 < G, qg1 = (r0 + 8) < G;

    for (int kt = 0; kt < LC / 128; kt++) {
        __syncthreads();
        for (int i = tid; i < 2048; i += 256) {
            int r = i >> 4, c8 = (i & 15) * 8;
            size_t g = (size_t)(kt * 128 + r) * HIDC + colbase + c8;
            int so = r * 136 + c8;
            *(uint4*)&smb[34816 + so] = *(const uint4*)&d_k_hi[g];
            *(uint4*)&smb[52224 + so] = *(const uint4*)&d_k_lo[g];
            *(uint4*)&smb[69632 + so] = *(const uint4*)&d_v_hi[g];
            *(uint4*)&smb[87040 + so] = *(const uint4*)&d_v_lo[g];
        }
        __syncthreads();

        // S = Q @ K^T over 128 keys (16 n-tiles), done in two 64-key halves
        float S[16][4];
#pragma unroll
        for (int nt = 0; nt < 16; nt++)
#pragma unroll
            for (int u = 0; u < 4; u++) S[nt][u] = 0.f;
#pragma unroll
        for (int half = 0; half < 2; half++) {
#pragma unroll
            for (int ks = 0; ks < 8; ks++) {
                uint32_t qa[2][4], kb[2][4][4];
                uint32_t aoff = ((uint32_t)(wid * 16 + (lane & 15)) * 136 + ks * 16 + (lane >> 4) * 8) * 2;
                ldm_x4(qa[0], sb + aoff);
                ldm_x4(qa[1], sb + 34816 + aoff);
                uint32_t bo_ = ((uint32_t)(half * 64 + ((lane >> 4) & 1) * 8 + (lane & 7)) * 136
                                + ks * 16 + ((lane >> 3) & 1) * 8) * 2;
#pragma unroll
                for (int ng = 0; ng < 4; ng++) {
                    uint32_t ro = bo_ + ng * 16 * 136 * 2;
                    ldm_x4(kb[0][ng], sb + 69632 + ro);
                    ldm_x4(kb[1][ng], sb + 104448 + ro);
                }
#pragma unroll
                for (int cmb = 0; cmb < 3; cmb++) {
                    const int ao = (cmb == 2) ? 1 : 0;
                    const int bo = (cmb == 1) ? 1 : 0;
#pragma unroll
                    for (int nt = 0; nt < 8; nt++)
                        mma16816(S[half * 8 + nt], qa[ao], &kb[bo][nt >> 1][(nt & 1) * 2]);
                }
            }
        }

        // mask + scale
#pragma unroll
        for (int nt = 0; nt < 16; nt++) {
            int key0 = kt * 128 + nt * 8 + (lane & 3) * 2;
            bool k0g = key0 < G, k1g = (key0 + 1) < G;
            S[nt][0] = (k0g == qg0) ? S[nt][0] * scale : -1e9f;
            S[nt][1] = (k1g == qg0) ? S[nt][1] * scale : -1e9f;
            S[nt][2] = (k0g == qg1) ? S[nt][2] * scale : -1e9f;
            S[nt][3] = (k1g == qg1) ? S[nt][3] * scale : -1e9f;
        }
        float tm0 = -INFINITY, tm1 = -INFINITY;
#pragma unroll
        for (int nt = 0; nt < 16; nt++) {
            tm0 = fmaxf(tm0, fmaxf(S[nt][0], S[nt][1]));
            tm1 = fmaxf(tm1, fmaxf(S[nt][2], S[nt][3]));
        }
        tm0 = fmaxf(tm0, __shfl_xor_sync(0xffffffffu, tm0, 1));
        tm0 = fmaxf(tm0, __shfl_xor_sync(0xffffffffu, tm0, 2));
        tm1 = fmaxf(tm1, __shfl_xor_sync(0xffffffffu, tm1, 1));
        tm1 = fmaxf(tm1, __shfl_xor_sync(0xffffffffu, tm1, 2));
        float mn0 = fmaxf(m0, tm0), mn1 = fmaxf(m1, tm1);
        float al0 = __expf(m0 - mn0), al1 = __expf(m1 - mn1);
        float sum0 = 0.f, sum1 = 0.f;
#pragma unroll
        for (int nt = 0; nt < 16; nt++) {
            S[nt][0] = __expf(S[nt][0] - mn0);
            S[nt][1] = __expf(S[nt][1] - mn0);
            S[nt][2] = __expf(S[nt][2] - mn1);
            S[nt][3] = __expf(S[nt][3] - mn1);
            sum0 += S[nt][0] + S[nt][1];
            sum1 += S[nt][2] + S[nt][3];
        }
        sum0 += __shfl_xor_sync(0xffffffffu, sum0, 1);
        sum0 += __shfl_xor_sync(0xffffffffu, sum0, 2);
        sum1 += __shfl_xor_sync(0xffffffffu, sum1, 1);
        sum1 += __shfl_xor_sync(0xffffffffu, sum1, 2);
        l0 = l0 * al0 + sum0;
        l1 = l1 * al1 + sum1;
        m0 = mn0; m1 = mn1;
#pragma unroll
        for (int nt = 0; nt < 16; nt++) {
            accO[nt][0] *= al0; accO[nt][1] *= al0;
            accO[nt][2] *= al1; accO[nt][3] *= al1;
        }

        // O += P @ V  (k dim = 128 keys -> 8 chunks of 16)
#pragma unroll
        for (int pk = 0; pk < 8; pk++) {
            uint32_t ph[4], pl[4];
            ph[0] = packbf(S[2*pk][0], S[2*pk][1]);     pl[0] = packlo(S[2*pk][0], S[2*pk][1], ph[0]);
            ph[1] = packbf(S[2*pk][2], S[2*pk][3]);     pl[1] = packlo(S[2*pk][2], S[2*pk][3], ph[1]);
            ph[2] = packbf(S[2*pk+1][0], S[2*pk+1][1]); pl[2] = packlo(S[2*pk+1][0], S[2*pk+1][1], ph[2]);
            ph[3] = packbf(S[2*pk+1][2], S[2*pk+1][3]); pl[3] = packlo(S[2*pk+1][2], S[2*pk+1][3], ph[3]);
            uint32_t vo = ((uint32_t)(pk * 16 + (lane & 15)) * 136 + (lane >> 4) * 8) * 2;
#pragma unroll
            for (int ng4 = 0; ng4 < 8; ng4++) {
                uint32_t co = vo + ng4 * 16 * 2;
                uint32_t vh[4], vl[4];
                ldm_x4_t(vh, sb + 139264 + co);
                ldm_x4_t(vl, sb + 174080 + co);
                mma16816(accO[ng4*2],   ph, &vh[0]);
                mma16816(accO[ng4*2+1], ph, &vh[2]);
                mma16816(accO[ng4*2],   ph, &vl[0]);
                mma16816(accO[ng4*2+1], ph, &vl[2]);
                mma16816(accO[ng4*2],   pl, &vh[0]);
                mma16816(accO[ng4*2+1], pl, &vh[2]);
            }
        }
    }

    float inv0 = 1.f / l0, inv1 = 1.f / l1;
#pragma unroll
    for (int nt = 0; nt < 16; nt++) {
        int col = head * HDC + nt * 8 + (lane & 3) * 2;
        *(float2*)&d_cat[(size_t)r0 * W2K + col]       = make_float2(accO[nt][0] * inv0, accO[nt][1] * inv0);
        *(float2*)&d_cat[(size_t)(r0 + 8) * W2K + col] = make_float2(accO[nt][2] * inv1, accO[nt][3] * inv1);
    }
}

// ---------------- audio cross-attention (fp32) ----------------
__global__ void xattn_kernel(const float* __restrict__ fmask, const float* __restrict__ ascale) {
    extern __shared__ float sm[];
    float* Qs = sm;
    float* Ks = sm + 64 * 132;
    float* Vs = sm + 2 * 64 * 132;
    float* S  = sm + 3 * 64 * 132;
    float* Mr = S + 64 * 65;
    float* Lr = Mr + 64;
    float* Ar = Lr + 64;
    const int tid = threadIdx.x;
    const int head = blockIdx.y;
    const int q0 = blockIdx.x * 64;
    for (int idx = tid * 4; idx < 64 * 128; idx += 1024) {
        int r = idx >> 7, d = idx & 127;
        *(float4*)&Qs[r * 132 + d] = *(const float4*)&d_h[(size_t)(q0 + r) * W1N + head * HDC + d];
    }
    if (tid < 64) { Mr[tid] = -INFINITY; Lr[tid] = 0.f; }
    float o[4][8];
#pragma unroll
    for (int i = 0; i < 4; i++)
#pragma unroll
        for (int j = 0; j < 8; j++) o[i][j] = 0.f;
    const int tr4 = (tid >> 4) << 2;
    const int tc4 = (tid & 15) << 2;
    const int tc8 = (tid & 15) << 3;
    const float scale = 0.08838834764831845f;
    __syncthreads();
    for (int kt = 0; kt < 2; kt++) {
        for (int idx = tid * 4; idx < 64 * 128; idx += 1024) {
            int r = idx >> 7, d = idx & 127;
            size_t base = (size_t)(kt * 64 + r) * MODN + HIDC + head * HDC + d;
            *(float4*)&Ks[r * 132 + d] = *(const float4*)&d_aqkv[base];
            *(float4*)&Vs[r * 132 + d] = *(const float4*)&d_aqkv[base + HIDC];
        }
        __syncthreads();
        float s[4][4] = {};
        for (int d = 0; d < 128; d += 4) {
            float4 qv[4], kv[4];
#pragma unroll
            for (int i = 0; i < 4; i++) qv[i] = *(const float4*)&Qs[(tr4 + i) * 132 + d];
#pragma unroll
            for (int j = 0; j < 4; j++) kv[j] = *(const float4*)&Ks[(tc4 + j) * 132 + d];
#pragma unroll
            for (int i = 0; i < 4; i++)
#pragma unroll
                for (int j = 0; j < 4; j++)
                    s[i][j] += qv[i].x*kv[j].x + qv[i].y*kv[j].y + qv[i].z*kv[j].z + qv[i].w*kv[j].w;
        }
#pragma unroll
        for (int i = 0; i < 4; i++)
#pragma unroll
            for (int j = 0; j < 4; j++)
                S[(tr4 + i) * 65 + tc4 + j] = s[i][j] * scale;
        __syncthreads();
        if (tid < 64) {
            float* Sr = S + tid * 65;
            float mo = Mr[tid], tm = -INFINITY;
            for (int cq = 0; cq < 64; cq++) tm = fmaxf(tm, Sr[cq]);
            float mn = fmaxf(mo, tm);
            float al = __expf(mo - mn);
            float sum = 0.f;
            for (int cq = 0; cq < 64; cq++) { float p = __expf(Sr[cq] - mn); Sr[cq] = p; sum += p; }
            Mr[tid] = mn; Ar[tid] = al; Lr[tid] = Lr[tid] * al + sum;
        }
        __syncthreads();
        {
            float a0 = Ar[tr4], a1 = Ar[tr4+1], a2 = Ar[tr4+2], a3 = Ar[tr4+3];
#pragma unroll
            for (int j = 0; j < 8; j++) { o[0][j]*=a0; o[1][j]*=a1; o[2][j]*=a2; o[3][j]*=a3; }
        }
#pragma unroll 4
        for (int j = 0; j < 64; j++) {
            float p[4];
#pragma unroll
            for (int i = 0; i < 4; i++) p[i] = S[(tr4 + i) * 65 + j];
            float4 v0 = *(const float4*)&Vs[j * 132 + tc8];
            float4 v1 = *(const float4*)&Vs[j * 132 + tc8 + 4];
#pragma unroll
            for (int i = 0; i < 4; i++) {
                o[i][0] = fmaf(p[i], v0.x, o[i][0]); o[i][1] = fmaf(p[i], v0.y, o[i][1]);
                o[i][2] = fmaf(p[i], v0.z, o[i][2]); o[i][3] = fmaf(p[i], v0.w, o[i][3]);
                o[i][4] = fmaf(p[i], v1.x, o[i][4]); o[i][5] = fmaf(p[i], v1.y, o[i][5]);
                o[i][6] = fmaf(p[i], v1.z, o[i][6]); o[i][7] = fmaf(p[i], v1.w, o[i][7]);
            }
        }
        __syncthreads();
    }
    float as = fminf(ascale[0], 2.0f);
#pragma unroll
    for (int i = 0; i < 4; i++) {
        int tok = q0 + tr4 + i;
        int t = tok / 384, rem = tok % 384;
        int gh = rem / 16, gw = rem % 16;
        float fm = fmask[t * 1536 + gh * 2 * 32 + gw * 2];
        float m = (1.f / Lr[tr4 + i]) * fm * as;
        size_t off = (size_t)tok * W2K + head * HDC + tc8;
        float4 c0 = *(const float4*)&d_cat[off];
        float4 c1 = *(const float4*)&d_cat[off + 4];
        c0.x += o[i][0]*m; c0.y += o[i][1]*m; c0.z += o[i][2]*m; c0.w += o[i][3]*m;
        c1.x += o[i][4]*m; c1.y += o[i][5]*m; c1.z += o[i][6]*m; c1.w += o[i][7]*m;
        *(float4*)&d_cat[off]     = c0;
        *(float4*)&d_cat[off + 4] = c1;
    }
}

extern "C" void kernel_launch(void* const* d_in, const int* in_sizes, int n_in,
                              void* d_out, int out_size) {
    const float* x     = (const float*)d_in[0];
    const float* vec   = (const float*)d_in[1];
    const float* trv   = (const float*)d_in[2];
    const float* fcos  = (const float*)d_in[3];
    const float* fsin  = (const float*)d_in[4];
    const float* aemb  = (const float*)d_in[5];
    const float* fmask = (const float*)d_in[6];
    const int*   cu    = (const int*)d_in[7];
    const float* mw    = (const float*)d_in[10];
    const float* mb    = (const float*)d_in[11];
    const float* w1    = (const float*)d_in[12];
    const float* b1    = (const float*)d_in[13];
    const float* qnw   = (const float*)d_in[14];
    const float* knw   = (const float*)d_in[15];
    const float* w2    = (const float*)d_in[16];
    const float* b2    = (const float*)d_in[17];
    const float* aqw   = (const float*)d_in[18];
    const float* aqb   = (const float*)d_in[19];
    const float* aknw  = (const float*)d_in[21];
    const float* ascale= (const float*)d_in[22];
    float* out = (float*)d_out;

    float* h    = nullptr; cudaGetSymbolAddress((void**)&h,    d_h);
    float* aqkv = nullptr; cudaGetSymbolAddress((void**)&aqkv, d_aqkv);
    float* gp   = nullptr; cudaGetSymbolAddress((void**)&gp,   d_gp);
    __nv_bfloat16 *ahi, *alo, *anhi, *anlo, *chi, *clo;
    __nv_bfloat16 *w1h, *w1l, *w2h, *w2l, *awh, *awl;
    cudaGetSymbolAddress((void**)&ahi,  d_a_hi);  cudaGetSymbolAddress((void**)&alo,  d_a_lo);
    cudaGetSymbolAddress((void**)&anhi, d_an_hi); cudaGetSymbolAddress((void**)&anlo, d_an_lo);
    cudaGetSymbolAddress((void**)&chi,  d_cat_hi);cudaGetSymbolAddress((void**)&clo,  d_cat_lo);
    cudaGetSymbolAddress((void**)&w1h,  d_w1t_hi);cudaGetSymbolAddress((void**)&w1l,  d_w1t_lo);
    cudaGetSymbolAddress((void**)&w2h,  d_w2t_hi);cudaGetSymbolAddress((void**)&w2l,  d_w2t_lo);
    cudaGetSymbolAddress((void**)&awh,  d_awt_hi);cudaGetSymbolAddress((void**)&awl,  d_awt_lo);

    const int XATTN_SMEM = (3 * 64 * 132 + 64 * 65 + 3 * 64) * 4;
    cudaFuncSetAttribute(xattn_kernel, cudaFuncAttributeMaxDynamicSharedMemorySize, XATTN_SMEM);
    const int ATTN_SMEM = 208896;
    cudaFuncSetAttribute(attn_hmma, cudaFuncAttributeMaxDynamicSharedMemorySize, ATTN_SMEM);
    const int GEMM_SMEM = 81920;
    cudaFuncSetAttribute(hmma_gemm, cudaFuncAttributeMaxDynamicSharedMemorySize, GEMM_SMEM);
    const int GEMM_SMEM2 = 221184;
    cudaFuncSetAttribute(hmma_gemm_big<2>, cudaFuncAttributeMaxDynamicSharedMemorySize, GEMM_SMEM2);
    cudaFuncSetAttribute(hmma_gemm_big<3>, cudaFuncAttributeMaxDynamicSharedMemorySize, GEMM_SMEM2);

    mod_part<<<dim3(MODN / 128, 8), 512>>>(vec, trv, mw);
    mod_reduce<<<MODN / 256, 256>>>(mb);
    transpose_conv<<<dim3(W1N / 32, HIDC / 32), dim3(8, 32)>>>(w1, w1h, w1l, HIDC, W1N);
    ln_mod_kernel<<<LC, 256>>>(x);
    hmma_gemm_big<2><<<dim3(LC / 256, W1N / 128, 1), 256, GEMM_SMEM2>>>(ahi, alo, w1h, w1l, b1, h, LC, W1N, HIDC);
    transpose_conv<<<dim3(HIDC / 32, W2K / 32), dim3(8, 32)>>>(w2, w2h, w2l, W2K, HIDC);
    transpose_conv<<<dim3(MODN / 32, HIDC / 32), dim3(8, 32)>>>(aqw, awh, awl, HIDC, MODN);
    qkv_kernel<<<(LC * HEADSC) / 4, 128>>>(qnw, knw, fcos, fsin);
    attn_hmma<<<dim3(LC / 128, HEADSC), 256, ATTN_SMEM>>>(cu);
    ln_plain_kernel<<<NAUD, 256>>>(aemb);
    hmma_gemm<<<dim3(NAUD / 128, MODN / 128), 256, GEMM_SMEM>>>(anhi, anlo, awh, awl, aqb, aqkv, NAUD, MODN, HIDC);
    akrms_kernel<<<(NAUD * HEADSC) / 4, 128>>>(aknw);
    xattn_kernel<<<dim3(LIMGC / 64, HEADSC), 256, XATTN_SMEM>>>(fmask, ascale);
    cat_conv_kernel<<<(int)(((size_t)LC * HIDC / 4) / 256), 256>>>();
    hmma_gemm_big<3><<<dim3(LC / 256, HIDC / 128, 3), 256, GEMM_SMEM2>>>(chi, clo, w2h, w2l, b2, gp, LC, HIDC, W2K);
    gemm2_combine<<<(int)(((size_t)LC * HIDC / 4) / 256), 256>>>(b2, x, out);
}

// round 12
// speedup vs baseline: 1.0394x; 1.0205x over previous
#include <cuda_runtime.h>
#include <cuda_bf16.h>
#include <math.h>
#include <stdint.h>

#define HIDC   3072
#define HEADSC 24
#define HDC    128
#define LC     2048
#define LIMGC  1920
#define FFNC   384
#define MLPDC  12288
#define W1N    21504
#define W2K    15360
#define MODN   9216
#define NAUD   128

// ---------------- scratch ----------------
__device__ float d_mod[MODN];
__device__ float d_trm[MODN];
__device__ float d_modp[8][MODN];
__device__ float d_trmp[8][MODN];
__device__ float d_h[(size_t)LC * W1N];
__device__ float d_cat[(size_t)LC * W2K];
__device__ float d_aqkv[(size_t)NAUD * MODN];
__device__ float d_gp[(size_t)3 * LC * HIDC];
__device__ __align__(16) __nv_bfloat16 d_a_hi[(size_t)LC * HIDC];
__device__ __align__(16) __nv_bfloat16 d_a_lo[(size_t)LC * HIDC];
__device__ __align__(16) __nv_bfloat16 d_an_hi[(size_t)NAUD * HIDC];
__device__ __align__(16) __nv_bfloat16 d_an_lo[(size_t)NAUD * HIDC];
__device__ __align__(16) __nv_bfloat16 d_cat_hi[(size_t)LC * W2K];
__device__ __align__(16) __nv_bfloat16 d_cat_lo[(size_t)LC * W2K];
__device__ __align__(16) __nv_bfloat16 d_w1t_hi[(size_t)W1N * HIDC];
__device__ __align__(16) __nv_bfloat16 d_w1t_lo[(size_t)W1N * HIDC];
__device__ __align__(16) __nv_bfloat16 d_w2t_hi[(size_t)HIDC * W2K];
__device__ __align__(16) __nv_bfloat16 d_w2t_lo[(size_t)HIDC * W2K];
__device__ __align__(16) __nv_bfloat16 d_awt_hi[(size_t)MODN * HIDC];
__device__ __align__(16) __nv_bfloat16 d_awt_lo[(size_t)MODN * HIDC];
__device__ __align__(16) __nv_bfloat16 d_q_hi[(size_t)LC * HIDC];
__device__ __align__(16) __nv_bfloat16 d_q_lo[(size_t)LC * HIDC];
__device__ __align__(16) __nv_bfloat16 d_k_hi[(size_t)LC * HIDC];
__device__ __align__(16) __nv_bfloat16 d_k_lo[(size_t)LC * HIDC];
__device__ __align__(16) __nv_bfloat16 d_v_hi[(size_t)LC * HIDC];
__device__ __align__(16) __nv_bfloat16 d_v_lo[(size_t)LC * HIDC];
// audio k/v hi-lo
__device__ __align__(16) __nv_bfloat16 d_ak_hi[(size_t)NAUD * HIDC];
__device__ __align__(16) __nv_bfloat16 d_ak_lo[(size_t)NAUD * HIDC];
__device__ __align__(16) __nv_bfloat16 d_av_hi[(size_t)NAUD * HIDC];
__device__ __align__(16) __nv_bfloat16 d_av_lo[(size_t)NAUD * HIDC];

// ---------------- helpers ----------------
__device__ __forceinline__ uint32_t smem_u32(const void* p) {
    uint32_t a;
    asm("{ .reg .u64 t; cvta.to.shared.u64 t, %1; cvt.u32.u64 %0, t; }" : "=r"(a) : "l"(p));
    return a;
}
__device__ __forceinline__ void ldm_x4(uint32_t* r, uint32_t addr) {
    asm volatile("ldmatrix.sync.aligned.m8n8.x4.shared.b16 {%0,%1,%2,%3}, [%4];"
        : "=r"(r[0]), "=r"(r[1]), "=r"(r[2]), "=r"(r[3]) : "r"(addr));
}
__device__ __forceinline__ void ldm_x4_t(uint32_t* r, uint32_t addr) {
    asm volatile("ldmatrix.sync.aligned.m8n8.x4.trans.shared.b16 {%0,%1,%2,%3}, [%4];"
        : "=r"(r[0]), "=r"(r[1]), "=r"(r[2]), "=r"(r[3]) : "r"(addr));
}
__device__ __forceinline__ void mma16816(float* d, const uint32_t* a, const uint32_t* b) {
    asm volatile("mma.sync.aligned.m16n8k16.row.col.f32.bf16.bf16.f32 "
        "{%0,%1,%2,%3}, {%4,%5,%6,%7}, {%8,%9}, {%0,%1,%2,%3};"
        : "+f"(d[0]), "+f"(d[1]), "+f"(d[2]), "+f"(d[3])
        : "r"(a[0]), "r"(a[1]), "r"(a[2]), "r"(a[3]), "r"(b[0]), "r"(b[1]));
}
__device__ __forceinline__ void cp16(uint32_t dst, const void* src) {
    asm volatile("cp.async.cg.shared.global [%0], [%1], 16;" :: "r"(dst), "l"(src));
}
#define CP_COMMIT() asm volatile("cp.async.commit_group;" ::: "memory")
#define CP_WAIT(n)  asm volatile("cp.async.wait_group %0;" :: "n"(n) : "memory")

__device__ __forceinline__ uint32_t packbf(float a, float b) {
    __nv_bfloat162 t = __floats2bfloat162_rn(a, b);
    return *reinterpret_cast<uint32_t*>(&t);
}
__device__ __forceinline__ uint32_t packlo(float a, float b, uint32_t hi) {
    __nv_bfloat162 h = *reinterpret_cast<__nv_bfloat162*>(&hi);
    return packbf(a - __bfloat162float(h.x), b - __bfloat162float(h.y));
}
__device__ __forceinline__ float gelu_fast(float x) {
    float u2 = 1.5957691216057308f * (x + 0.044715f * x * x * x);
    return x / (1.f + __expf(-u2));
}
__device__ __forceinline__ void block_reduce2(float& s, float& s2, float* buf) {
    int tid = threadIdx.x, lane = tid & 31, w = tid >> 5;
#pragma unroll
    for (int o = 16; o > 0; o >>= 1) {
        s  += __shfl_xor_sync(0xffffffffu, s,  o);
        s2 += __shfl_xor_sync(0xffffffffu, s2, o);
    }
    if (lane == 0) { buf[w] = s; buf[32 + w] = s2; }
    __syncthreads();
    if (tid == 0) {
        float a = 0.f, b = 0.f;
#pragma unroll
        for (int i = 0; i < 8; i++) { a += buf[i]; b += buf[32 + i]; }
        buf[0] = a; buf[32] = b;
    }
    __syncthreads();
    s = buf[0]; s2 = buf[32];
}
__device__ __forceinline__ void split_store4(__nv_bfloat16* hi, __nv_bfloat16* lo, size_t i, float4 v) {
    __nv_bfloat162 h0 = __floats2bfloat162_rn(v.x, v.y);
    __nv_bfloat162 h1 = __floats2bfloat162_rn(v.z, v.w);
    *(uint2*)&hi[i] = make_uint2(*(uint32_t*)&h0, *(uint32_t*)&h1);
    __nv_bfloat162 l0 = __floats2bfloat162_rn(v.x - __bfloat162float(h0.x), v.y - __bfloat162float(h0.y));
    __nv_bfloat162 l1 = __floats2bfloat162_rn(v.z - __bfloat162float(h1.x), v.w - __bfloat162float(h1.y));
    *(uint2*)&lo[i] = make_uint2(*(uint32_t*)&l0, *(uint32_t*)&l1);
}
__device__ __forceinline__ void split_store2(__nv_bfloat16* hi, __nv_bfloat16* lo, size_t i, float a, float b) {
    __nv_bfloat162 h = __floats2bfloat162_rn(a, b);
    *(uint32_t*)&hi[i] = *(uint32_t*)&h;
    __nv_bfloat162 l = __floats2bfloat162_rn(a - __bfloat162float(h.x), b - __bfloat162float(h.y));
    *(uint32_t*)&lo[i] = *(uint32_t*)&l;
}

// ---------------- transpose + bf16 split ----------------
__global__ void transpose_conv(const float* __restrict__ W, __nv_bfloat16* __restrict__ hi,
                               __nv_bfloat16* __restrict__ lo, int K, int N) {
    __shared__ float t[32][36];
    int n0 = blockIdx.x * 32, k0 = blockIdx.y * 32;
    int tx = threadIdx.x;
    int ty = threadIdx.y;
    float4 v = *(const float4*)&W[(size_t)(k0 + ty) * N + n0 + tx * 4];
    t[ty][tx * 4 + 0] = v.x; t[ty][tx * 4 + 1] = v.y;
    t[ty][tx * 4 + 2] = v.z; t[ty][tx * 4 + 3] = v.w;
    __syncthreads();
    float4 o = make_float4(t[tx * 4 + 0][ty], t[tx * 4 + 1][ty],
                           t[tx * 4 + 2][ty], t[tx * 4 + 3][ty]);
    split_store4(hi, lo, (size_t)(n0 + ty) * K + k0 + tx * 4, o);
}

// ---------------- mod partials ----------------
__global__ void mod_part(const float* __restrict__ vec, const float* __restrict__ trv,
                         const float* __restrict__ mw) {
    __shared__ float sv[384], st[384];
    __shared__ float part[2][4][128];
    int tid = threadIdx.x, by = blockIdx.y;
    if (tid < 384) {
        int k = by * 384 + tid;
        float a = vec[k]; sv[tid] = a / (1.f + expf(-a));
        float b = trv[k]; st[tid] = b / (1.f + expf(-b));
    }
    __syncthreads();
    int jl = tid & 127, sl = tid >> 7;
    int j = blockIdx.x * 128 + jl;
    float a0 = 0.f, a1 = 0.f;
    int kend = (sl + 1) * 96;
    for (int kl = sl * 96; kl < kend; kl++) {
        float w = mw[(size_t)(by * 384 + kl) * MODN + j];
        a0 = fmaf(sv[kl], w, a0);
        a1 = fmaf(st[kl], w, a1);
    }
    part[0][sl][jl] = a0; part[1][sl][jl] = a1;
    __syncthreads();
    if (tid < 128) {
        int jj = blockIdx.x * 128 + tid;
        d_modp[by][jj] = part[0][0][tid] + part[0][1][tid] + part[0][2][tid] + part[0][3][tid];
    } else if (tid < 256) {
        int t = tid - 128, jj = blockIdx.x * 128 + t;
        d_trmp[by][jj] = part[1][0][t] + part[1][1][t] + part[1][2][t] + part[1][3][t];
    }
}
__global__ void mod_reduce(const float* __restrict__ mb) {
    int j = blockIdx.x * 256 + threadIdx.x;
    float s0 = mb[j], s1 = mb[j];
#pragma unroll
    for (int p = 0; p < 8; p++) { s0 += d_modp[p][j]; s1 += d_trmp[p][j]; }
    d_mod[j] = s0; d_trm[j] = s1;
}

// ---------------- LN + modulate -> bf16 hi/lo ----------------
__global__ void ln_mod_kernel(const float* __restrict__ x) {
    int row = blockIdx.x, tid = threadIdx.x;
    const float* xr = x + (size_t)row * HIDC;
    float s = 0.f, s2 = 0.f;
    for (int j = tid * 4; j < HIDC; j += 1024) {
        float4 v = *(const float4*)&xr[j];
        s  += v.x + v.y + v.z + v.w;
        s2 += v.x*v.x + v.y*v.y + v.z*v.z + v.w*v.w;
    }
    __shared__ float buf[64];
    block_reduce2(s, s2, buf);
    float mean = s * (1.f / HIDC);
    float inv = rsqrtf(s2 * (1.f / HIDC) - mean * mean + 1e-6f);
    const float* mv = (row < FFNC) ? d_trm : d_mod;
    for (int j = tid * 4; j < HIDC; j += 1024) {
        float4 v  = *(const float4*)&xr[j];
        float4 sc = *(const float4*)&mv[HIDC + j];
        float4 sh = *(const float4*)&mv[j];
        float4 o;
        o.x = (v.x - mean) * inv * (1.f + sc.x) + sh.x;
        o.y = (v.y - mean) * inv * (1.f + sc.y) + sh.y;
        o.z = (v.z - mean) * inv * (1.f + sc.z) + sh.z;
        o.w = (v.w - mean) * inv * (1.f + sc.w) + sh.w;
        split_store4(d_a_hi, d_a_lo, (size_t)row * HIDC + j, o);
    }
}

// ---------------- audio LN -> bf16 hi/lo ----------------
__global__ void ln_plain_kernel(const float* __restrict__ a) {
    int row = blockIdx.x, tid = threadIdx.x;
    const float* xr = a + (size_t)row * HIDC;
    float s = 0.f, s2 = 0.f;
    for (int j = tid * 4; j < HIDC; j += 1024) {
        float4 v = *(const float4*)&xr[j];
        s  += v.x + v.y + v.z + v.w;
        s2 += v.x*v.x + v.y*v.y + v.z*v.z + v.w*v.w;
    }
    __shared__ float buf[64];
    block_reduce2(s, s2, buf);
    float mean = s * (1.f / HIDC);
    float inv = rsqrtf(s2 * (1.f / HIDC) - mean * mean + 1e-6f);
    for (int j = tid * 4; j < HIDC; j += 1024) {
        float4 v = *(const float4*)&xr[j];
        float4 o = make_float4((v.x - mean) * inv, (v.y - mean) * inv,
                               (v.z - mean) * inv, (v.w - mean) * inv);
        split_store4(d_an_hi, d_an_lo, (size_t)row * HIDC + j, o);
    }
}

// ---------------- attn region of cat: fp32 -> bf16 hi/lo ----------------
__global__ void cat_conv_kernel() {
    size_t i = ((size_t)blockIdx.x * 256 + threadIdx.x) * 4;
    int row = (int)(i / HIDC), col = (int)(i % HIDC);
    size_t b = (size_t)row * W2K + col;
    float4 v = *(const float4*)&d_cat[b];
    split_store4(d_cat_hi, d_cat_lo, b, v);
}

// ---------------- GEMM2 combine ----------------
__global__ void gemm2_combine(const float* __restrict__ bias, const float* __restrict__ resid,
                              float* __restrict__ out) {
    size_t i = ((size_t)blockIdx.x * 256 + threadIdx.x) * 4;
    int m = (int)(i / HIDC), n = (int)(i % HIDC);
    const float* gv = (m < FFNC) ? d_trm : d_mod;
    float4 p0 = *(const float4*)&d_gp[i];
    float4 p1 = *(const float4*)&d_gp[(size_t)LC * HIDC + i];
    float4 p2 = *(const float4*)&d_gp[(size_t)2 * LC * HIDC + i];
    float4 bb = *(const float4*)&bias[n];
    float4 gg = *(const float4*)&gv[2 * HIDC + n];
    float4 rr = *(const float4*)&resid[i];
    float4 o;
    o.x = rr.x + (p0.x + p1.x + p2.x + bb.x) * gg.x;
    o.y = rr.y + (p0.y + p1.y + p2.y + bb.y) * gg.y;
    o.z = rr.z + (p0.z + p1.z + p2.z + bb.z) * gg.z;
    o.w = rr.w + (p0.w + p1.w + p2.w + bb.w) * gg.w;
    *(float4*)&out[i] = o;
}

// ---------------- big HMMA GEMM: 256x128 CTA, 64x64 warp, BK=64, 2 stages ----------------
template<int MODE>
__global__ void __launch_bounds__(256, 1) hmma_gemm_big(
        const __nv_bfloat16* __restrict__ Ahi, const __nv_bfloat16* __restrict__ Alo,
        const __nv_bfloat16* __restrict__ Bhi, const __nv_bfloat16* __restrict__ Blo,
        const float* __restrict__ bias, float* __restrict__ C,
        int M, int N, int K) {
    extern __shared__ char smraw[];
    const int tid = threadIdx.x;
    const int lane = tid & 31, wid = tid >> 5;
    const int bm = blockIdx.x * 256, bn = blockIdx.y * 128;
    const int wm = wid & 3, wn = wid >> 2;
    const int Kper = K / gridDim.z;
    const int ko = blockIdx.z * Kper;
    const uint32_t sbase = smem_u32(smraw);
    const __nv_bfloat16* srcs[4] = {
        Ahi + (size_t)bm * K + ko, Alo + (size_t)bm * K + ko,
        Bhi + (size_t)bn * K + ko, Blo + (size_t)bn * K + ko };

    float acc[4][8][4];
#pragma unroll
    for (int a = 0; a < 4; a++)
#pragma unroll
        for (int b = 0; b < 8; b++)
#pragma unroll
            for (int c = 0; c < 4; c++) acc[a][b][c] = 0.f;

    const int NC = Kper >> 6;
#pragma unroll
    for (int i = 0; i < 24; i++) {
        int id = tid + i * 256;
        if (id < 4096) {
            int op = id >> 11, rem = id & 2047, r = rem >> 3, q = rem & 7;
            cp16(sbase + op * 36864 + r * 144 + q * 16, srcs[op] + (size_t)r * K + q * 8);
        } else {
            int t = id - 4096, op = t >> 10, rem = t & 1023, r = rem >> 3, q = rem & 7;
            cp16(sbase + 73728 + op * 18432 + r * 144 + q * 16, srcs[2 + op] + (size_t)r * K + q * 8);
        }
    }
    CP_COMMIT();

    for (int c = 0; c < NC; c++) {
        const int stage = c & 1;
        if (c + 1 < NC) {
            const int kc = (c + 1) << 6;
            const uint32_t db = sbase + (stage ^ 1) * 110592;
#pragma unroll
            for (int i = 0; i < 24; i++) {
                int id = tid + i * 256;
                if (id < 4096) {
                    int op = id >> 11, rem = id & 2047, r = rem >> 3, q = rem & 7;
                    cp16(db + op * 36864 + r * 144 + q * 16, srcs[op] + (size_t)r * K + kc + q * 8);
                } else {
                    int t = id - 4096, op = t >> 10, rem = t & 1023, r = rem >> 3, q = rem & 7;
                    cp16(db + 73728 + op * 18432 + r * 144 + q * 16, srcs[2 + op] + (size_t)r * K + kc + q * 8);
                }
            }
            CP_COMMIT();
            CP_WAIT(1);
        } else {
            CP_WAIT(0);
        }
        __syncthreads();
        const uint32_t base = sbase + stage * 110592;
#pragma unroll
        for (int kk = 0; kk < 4; kk++) {
            uint32_t afr[2][4][4];
            uint32_t bfr[2][4][4];
            const uint32_t aoff = (uint32_t)(wm * 64 + (lane & 15)) * 144 + kk * 32 + (lane >> 4) * 16;
#pragma unroll
            for (int op = 0; op < 2; op++)
#pragma unroll
                for (int mi = 0; mi < 4; mi++)
                    ldm_x4(afr[op][mi], base + op * 36864 + aoff + mi * 16 * 144);
            const uint32_t boff = (uint32_t)(wn * 64 + ((lane >> 4) & 1) * 8 + (lane & 7)) * 144
                                  + kk * 32 + ((lane >> 3) & 1) * 16;
#pragma unroll
            for (int op = 0; op < 2; op++)
#pragma unroll
                for (int ng = 0; ng < 4; ng++)
                    ldm_x4(bfr[op][ng], base + 73728 + op * 18432 + boff + ng * 16 * 144);
#pragma unroll
            for (int cmb = 0; cmb < 3; cmb++) {
                const int ao = (cmb == 2) ? 1 : 0;
                const int bo = (cmb == 1) ? 1 : 0;
#pragma unroll
                for (int mi = 0; mi < 4; mi++)
#pragma unroll
                    for (int ng = 0; ng < 4; ng++) {
                        mma16816(acc[mi][ng * 2 + 0], afr[ao][mi], &bfr[bo][ng][0]);
                        mma16816(acc[mi][ng * 2 + 1], afr[ao][mi], &bfr[bo][ng][2]);
                    }
            }
        }
        __syncthreads();
    }
    const int gid = lane >> 2, tq = (lane & 3) << 1;
    float* Cz = (MODE == 3) ? (C + (size_t)blockIdx.z * M * N) : C;
#pragma unroll
    for (int mi = 0; mi < 4; mi++) {
#pragma unroll
        for (int half = 0; half < 2; half++) {
            const int m = bm + wm * 64 + mi * 16 + half * 8 + gid;
#pragma unroll
            for (int ni = 0; ni < 8; ni++) {
                const int n = bn + wn * 64 + ni * 8 + tq;
                if (MODE == 3) {
                    *(float2*)&Cz[(size_t)m * N + n] =
                        make_float2(acc[mi][ni][half * 2 + 0], acc[mi][ni][half * 2 + 1]);
                } else {
                    float v0 = acc[mi][ni][half * 2 + 0] + bias[n];
                    float v1 = acc[mi][ni][half * 2 + 1] + bias[n + 1];
                    if (n < 2 * HIDC) {
                        *(float2*)&Cz[(size_t)m * W1N + n] = make_float2(v0, v1);
                    } else if (n < 3 * HIDC) {
                        size_t idx = (size_t)m * HIDC + (n - 2 * HIDC);
                        split_store2(d_v_hi, d_v_lo, idx, v0, v1);
                    } else {
                        size_t idx = (size_t)m * W2K + (n - 2 * HIDC);
                        split_store2(d_cat_hi, d_cat_lo, idx, gelu_fast(v0), gelu_fast(v1));
                    }
                }
            }
        }
    }
}

// ---------------- small HMMA GEMM (128x128) for audio path ----------------
__global__ void __launch_bounds__(256, 1) hmma_gemm(
        const __nv_bfloat16* __restrict__ Ahi, const __nv_bfloat16* __restrict__ Alo,
        const __nv_bfloat16* __restrict__ Bhi, const __nv_bfloat16* __restrict__ Blo,
        const float* __restrict__ bias, float* __restrict__ C,
        int M, int N, int K) {
    extern __shared__ char smraw[];
    const int tid = threadIdx.x;
    const int lane = tid & 31, wid = tid >> 5;
    const int bm = blockIdx.x * 128, bn = blockIdx.y * 128;
    const int wm = wid & 3, wn = wid >> 2;
    const uint32_t sbase = smem_u32(smraw);
    const __nv_bfloat16* srcs[4] = {
        Ahi + (size_t)bm * K, Alo + (size_t)bm * K,
        Bhi + (size_t)bn * K, Blo + (size_t)bn * K };
    float acc[2][8][4];
#pragma unroll
    for (int a = 0; a < 2; a++)
#pragma unroll
        for (int b = 0; b < 8; b++)
#pragma unroll
            for (int c = 0; c < 4; c++) acc[a][b][c] = 0.f;
    const int NC = K >> 5;
    {
#pragma unroll
        for (int i = 0; i < 8; i++) {
            int id = tid + i * 256;
            int op = id >> 9, rem = id & 511;
            int r = rem >> 2, q = rem & 3;
            cp16(sbase + op * 10240 + r * 80 + q * 16, srcs[op] + (size_t)r * K + q * 8);
        }
        CP_COMMIT();
    }
    for (int c = 0; c < NC; c++) {
        const int stage = c & 1;
        if (c + 1 < NC) {
            const int kc = (c + 1) << 5;
            const uint32_t db = sbase + (stage ^ 1) * 40960;
#pragma unroll
            for (int i = 0; i < 8; i++) {
                int id = tid + i * 256;
                int op = id >> 9, rem = id & 511;
                int r = rem >> 2, q = rem & 3;
                cp16(db + op * 10240 + r * 80 + q * 16, srcs[op] + (size_t)r * K + kc + q * 8);
            }
            CP_COMMIT();
            CP_WAIT(1);
        } else {
            CP_WAIT(0);
        }
        __syncthreads();
        const uint32_t base = sbase + stage * 40960;
#pragma unroll
        for (int kk = 0; kk < 2; kk++) {
            uint32_t afr[2][2][4];
            uint32_t bfr[2][4][4];
            const uint32_t aoff = (uint32_t)(wm * 32 + (lane & 15)) * 80 + kk * 32 + (lane >> 4) * 16;
#pragma unroll
            for (int op = 0; op < 2; op++)
#pragma unroll
                for (int mi = 0; mi < 2; mi++)
                    ldm_x4(afr[op][mi], base + op * 10240 + aoff + mi * 16 * 80);
            const uint32_t boff = (uint32_t)(wn * 64 + ((lane >> 4) & 1) * 8 + (lane & 7)) * 80
                                  + kk * 32 + ((lane >> 3) & 1) * 16;
#pragma unroll
            for (int op = 0; op < 2; op++)
#pragma unroll
                for (int ng = 0; ng < 4; ng++)
                    ldm_x4(bfr[op][ng], base + 20480 + op * 10240 + boff + ng * 16 * 80);
#pragma unroll
            for (int cmb = 0; cmb < 3; cmb++) {
                const int ao = (cmb == 2) ? 1 : 0;
                const int bo = (cmb == 1) ? 1 : 0;
#pragma unroll
                for (int mi = 0; mi < 2; mi++)
#pragma unroll
                    for (int ng = 0; ng < 4; ng++) {
                        mma16816(acc[mi][ng * 2 + 0], afr[ao][mi], &bfr[bo][ng][0]);
                        mma16816(acc[mi][ng * 2 + 1], afr[ao][mi], &bfr[bo][ng][2]);
                    }
            }
        }
        __syncthreads();
    }
    const int gid = lane >> 2, tq = (lane & 3) << 1;
#pragma unroll
    for (int mi = 0; mi < 2; mi++) {
        const int m0 = bm + wm * 32 + mi * 16 + gid;
        const int m1 = m0 + 8;
#pragma unroll
        for (int ni = 0; ni < 8; ni++) {
            const int n = bn + wn * 64 + ni * 8 + tq;
            const float b0 = bias[n], b1 = bias[n + 1];
            size_t off0 = (size_t)m0 * N + n;
            size_t off1 = (size_t)m1 * N + n;
            *(float2*)&C[off0] = make_float2(acc[mi][ni][0] + b0, acc[mi][ni][1] + b1);
            *(float2*)&C[off1] = make_float2(acc[mi][ni][2] + b0, acc[mi][ni][3] + b1);
        }
    }
}

// ---------------- RMS(q,k)+RoPE ----------------
__global__ void qkv_kernel(const float* __restrict__ qw, const float* __restrict__ kw,
                           const float* __restrict__ fcos, const float* __restrict__ fsin) {
    int gwarp = blockIdx.x * 4 + (threadIdx.x >> 5);
    int lane = threadIdx.x & 31;
    int tok = gwarp / HEADSC, head = gwarp % HEADSC;
    float* base = d_h + (size_t)tok * W1N + head * HDC;
    size_t bidx = (size_t)tok * HIDC + head * HDC + lane * 4;
    bool rope = tok < LIMGC;
    float4 c = make_float4(0,0,0,0), sn = make_float4(0,0,0,0);
    if (rope) {
        c  = *(const float4*)&fcos[tok * HDC + lane * 4];
        sn = *(const float4*)&fsin[tok * HDC + lane * 4];
    }
#pragma unroll
    for (int which = 0; which < 2; which++) {
        float* p = base + which * HIDC;
        const float* w = which ? kw : qw;
        float4 v = *(float4*)&p[lane * 4];
        float ss = v.x*v.x + v.y*v.y + v.z*v.z + v.w*v.w;
#pragma unroll
        for (int o = 16; o > 0; o >>= 1) ss += __shfl_xor_sync(0xffffffffu, ss, o);
        float inv = rsqrtf(ss * (1.f / HDC) + 1e-6f);
        float4 ww = *(const float4*)&w[lane * 4];
        v.x *= inv * ww.x; v.y *= inv * ww.y; v.z *= inv * ww.z; v.w *= inv * ww.w;
        if (rope) {
            float nx = v.x * c.x - v.y * sn.x;
            float ny = v.y * c.x + v.x * sn.x;
            float nz = v.z * c.z - v.w * sn.z;
            float nw = v.w * c.z + v.z * sn.z;
            v = make_float4(nx, ny, nz, nw);
        }
        __nv_bfloat16* hi = which ? d_k_hi : d_q_hi;
        __nv_bfloat16* lo = which ? d_k_lo : d_q_lo;
        split_store4(hi, lo, bidx, v);
    }
}

// ---------------- audio k RMS + v -> bf16 hi/lo ----------------
__global__ void akv_kernel(const float* __restrict__ kw) {
    int gwarp = blockIdx.x * 4 + (threadIdx.x >> 5);
    int lane = threadIdx.x & 31;
    int tok = gwarp / HEADSC, head = gwarp % HEADSC;
    const float* p = d_aqkv + (size_t)tok * MODN + HIDC + head * HDC;
    size_t bidx = (size_t)tok * HIDC + head * HDC + lane * 4;
    float4 v = *(const float4*)&p[lane * 4];
    float ss = v.x*v.x + v.y*v.y + v.z*v.z + v.w*v.w;
#pragma unroll
    for (int o = 16; o > 0; o >>= 1) ss += __shfl_xor_sync(0xffffffffu, ss, o);
    float inv = rsqrtf(ss * (1.f / HDC) + 1e-6f);
    float4 ww = *(const float4*)&kw[lane * 4];
    v.x *= inv * ww.x; v.y *= inv * ww.y; v.z *= inv * ww.z; v.w *= inv * ww.w;
    split_store4(d_ak_hi, d_ak_lo, bidx, v);
    float4 vv = *(const float4*)&p[HIDC + lane * 4];
    split_store4(d_av_hi, d_av_lo, bidx, vv);
}

// ---------------- HMMA flash self-attention, 128q x 128k tiles ----------------
__global__ void __launch_bounds__(256, 1) attn_hmma(const int* __restrict__ cu) {
    extern __shared__ __nv_bfloat16 smb[];
    const int tid = threadIdx.x, lane = tid & 31, wid = tid >> 5;
    const int head = blockIdx.y, q0 = blockIdx.x * 128;
    const int G = cu[1] - cu[0];
    const size_t colbase = (size_t)head * HDC;
    const uint32_t sb = smem_u32(smb);
    const float scale = 0.08838834764831845f;

    for (int i = tid; i < 2048; i += 256) {
        int r = i >> 4, c8 = (i & 15) * 8;
        size_t g = (size_t)(q0 + r) * HIDC + colbase + c8;
        *(uint4*)&smb[r * 136 + c8]          = *(const uint4*)&d_q_hi[g];
        *(uint4*)&smb[17408 + r * 136 + c8]  = *(const uint4*)&d_q_lo[g];
    }

    float accO[16][4];
#pragma unroll
    for (int nt = 0; nt < 16; nt++)
#pragma unroll
        for (int u = 0; u < 4; u++) accO[nt][u] = 0.f;
    float m0 = -INFINITY, m1 = -INFINITY, l0 = 0.f, l1 = 0.f;

    const int r0 = q0 + wid * 16 + (lane >> 2);
    const bool qg0 = r0 < G, qg1 = (r0 + 8) < G;

    for (int kt = 0; kt < LC / 128; kt++) {
        __syncthreads();
        for (int i = tid; i < 2048; i += 256) {
            int r = i >> 4, c8 = (i & 15) * 8;
            size_t g = (size_t)(kt * 128 + r) * HIDC + colbase + c8;
            int so = r * 136 + c8;
            *(uint4*)&smb[34816 + so] = *(const uint4*)&d_k_hi[g];
            *(uint4*)&smb[52224 + so] = *(const uint4*)&d_k_lo[g];
            *(uint4*)&smb[69632 + so] = *(const uint4*)&d_v_hi[g];
            *(uint4*)&smb[87040 + so] = *(const uint4*)&d_v_lo[g];
        }
        __syncthreads();

        float S[16][4];
#pragma unroll
        for (int nt = 0; nt < 16; nt++)
#pragma unroll
            for (int u = 0; u < 4; u++) S[nt][u] = 0.f;
#pragma unroll
        for (int half = 0; half < 2; half++) {
#pragma unroll
            for (int ks = 0; ks < 8; ks++) {
                uint32_t qa[2][4], kb[2][4][4];
                uint32_t aoff = ((uint32_t)(wid * 16 + (lane & 15)) * 136 + ks * 16 + (lane >> 4) * 8) * 2;
                ldm_x4(qa[0], sb + aoff);
                ldm_x4(qa[1], sb + 34816 + aoff);
                uint32_t bo_ = ((uint32_t)(half * 64 + ((lane >> 4) & 1) * 8 + (lane & 7)) * 136
                                + ks * 16 + ((lane >> 3) & 1) * 8) * 2;
#pragma unroll
                for (int ng = 0; ng < 4; ng++) {
                    uint32_t ro = bo_ + ng * 16 * 136 * 2;
                    ldm_x4(kb[0][ng], sb + 69632 + ro);
                    ldm_x4(kb[1][ng], sb + 104448 + ro);
                }
#pragma unroll
                for (int cmb = 0; cmb < 3; cmb++) {
                    const int ao = (cmb == 2) ? 1 : 0;
                    const int bo = (cmb == 1) ? 1 : 0;
#pragma unroll
                    for (int nt = 0; nt < 8; nt++)
                        mma16816(S[half * 8 + nt], qa[ao], &kb[bo][nt >> 1][(nt & 1) * 2]);
                }
            }
        }

#pragma unroll
        for (int nt = 0; nt < 16; nt++) {
            int key0 = kt * 128 + nt * 8 + (lane & 3) * 2;
            bool k0g = key0 < G, k1g = (key0 + 1) < G;
            S[nt][0] = (k0g == qg0) ? S[nt][0] * scale : -1e9f;
            S[nt][1] = (k1g == qg0) ? S[nt][1] * scale : -1e9f;
            S[nt][2] = (k0g == qg1) ? S[nt][2] * scale : -1e9f;
            S[nt][3] = (k1g == qg1) ? S[nt][3] * scale : -1e9f;
        }
        float tm0 = -INFINITY, tm1 = -INFINITY;
#pragma unroll
        for (int nt = 0; nt < 16; nt++) {
            tm0 = fmaxf(tm0, fmaxf(S[nt][0], S[nt][1]));
            tm1 = fmaxf(tm1, fmaxf(S[nt][2], S[nt][3]));
        }
        tm0 = fmaxf(tm0, __shfl_xor_sync(0xffffffffu, tm0, 1));
        tm0 = fmaxf(tm0, __shfl_xor_sync(0xffffffffu, tm0, 2));
        tm1 = fmaxf(tm1, __shfl_xor_sync(0xffffffffu, tm1, 1));
        tm1 = fmaxf(tm1, __shfl_xor_sync(0xffffffffu, tm1, 2));
        float mn0 = fmaxf(m0, tm0), mn1 = fmaxf(m1, tm1);
        float al0 = __expf(m0 - mn0), al1 = __expf(m1 - mn1);
        float sum0 = 0.f, sum1 = 0.f;
#pragma unroll
        for (int nt = 0; nt < 16; nt++) {
            S[nt][0] = __expf(S[nt][0] - mn0);
            S[nt][1] = __expf(S[nt][1] - mn0);
            S[nt][2] = __expf(S[nt][2] - mn1);
            S[nt][3] = __expf(S[nt][3] - mn1);
            sum0 += S[nt][0] + S[nt][1];
            sum1 += S[nt][2] + S[nt][3];
        }
        sum0 += __shfl_xor_sync(0xffffffffu, sum0, 1);
        sum0 += __shfl_xor_sync(0xffffffffu, sum0, 2);
        sum1 += __shfl_xor_sync(0xffffffffu, sum1, 1);
        sum1 += __shfl_xor_sync(0xffffffffu, sum1, 2);
        l0 = l0 * al0 + sum0;
        l1 = l1 * al1 + sum1;
        m0 = mn0; m1 = mn1;
#pragma unroll
        for (int nt = 0; nt < 16; nt++) {
            accO[nt][0] *= al0; accO[nt][1] *= al0;
            accO[nt][2] *= al1; accO[nt][3] *= al1;
        }

#pragma unroll
        for (int pk = 0; pk < 8; pk++) {
            uint32_t ph[4], pl[4];
            ph[0] = packbf(S[2*pk][0], S[2*pk][1]);     pl[0] = packlo(S[2*pk][0], S[2*pk][1], ph[0]);
            ph[1] = packbf(S[2*pk][2], S[2*pk][3]);     pl[1] = packlo(S[2*pk][2], S[2*pk][3], ph[1]);
            ph[2] = packbf(S[2*pk+1][0], S[2*pk+1][1]); pl[2] = packlo(S[2*pk+1][0], S[2*pk+1][1], ph[2]);
            ph[3] = packbf(S[2*pk+1][2], S[2*pk+1][3]); pl[3] = packlo(S[2*pk+1][2], S[2*pk+1][3], ph[3]);
            uint32_t vo = ((uint32_t)(pk * 16 + (lane & 15)) * 136 + (lane >> 4) * 8) * 2;
#pragma unroll
            for (int ng4 = 0; ng4 < 8; ng4++) {
                uint32_t co = vo + ng4 * 16 * 2;
                uint32_t vh[4], vl[4];
                ldm_x4_t(vh, sb + 139264 + co);
                ldm_x4_t(vl, sb + 174080 + co);
                mma16816(accO[ng4*2],   ph, &vh[0]);
                mma16816(accO[ng4*2+1], ph, &vh[2]);
                mma16816(accO[ng4*2],   ph, &vl[0]);
                mma16816(accO[ng4*2+1], ph, &vl[2]);
                mma16816(accO[ng4*2],   pl, &vh[0]);
                mma16816(accO[ng4*2+1], pl, &vh[2]);
            }
        }
    }

    float inv0 = 1.f / l0, inv1 = 1.f / l1;
#pragma unroll
    for (int nt = 0; nt < 16; nt++) {
        int col = head * HDC + nt * 8 + (lane & 3) * 2;
        *(float2*)&d_cat[(size_t)r0 * W2K + col]       = make_float2(accO[nt][0] * inv0, accO[nt][1] * inv0);
        *(float2*)&d_cat[(size_t)(r0 + 8) * W2K + col] = make_float2(accO[nt][2] * inv1, accO[nt][3] * inv1);
    }
}

// ---------------- HMMA audio cross-attention: 128q x 128 audio keys, single tile ----------------
__global__ void __launch_bounds__(256, 1) xattn_hmma(const float* __restrict__ fmask,
                                                     const float* __restrict__ ascale) {
    extern __shared__ __nv_bfloat16 smb[];
    const int tid = threadIdx.x, lane = tid & 31, wid = tid >> 5;
    const int head = blockIdx.y, q0 = blockIdx.x * 128;
    const size_t colbase = (size_t)head * HDC;
    const uint32_t sb = smem_u32(smb);
    const float scale = 0.08838834764831845f;

    for (int i = tid; i < 2048; i += 256) {
        int r = i >> 4, c8 = (i & 15) * 8;
        size_t gq = (size_t)(q0 + r) * HIDC + colbase + c8;
        size_t ga = (size_t)r * HIDC + colbase + c8;
        int so = r * 136 + c8;
        *(uint4*)&smb[so]          = *(const uint4*)&d_q_hi[gq];
        *(uint4*)&smb[17408 + so]  = *(const uint4*)&d_q_lo[gq];
        *(uint4*)&smb[34816 + so]  = *(const uint4*)&d_ak_hi[ga];
        *(uint4*)&smb[52224 + so]  = *(const uint4*)&d_ak_lo[ga];
        *(uint4*)&smb[69632 + so]  = *(const uint4*)&d_av_hi[ga];
        *(uint4*)&smb[87040 + so]  = *(const uint4*)&d_av_lo[ga];
    }
    __syncthreads();

    float S[16][4];
#pragma unroll
    for (int nt = 0; nt < 16; nt++)
#pragma unroll
        for (int u = 0; u < 4; u++) S[nt][u] = 0.f;
#pragma unroll
    for (int half = 0; half < 2; half++) {
#pragma unroll
        for (int ks = 0; ks < 8; ks++) {
            uint32_t qa[2][4], kb[2][4][4];
            uint32_t aoff = ((uint32_t)(wid * 16 + (lane & 15)) * 136 + ks * 16 + (lane >> 4) * 8) * 2;
            ldm_x4(qa[0], sb + aoff);
            ldm_x4(qa[1], sb + 34816 + aoff);
            uint32_t bo_ = ((uint32_t)(half * 64 + ((lane >> 4) & 1) * 8 + (lane & 7)) * 136
                            + ks * 16 + ((lane >> 3) & 1) * 8) * 2;
#pragma unroll
            for (int ng = 0; ng < 4; ng++) {
                uint32_t ro = bo_ + ng * 16 * 136 * 2;
                ldm_x4(kb[0][ng], sb + 69632 + ro);
                ldm_x4(kb[1][ng], sb + 104448 + ro);
            }
#pragma unroll
            for (int cmb = 0; cmb < 3; cmb++) {
                const int ao = (cmb == 2) ? 1 : 0;
                const int bo = (cmb == 1) ? 1 : 0;
#pragma unroll
                for (int nt = 0; nt < 8; nt++)
                    mma16816(S[half * 8 + nt], qa[ao], &kb[bo][nt >> 1][(nt & 1) * 2]);
            }
        }
    }

    // single-pass softmax (all 128 keys valid)
    float tm0 = -INFINITY, tm1 = -INFINITY;
#pragma unroll
    for (int nt = 0; nt < 16; nt++) {
        S[nt][0] *= scale; S[nt][1] *= scale; S[nt][2] *= scale; S[nt][3] *= scale;
        tm0 = fmaxf(tm0, fmaxf(S[nt][0], S[nt][1]));
        tm1 = fmaxf(tm1, fmaxf(S[nt][2], S[nt][3]));
    }
    tm0 = fmaxf(tm0, __shfl_xor_sync(0xffffffffu, tm0, 1));
    tm0 = fmaxf(tm0, __shfl_xor_sync(0xffffffffu, tm0, 2));
    tm1 = fmaxf(tm1, __shfl_xor_sync(0xffffffffu, tm1, 1));
    tm1 = fmaxf(tm1, __shfl_xor_sync(0xffffffffu, tm1, 2));
    float sum0 = 0.f, sum1 = 0.f;
#pragma unroll
    for (int nt = 0; nt < 16; nt++) {
        S[nt][0] = __expf(S[nt][0] - tm0);
        S[nt][1] = __expf(S[nt][1] - tm0);
        S[nt][2] = __expf(S[nt][2] - tm1);
        S[nt][3] = __expf(S[nt][3] - tm1);
        sum0 += S[nt][0] + S[nt][1];
        sum1 += S[nt][2] + S[nt][3];
    }
    sum0 += __shfl_xor_sync(0xffffffffu, sum0, 1);
    sum0 += __shfl_xor_sync(0xffffffffu, sum0, 2);
    sum1 += __shfl_xor_sync(0xffffffffu, sum1, 1);
    sum1 += __shfl_xor_sync(0xffffffffu, sum1, 2);

    float accO[16][4];
#pragma unroll
    for (int nt = 0; nt < 16; nt++)
#pragma unroll
        for (int u = 0; u < 4; u++) accO[nt][u] = 0.f;
#pragma unroll
    for (int pk = 0; pk < 8; pk++) {
        uint32_t ph[4], pl[4];
        ph[0] = packbf(S[2*pk][0], S[2*pk][1]);     pl[0] = packlo(S[2*pk][0], S[2*pk][1], ph[0]);
        ph[1] = packbf(S[2*pk][2], S[2*pk][3]);     pl[1] = packlo(S[2*pk][2], S[2*pk][3], ph[1]);
        ph[2] = packbf(S[2*pk+1][0], S[2*pk+1][1]); pl[2] = packlo(S[2*pk+1][0], S[2*pk+1][1], ph[2]);
        ph[3] = packbf(S[2*pk+1][2], S[2*pk+1][3]); pl[3] = packlo(S[2*pk+1][2], S[2*pk+1][3], ph[3]);
        uint32_t vo = ((uint32_t)(pk * 16 + (lane & 15)) * 136 + (lane >> 4) * 8) * 2;
#pragma unroll
        for (int ng4 = 0; ng4 < 8; ng4++) {
            uint32_t co = vo + ng4 * 16 * 2;
            uint32_t vh[4], vl[4];
            ldm_x4_t(vh, sb + 139264 + co);
            ldm_x4_t(vl, sb + 174080 + co);
            mma16816(accO[ng4*2],   ph, &vh[0]);
            mma16816(accO[ng4*2+1], ph, &vh[2]);
            mma16816(accO[ng4*2],   ph, &vl[0]);
            mma16816(accO[ng4*2+1], ph, &vl[2]);
            mma16816(accO[ng4*2],   pl, &vh[0]);
            mma16816(accO[ng4*2+1], pl, &vh[2]);
        }
    }

    const float as = fminf(ascale[0], 2.0f);
    const int r0 = q0 + wid * 16 + (lane >> 2);
    const int r1 = r0 + 8;
    int t0 = r0 / 384, rem0 = r0 % 384;
    int t1 = r1 / 384, rem1 = r1 % 384;
    float fm0 = fmask[t0 * 1536 + (rem0 / 16) * 64 + (rem0 % 16) * 2];
    float fm1 = fmask[t1 * 1536 + (rem1 / 16) * 64 + (rem1 % 16) * 2];
    float mf0 = fm0 * as / sum0;
    float mf1 = fm1 * as / sum1;
#pragma unroll
    for (int nt = 0; nt < 16; nt++) {
        int col = head * HDC + nt * 8 + (lane & 3) * 2;
        float2 c0 = *(float2*)&d_cat[(size_t)r0 * W2K + col];
        float2 c1 = *(float2*)&d_cat[(size_t)r1 * W2K + col];
        c0.x += accO[nt][0] * mf0; c0.y += accO[nt][1] * mf0;
        c1.x += accO[nt][2] * mf1; c1.y += accO[nt][3] * mf1;
        *(float2*)&d_cat[(size_t)r0 * W2K + col] = c0;
        *(float2*)&d_cat[(size_t)r1 * W2K + col] = c1;
    }
}

extern "C" void kernel_launch(void* const* d_in, const int* in_sizes, int n_in,
                              void* d_out, int out_size) {
    const float* x     = (const float*)d_in[0];
    const float* vec   = (const float*)d_in[1];
    const float* trv   = (const float*)d_in[2];
    const float* fcos  = (const float*)d_in[3];
    const float* fsin  = (const float*)d_in[4];
    const float* aemb  = (const float*)d_in[5];
    const float* fmask = (const float*)d_in[6];
    const int*   cu    = (const int*)d_in[7];
    const float* mw    = (const float*)d_in[10];
    const float* mb    = (const float*)d_in[11];
    const float* w1    = (const float*)d_in[12];
    const float* b1    = (const float*)d_in[13];
    const float* qnw   = (const float*)d_in[14];
    const float* knw   = (const float*)d_in[15];
    const float* w2    = (const float*)d_in[16];
    const float* b2    = (const float*)d_in[17];
    const float* aqw   = (const float*)d_in[18];
    const float* aqb   = (const float*)d_in[19];
    const float* aknw  = (const float*)d_in[21];
    const float* ascale= (const float*)d_in[22];
    float* out = (float*)d_out;

    float* h    = nullptr; cudaGetSymbolAddress((void**)&h,    d_h);
    float* aqkv = nullptr; cudaGetSymbolAddress((void**)&aqkv, d_aqkv);
    float* gp   = nullptr; cudaGetSymbolAddress((void**)&gp,   d_gp);
    __nv_bfloat16 *ahi, *alo, *anhi, *anlo, *chi, *clo;
    __nv_bfloat16 *w1h, *w1l, *w2h, *w2l, *awh, *awl;
    cudaGetSymbolAddress((void**)&ahi,  d_a_hi);  cudaGetSymbolAddress((void**)&alo,  d_a_lo);
    cudaGetSymbolAddress((void**)&anhi, d_an_hi); cudaGetSymbolAddress((void**)&anlo, d_an_lo);
    cudaGetSymbolAddress((void**)&chi,  d_cat_hi);cudaGetSymbolAddress((void**)&clo,  d_cat_lo);
    cudaGetSymbolAddress((void**)&w1h,  d_w1t_hi);cudaGetSymbolAddress((void**)&w1l,  d_w1t_lo);
    cudaGetSymbolAddress((void**)&w2h,  d_w2t_hi);cudaGetSymbolAddress((void**)&w2l,  d_w2t_lo);
    cudaGetSymbolAddress((void**)&awh,  d_awt_hi);cudaGetSymbolAddress((void**)&awl,  d_awt_lo);

    const int ATTN_SMEM = 208896;
    cudaFuncSetAttribute(attn_hmma,  cudaFuncAttributeMaxDynamicSharedMemorySize, ATTN_SMEM);
    cudaFuncSetAttribute(xattn_hmma, cudaFuncAttributeMaxDynamicSharedMemorySize, ATTN_SMEM);
    const int GEMM_SMEM = 81920;
    cudaFuncSetAttribute(hmma_gemm, cudaFuncAttributeMaxDynamicSharedMemorySize, GEMM_SMEM);
    const int GEMM_SMEM2 = 221184;
    cudaFuncSetAttribute(hmma_gemm_big<2>, cudaFuncAttributeMaxDynamicSharedMemorySize, GEMM_SMEM2);
    cudaFuncSetAttribute(hmma_gemm_big<3>, cudaFuncAttributeMaxDynamicSharedMemorySize, GEMM_SMEM2);

    mod_part<<<dim3(MODN / 128, 8), 512>>>(vec, trv, mw);
    mod_reduce<<<MODN / 256, 256>>>(mb);
    transpose_conv<<<dim3(W1N / 32, HIDC / 32), dim3(8, 32)>>>(w1, w1h, w1l, HIDC, W1N);
    ln_mod_kernel<<<LC, 256>>>(x);
    hmma_gemm_big<2><<<dim3(LC / 256, W1N / 128, 1), 256, GEMM_SMEM2>>>(ahi, alo, w1h, w1l, b1, h, LC, W1N, HIDC);
    transpose_conv<<<dim3(HIDC / 32, W2K / 32), dim3(8, 32)>>>(w2, w2h, w2l, W2K, HIDC);
    transpose_conv<<<dim3(MODN / 32, HIDC / 32), dim3(8, 32)>>>(aqw, awh, awl, HIDC, MODN);
    qkv_kernel<<<(LC * HEADSC) / 4, 128>>>(qnw, knw, fcos, fsin);
    attn_hmma<<<dim3(LC / 128, HEADSC), 256, ATTN_SMEM>>>(cu);
    ln_plain_kernel<<<NAUD, 256>>>(aemb);
    hmma_gemm<<<dim3(NAUD / 128, MODN / 128), 256, GEMM_SMEM>>>(anhi, anlo, awh, awl, aqb, aqkv, NAUD, MODN, HIDC);
    akv_kernel<<<(NAUD * HEADSC) / 4, 128>>>(aknw);
    xattn_hmma<<<dim3(LIMGC / 128, HEADSC), 256, ATTN_SMEM>>>(fmask, ascale);
    cat_conv_kernel<<<(int)(((size_t)LC * HIDC / 4) / 256), 256>>>();
    hmma_gemm_big<3><<<dim3(LC / 256, HIDC / 128, 3), 256, GEMM_SMEM2>>>(chi, clo, w2h, w2l, b2, gp, LC, HIDC, W2K);
    gemm2_combine<<<(int)(((size_t)LC * HIDC / 4) / 256), 256>>>(b2, x, out);
}

// round 13
// speedup vs baseline: 1.0421x; 1.0026x over previous
#include <cuda_runtime.h>
#include <cuda_bf16.h>
#include <math.h>
#include <stdint.h>

#define HIDC   3072
#define HEADSC 24
#define HDC    128
#define LC     2048
#define LIMGC  1920
#define FFNC   384
#define MLPDC  12288
#define W1N    21504
#define W2K    15360
#define MODN   9216
#define NAUD   128

// ---------------- scratch ----------------
__device__ float d_mod[MODN];
__device__ float d_trm[MODN];
__device__ float d_modp[8][MODN];
__device__ float d_trmp[8][MODN];
__device__ float d_cat[(size_t)LC * W2K];
__device__ float d_aqkv[(size_t)NAUD * MODN];
__device__ float d_gp[(size_t)3 * LC * HIDC];
__device__ __align__(16) __nv_bfloat16 d_a_hi[(size_t)LC * HIDC];
__device__ __align__(16) __nv_bfloat16 d_a_lo[(size_t)LC * HIDC];
__device__ __align__(16) __nv_bfloat16 d_an_hi[(size_t)NAUD * HIDC];
__device__ __align__(16) __nv_bfloat16 d_an_lo[(size_t)NAUD * HIDC];
__device__ __align__(16) __nv_bfloat16 d_cat_hi[(size_t)LC * W2K];
__device__ __align__(16) __nv_bfloat16 d_cat_lo[(size_t)LC * W2K];
__device__ __align__(16) __nv_bfloat16 d_w1t_hi[(size_t)W1N * HIDC];
__device__ __align__(16) __nv_bfloat16 d_w1t_lo[(size_t)W1N * HIDC];
__device__ __align__(16) __nv_bfloat16 d_w2t_hi[(size_t)HIDC * W2K];
__device__ __align__(16) __nv_bfloat16 d_w2t_lo[(size_t)HIDC * W2K];
__device__ __align__(16) __nv_bfloat16 d_awt_hi[(size_t)MODN * HIDC];
__device__ __align__(16) __nv_bfloat16 d_awt_lo[(size_t)MODN * HIDC];
__device__ __align__(16) __nv_bfloat16 d_q_hi[(size_t)LC * HIDC];
__device__ __align__(16) __nv_bfloat16 d_q_lo[(size_t)LC * HIDC];
__device__ __align__(16) __nv_bfloat16 d_k_hi[(size_t)LC * HIDC];
__device__ __align__(16) __nv_bfloat16 d_k_lo[(size_t)LC * HIDC];
__device__ __align__(16) __nv_bfloat16 d_v_hi[(size_t)LC * HIDC];
__device__ __align__(16) __nv_bfloat16 d_v_lo[(size_t)LC * HIDC];
__device__ __align__(16) __nv_bfloat16 d_ak_hi[(size_t)NAUD * HIDC];
__device__ __align__(16) __nv_bfloat16 d_ak_lo[(size_t)NAUD * HIDC];
__device__ __align__(16) __nv_bfloat16 d_av_hi[(size_t)NAUD * HIDC];
__device__ __align__(16) __nv_bfloat16 d_av_lo[(size_t)NAUD * HIDC];

// ---------------- helpers ----------------
__device__ __forceinline__ uint32_t smem_u32(const void* p) {
    uint32_t a;
    asm("{ .reg .u64 t; cvta.to.shared.u64 t, %1; cvt.u32.u64 %0, t; }" : "=r"(a) : "l"(p));
    return a;
}
__device__ __forceinline__ void ldm_x4(uint32_t* r, uint32_t addr) {
    asm volatile("ldmatrix.sync.aligned.m8n8.x4.shared.b16 {%0,%1,%2,%3}, [%4];"
        : "=r"(r[0]), "=r"(r[1]), "=r"(r[2]), "=r"(r[3]) : "r"(addr));
}
__device__ __forceinline__ void ldm_x4_t(uint32_t* r, uint32_t addr) {
    asm volatile("ldmatrix.sync.aligned.m8n8.x4.trans.shared.b16 {%0,%1,%2,%3}, [%4];"
        : "=r"(r[0]), "=r"(r[1]), "=r"(r[2]), "=r"(r[3]) : "r"(addr));
}
__device__ __forceinline__ void mma16816(float* d, const uint32_t* a, const uint32_t* b) {
    asm volatile("mma.sync.aligned.m16n8k16.row.col.f32.bf16.bf16.f32 "
        "{%0,%1,%2,%3}, {%4,%5,%6,%7}, {%8,%9}, {%0,%1,%2,%3};"
        : "+f"(d[0]), "+f"(d[1]), "+f"(d[2]), "+f"(d[3])
        : "r"(a[0]), "r"(a[1]), "r"(a[2]), "r"(a[3]), "r"(b[0]), "r"(b[1]));
}
__device__ __forceinline__ void cp16(uint32_t dst, const void* src) {
    asm volatile("cp.async.cg.shared.global [%0], [%1], 16;" :: "r"(dst), "l"(src));
}
#define CP_COMMIT() asm volatile("cp.async.commit_group;" ::: "memory")
#define CP_WAIT(n)  asm volatile("cp.async.wait_group %0;" :: "n"(n) : "memory")

__device__ __forceinline__ uint32_t packbf(float a, float b) {
    __nv_bfloat162 t = __floats2bfloat162_rn(a, b);
    return *reinterpret_cast<uint32_t*>(&t);
}
__device__ __forceinline__ uint32_t packlo(float a, float b, uint32_t hi) {
    __nv_bfloat162 h = *reinterpret_cast<__nv_bfloat162*>(&hi);
    return packbf(a - __bfloat162float(h.x), b - __bfloat162float(h.y));
}
__device__ __forceinline__ float gelu_fast(float x) {
    float u2 = 1.5957691216057308f * (x + 0.044715f * x * x * x);
    return x / (1.f + __expf(-u2));
}
__device__ __forceinline__ void block_reduce2(float& s, float& s2, float* buf) {
    int tid = threadIdx.x, lane = tid & 31, w = tid >> 5;
#pragma unroll
    for (int o = 16; o > 0; o >>= 1) {
        s  += __shfl_xor_sync(0xffffffffu, s,  o);
        s2 += __shfl_xor_sync(0xffffffffu, s2, o);
    }
    if (lane == 0) { buf[w] = s; buf[32 + w] = s2; }
    __syncthreads();
    if (tid == 0) {
        float a = 0.f, b = 0.f;
#pragma unroll
        for (int i = 0; i < 8; i++) { a += buf[i]; b += buf[32 + i]; }
        buf[0] = a; buf[32] = b;
    }
    __syncthreads();
    s = buf[0]; s2 = buf[32];
}
__device__ __forceinline__ void split_store4(__nv_bfloat16* hi, __nv_bfloat16* lo, size_t i, float4 v) {
    __nv_bfloat162 h0 = __floats2bfloat162_rn(v.x, v.y);
    __nv_bfloat162 h1 = __floats2bfloat162_rn(v.z, v.w);
    *(uint2*)&hi[i] = make_uint2(*(uint32_t*)&h0, *(uint32_t*)&h1);
    __nv_bfloat162 l0 = __floats2bfloat162_rn(v.x - __bfloat162float(h0.x), v.y - __bfloat162float(h0.y));
    __nv_bfloat162 l1 = __floats2bfloat162_rn(v.z - __bfloat162float(h1.x), v.w - __bfloat162float(h1.y));
    *(uint2*)&lo[i] = make_uint2(*(uint32_t*)&l0, *(uint32_t*)&l1);
}
__device__ __forceinline__ void split_store2(__nv_bfloat16* hi, __nv_bfloat16* lo, size_t i, float a, float b) {
    __nv_bfloat162 h = __floats2bfloat162_rn(a, b);
    *(uint32_t*)&hi[i] = *(uint32_t*)&h;
    __nv_bfloat162 l = __floats2bfloat162_rn(a - __bfloat162float(h.x), b - __bfloat162float(h.y));
    *(uint32_t*)&lo[i] = *(uint32_t*)&l;
}

// ---------------- transpose + bf16 split ----------------
__global__ void transpose_conv(const float* __restrict__ W, __nv_bfloat16* __restrict__ hi,
                               __nv_bfloat16* __restrict__ lo, int K, int N) {
    __shared__ float t[32][36];
    int n0 = blockIdx.x * 32, k0 = blockIdx.y * 32;
    int tx = threadIdx.x;
    int ty = threadIdx.y;
    float4 v = *(const float4*)&W[(size_t)(k0 + ty) * N + n0 + tx * 4];
    t[ty][tx * 4 + 0] = v.x; t[ty][tx * 4 + 1] = v.y;
    t[ty][tx * 4 + 2] = v.z; t[ty][tx * 4 + 3] = v.w;
    __syncthreads();
    float4 o = make_float4(t[tx * 4 + 0][ty], t[tx * 4 + 1][ty],
                           t[tx * 4 + 2][ty], t[tx * 4 + 3][ty]);
    split_store4(hi, lo, (size_t)(n0 + ty) * K + k0 + tx * 4, o);
}

// ---------------- mod partials ----------------
__global__ void mod_part(const float* __restrict__ vec, const float* __restrict__ trv,
                         const float* __restrict__ mw) {
    __shared__ float sv[384], st[384];
    __shared__ float part[2][4][128];
    int tid = threadIdx.x, by = blockIdx.y;
    if (tid < 384) {
        int k = by * 384 + tid;
        float a = vec[k]; sv[tid] = a / (1.f + expf(-a));
        float b = trv[k]; st[tid] = b / (1.f + expf(-b));
    }
    __syncthreads();
    int jl = tid & 127, sl = tid >> 7;
    int j = blockIdx.x * 128 + jl;
    float a0 = 0.f, a1 = 0.f;
    int kend = (sl + 1) * 96;
    for (int kl = sl * 96; kl < kend; kl++) {
        float w = mw[(size_t)(by * 384 + kl) * MODN + j];
        a0 = fmaf(sv[kl], w, a0);
        a1 = fmaf(st[kl], w, a1);
    }
    part[0][sl][jl] = a0; part[1][sl][jl] = a1;
    __syncthreads();
    if (tid < 128) {
        int jj = blockIdx.x * 128 + tid;
        d_modp[by][jj] = part[0][0][tid] + part[0][1][tid] + part[0][2][tid] + part[0][3][tid];
    } else if (tid < 256) {
        int t = tid - 128, jj = blockIdx.x * 128 + t;
        d_trmp[by][jj] = part[1][0][t] + part[1][1][t] + part[1][2][t] + part[1][3][t];
    }
}
__global__ void mod_reduce(const float* __restrict__ mb) {
    int j = blockIdx.x * 256 + threadIdx.x;
    float s0 = mb[j], s1 = mb[j];
#pragma unroll
    for (int p = 0; p < 8; p++) { s0 += d_modp[p][j]; s1 += d_trmp[p][j]; }
    d_mod[j] = s0; d_trm[j] = s1;
}

// ---------------- LN + modulate -> bf16 hi/lo ----------------
__global__ void ln_mod_kernel(const float* __restrict__ x) {
    int row = blockIdx.x, tid = threadIdx.x;
    const float* xr = x + (size_t)row * HIDC;
    float s = 0.f, s2 = 0.f;
    for (int j = tid * 4; j < HIDC; j += 1024) {
        float4 v = *(const float4*)&xr[j];
        s  += v.x + v.y + v.z + v.w;
        s2 += v.x*v.x + v.y*v.y + v.z*v.z + v.w*v.w;
    }
    __shared__ float buf[64];
    block_reduce2(s, s2, buf);
    float mean = s * (1.f / HIDC);
    float inv = rsqrtf(s2 * (1.f / HIDC) - mean * mean + 1e-6f);
    const float* mv = (row < FFNC) ? d_trm : d_mod;
    for (int j = tid * 4; j < HIDC; j += 1024) {
        float4 v  = *(const float4*)&xr[j];
        float4 sc = *(const float4*)&mv[HIDC + j];
        float4 sh = *(const float4*)&mv[j];
        float4 o;
        o.x = (v.x - mean) * inv * (1.f + sc.x) + sh.x;
        o.y = (v.y - mean) * inv * (1.f + sc.y) + sh.y;
        o.z = (v.z - mean) * inv * (1.f + sc.z) + sh.z;
        o.w = (v.w - mean) * inv * (1.f + sc.w) + sh.w;
        split_store4(d_a_hi, d_a_lo, (size_t)row * HIDC + j, o);
    }
}

// ---------------- audio LN -> bf16 hi/lo ----------------
__global__ void ln_plain_kernel(const float* __restrict__ a) {
    int row = blockIdx.x, tid = threadIdx.x;
    const float* xr = a + (size_t)row * HIDC;
    float s = 0.f, s2 = 0.f;
    for (int j = tid * 4; j < HIDC; j += 1024) {
        float4 v = *(const float4*)&xr[j];
        s  += v.x + v.y + v.z + v.w;
        s2 += v.x*v.x + v.y*v.y + v.z*v.z + v.w*v.w;
    }
    __shared__ float buf[64];
    block_reduce2(s, s2, buf);
    float mean = s * (1.f / HIDC);
    float inv = rsqrtf(s2 * (1.f / HIDC) - mean * mean + 1e-6f);
    for (int j = tid * 4; j < HIDC; j += 1024) {
        float4 v = *(const float4*)&xr[j];
        float4 o = make_float4((v.x - mean) * inv, (v.y - mean) * inv,
                               (v.z - mean) * inv, (v.w - mean) * inv);
        split_store4(d_an_hi, d_an_lo, (size_t)row * HIDC + j, o);
    }
}

// ---------------- GEMM2 combine ----------------
__global__ void gemm2_combine(const float* __restrict__ bias, const float* __restrict__ resid,
                              float* __restrict__ out) {
    size_t i = ((size_t)blockIdx.x * 256 + threadIdx.x) * 4;
    int m = (int)(i / HIDC), n = (int)(i % HIDC);
    const float* gv = (m < FFNC) ? d_trm : d_mod;
    float4 p0 = *(const float4*)&d_gp[i];
    float4 p1 = *(const float4*)&d_gp[(size_t)LC * HIDC + i];
    float4 p2 = *(const float4*)&d_gp[(size_t)2 * LC * HIDC + i];
    float4 bb = *(const float4*)&bias[n];
    float4 gg = *(const float4*)&gv[2 * HIDC + n];
    float4 rr = *(const float4*)&resid[i];
    float4 o;
    o.x = rr.x + (p0.x + p1.x + p2.x + bb.x) * gg.x;
    o.y = rr.y + (p0.y + p1.y + p2.y + bb.y) * gg.y;
    o.z = rr.z + (p0.z + p1.z + p2.z + bb.z) * gg.z;
    o.w = rr.w + (p0.w + p1.w + p2.w + bb.w) * gg.w;
    *(float4*)&out[i] = o;
}

// ---------------- big HMMA GEMM: 256x128 CTA, 64x64 warp, BK=64, 2 stages ----------------
// MODE 2 (GEMM1): q/k region -> fused rms+rope+split to d_q/d_k; v -> split; mlp -> gelu split.
// MODE 3 (GEMM2 split-K): partial fp32 -> C + z*M*N.
template<int MODE>
__global__ void __launch_bounds__(256, 1) hmma_gemm_big(
        const __nv_bfloat16* __restrict__ Ahi, const __nv_bfloat16* __restrict__ Alo,
        const __nv_bfloat16* __restrict__ Bhi, const __nv_bfloat16* __restrict__ Blo,
        const float* __restrict__ bias, float* __restrict__ C,
        int M, int N, int K,
        const float* __restrict__ qnw, const float* __restrict__ knw,
        const float* __restrict__ fcos, const float* __restrict__ fsin) {
    extern __shared__ char smraw[];
    const int tid = threadIdx.x;
    const int lane = tid & 31, wid = tid >> 5;
    const int bm = blockIdx.x * 256, bn = blockIdx.y * 128;
    const int wm = wid & 3, wn = wid >> 2;
    const int Kper = K / gridDim.z;
    const int ko = blockIdx.z * Kper;
    const uint32_t sbase = smem_u32(smraw);
    const __nv_bfloat16* srcs[4] = {
        Ahi + (size_t)bm * K + ko, Alo + (size_t)bm * K + ko,
        Bhi + (size_t)bn * K + ko, Blo + (size_t)bn * K + ko };

    float acc[4][8][4];
#pragma unroll
    for (int a = 0; a < 4; a++)
#pragma unroll
        for (int b = 0; b < 8; b++)
#pragma unroll
            for (int c = 0; c < 4; c++) acc[a][b][c] = 0.f;

    const int NC = Kper >> 6;
#pragma unroll
    for (int i = 0; i < 24; i++) {
        int id = tid + i * 256;
        if (id < 4096) {
            int op = id >> 11, rem = id & 2047, r = rem >> 3, q = rem & 7;
            cp16(sbase + op * 36864 + r * 144 + q * 16, srcs[op] + (size_t)r * K + q * 8);
        } else {
            int t = id - 4096, op = t >> 10, rem = t & 1023, r = rem >> 3, q = rem & 7;
            cp16(sbase + 73728 + op * 18432 + r * 144 + q * 16, srcs[2 + op] + (size_t)r * K + q * 8);
        }
    }
    CP_COMMIT();

    for (int c = 0; c < NC; c++) {
        const int stage = c & 1;
        if (c + 1 < NC) {
            const int kc = (c + 1) << 6;
            const uint32_t db = sbase + (stage ^ 1) * 110592;
#pragma unroll
            for (int i = 0; i < 24; i++) {
                int id = tid + i * 256;
                if (id < 4096) {
                    int op = id >> 11, rem = id & 2047, r = rem >> 3, q = rem & 7;
                    cp16(db + op * 36864 + r * 144 + q * 16, srcs[op] + (size_t)r * K + kc + q * 8);
                } else {
                    int t = id - 4096, op = t >> 10, rem = t & 1023, r = rem >> 3, q = rem & 7;
                    cp16(db + 73728 + op * 18432 + r * 144 + q * 16, srcs[2 + op] + (size_t)r * K + kc + q * 8);
                }
            }
            CP_COMMIT();
            CP_WAIT(1);
        } else {
            CP_WAIT(0);
        }
        __syncthreads();
        const uint32_t base = sbase + stage * 110592;
#pragma unroll
        for (int kk = 0; kk < 4; kk++) {
            uint32_t afr[2][4][4];
            uint32_t bfr[2][4][4];
            const uint32_t aoff = (uint32_t)(wm * 64 + (lane & 15)) * 144 + kk * 32 + (lane >> 4) * 16;
#pragma unroll
            for (int op = 0; op < 2; op++)
#pragma unroll
                for (int mi = 0; mi < 4; mi++)
                    ldm_x4(afr[op][mi], base + op * 36864 + aoff + mi * 16 * 144);
            const uint32_t boff = (uint32_t)(wn * 64 + ((lane >> 4) & 1) * 8 + (lane & 7)) * 144
                                  + kk * 32 + ((lane >> 3) & 1) * 16;
#pragma unroll
            for (int op = 0; op < 2; op++)
#pragma unroll
                for (int ng = 0; ng < 4; ng++)
                    ldm_x4(bfr[op][ng], base + 73728 + op * 18432 + boff + ng * 16 * 144);
#pragma unroll
            for (int cmb = 0; cmb < 3; cmb++) {
                const int ao = (cmb == 2) ? 1 : 0;
                const int bo = (cmb == 1) ? 1 : 0;
#pragma unroll
                for (int mi = 0; mi < 4; mi++)
#pragma unroll
                    for (int ng = 0; ng < 4; ng++) {
                        mma16816(acc[mi][ng * 2 + 0], afr[ao][mi], &bfr[bo][ng][0]);
                        mma16816(acc[mi][ng * 2 + 1], afr[ao][mi], &bfr[bo][ng][2]);
                    }
            }
        }
        __syncthreads();
    }
    const int gid = lane >> 2, tq = (lane & 3) << 1;

    if (MODE == 2 && bn < 2 * HIDC) {
        // fused bias + RMS + RoPE + bf16 split for q/k (CTA covers one head)
        __syncthreads();
        float* red = (float*)smraw;   // 512 floats
#pragma unroll
        for (int mi = 0; mi < 4; mi++)
#pragma unroll
            for (int ni = 0; ni < 8; ni++) {
                int n = bn + wn * 64 + ni * 8 + tq;
                float b0 = bias[n], b1 = bias[n + 1];
                acc[mi][ni][0] += b0; acc[mi][ni][1] += b1;
                acc[mi][ni][2] += b0; acc[mi][ni][3] += b1;
            }
#pragma unroll
        for (int mi = 0; mi < 4; mi++)
#pragma unroll
            for (int half = 0; half < 2; half++) {
                float s = 0.f;
#pragma unroll
                for (int ni = 0; ni < 8; ni++) {
                    float v0 = acc[mi][ni][half * 2], v1 = acc[mi][ni][half * 2 + 1];
                    s += v0 * v0 + v1 * v1;
                }
                s += __shfl_xor_sync(0xffffffffu, s, 1);
                s += __shfl_xor_sync(0xffffffffu, s, 2);
                if ((lane & 3) == 0)
                    red[wn * 256 + wm * 64 + mi * 16 + half * 8 + gid] = s;
            }
        __syncthreads();
        const bool isq = bn < HIDC;
        const int head = (isq ? bn : bn - HIDC) >> 7;
        const float* rw = isq ? qnw : knw;
        __nv_bfloat16* ohi = isq ? d_q_hi : d_k_hi;
        __nv_bfloat16* olo = isq ? d_q_lo : d_k_lo;
#pragma unroll
        for (int mi = 0; mi < 4; mi++)
#pragma unroll
            for (int half = 0; half < 2; half++) {
                int rloc = wm * 64 + mi * 16 + half * 8 + gid;
                int m = bm + rloc;
                float rs = rsqrtf((red[rloc] + red[256 + rloc]) * (1.f / HDC) + 1e-6f);
                bool rope = m < LIMGC;
#pragma unroll
                for (int ni = 0; ni < 8; ni++) {
                    int cd = wn * 64 + ni * 8 + tq;
                    float v0 = acc[mi][ni][half * 2]     * rs * rw[cd];
                    float v1 = acc[mi][ni][half * 2 + 1] * rs * rw[cd + 1];
                    if (rope) {
                        float cc = fcos[m * HDC + cd];
                        float sc = fsin[m * HDC + cd];
                        float n0 = v0 * cc - v1 * sc;
                        float n1 = v1 * cc + v0 * sc;
                        v0 = n0; v1 = n1;
                    }
                    split_store2(ohi, olo, (size_t)m * HIDC + head * HDC + cd, v0, v1);
                }
            }
        return;
    }

    float* Cz = (MODE == 3) ? (C + (size_t)blockIdx.z * M * N) : C;
#pragma unroll
    for (int mi = 0; mi < 4; mi++) {
#pragma unroll
        for (int half = 0; half < 2; half++) {
            const int m = bm + wm * 64 + mi * 16 + half * 8 + gid;
#pragma unroll
            for (int ni = 0; ni < 8; ni++) {
                const int n = bn + wn * 64 + ni * 8 + tq;
                if (MODE == 3) {
                    *(float2*)&Cz[(size_t)m * N + n] =
                        make_float2(acc[mi][ni][half * 2 + 0], acc[mi][ni][half * 2 + 1]);
                } else {
                    float v0 = acc[mi][ni][half * 2 + 0] + bias[n];
                    float v1 = acc[mi][ni][half * 2 + 1] + bias[n + 1];
                    if (n < 3 * HIDC) {
                        size_t idx = (size_t)m * HIDC + (n - 2 * HIDC);
                        split_store2(d_v_hi, d_v_lo, idx, v0, v1);
                    } else {
                        size_t idx = (size_t)m * W2K + (n - 2 * HIDC);
                        split_store2(d_cat_hi, d_cat_lo, idx, gelu_fast(v0), gelu_fast(v1));
                    }
                }
            }
        }
    }
}

// ---------------- small HMMA GEMM (128x128) for audio path ----------------
__global__ void __launch_bounds__(256, 1) hmma_gemm(
        const __nv_bfloat16* __restrict__ Ahi, const __nv_bfloat16* __restrict__ Alo,
        const __nv_bfloat16* __restrict__ Bhi, const __nv_bfloat16* __restrict__ Blo,
        const float* __restrict__ bias, float* __restrict__ C,
        int M, int N, int K) {
    extern __shared__ char smraw[];
    const int tid = threadIdx.x;
    const int lane = tid & 31, wid = tid >> 5;
    const int bm = blockIdx.x * 128, bn = blockIdx.y * 128;
    const int wm = wid & 3, wn = wid >> 2;
    const uint32_t sbase = smem_u32(smraw);
    const __nv_bfloat16* srcs[4] = {
        Ahi + (size_t)bm * K, Alo + (size_t)bm * K,
        Bhi + (size_t)bn * K, Blo + (size_t)bn * K };
    float acc[2][8][4];
#pragma unroll
    for (int a = 0; a < 2; a++)
#pragma unroll
        for (int b = 0; b < 8; b++)
#pragma unroll
            for (int c = 0; c < 4; c++) acc[a][b][c] = 0.f;
    const int NC = K >> 5;
    {
#pragma unroll
        for (int i = 0; i < 8; i++) {
            int id = tid + i * 256;
            int op = id >> 9, rem = id & 511;
            int r = rem >> 2, q = rem & 3;
            cp16(sbase + op * 10240 + r * 80 + q * 16, srcs[op] + (size_t)r * K + q * 8);
        }
        CP_COMMIT();
    }
    for (int c = 0; c < NC; c++) {
        const int stage = c & 1;
        if (c + 1 < NC) {
            const int kc = (c + 1) << 5;
            const uint32_t db = sbase + (stage ^ 1) * 40960;
#pragma unroll
            for (int i = 0; i < 8; i++) {
                int id = tid + i * 256;
                int op = id >> 9, rem = id & 511;
                int r = rem >> 2, q = rem & 3;
                cp16(db + op * 10240 + r * 80 + q * 16, srcs[op] + (size_t)r * K + kc + q * 8);
            }
            CP_COMMIT();
            CP_WAIT(1);
        } else {
            CP_WAIT(0);
        }
        __syncthreads();
        const uint32_t base = sbase + stage * 40960;
#pragma unroll
        for (int kk = 0; kk < 2; kk++) {
            uint32_t afr[2][2][4];
            uint32_t bfr[2][4][4];
            const uint32_t aoff = (uint32_t)(wm * 32 + (lane & 15)) * 80 + kk * 32 + (lane >> 4) * 16;
#pragma unroll
            for (int op = 0; op < 2; op++)
#pragma unroll
                for (int mi = 0; mi < 2; mi++)
                    ldm_x4(afr[op][mi], base + op * 10240 + aoff + mi * 16 * 80);
            const uint32_t boff = (uint32_t)(wn * 64 + ((lane >> 4) & 1) * 8 + (lane & 7)) * 80
                                  + kk * 32 + ((lane >> 3) & 1) * 16;
#pragma unroll
            for (int op = 0; op < 2; op++)
#pragma unroll
                for (int ng = 0; ng < 4; ng++)
                    ldm_x4(bfr[op][ng], base + 20480 + op * 10240 + boff + ng * 16 * 80);
#pragma unroll
            for (int cmb = 0; cmb < 3; cmb++) {
                const int ao = (cmb == 2) ? 1 : 0;
                const int bo = (cmb == 1) ? 1 : 0;
#pragma unroll
                for (int mi = 0; mi < 2; mi++)
#pragma unroll
                    for (int ng = 0; ng < 4; ng++) {
                        mma16816(acc[mi][ng * 2 + 0], afr[ao][mi], &bfr[bo][ng][0]);
                        mma16816(acc[mi][ng * 2 + 1], afr[ao][mi], &bfr[bo][ng][2]);
                    }
            }
        }
        __syncthreads();
    }
    const int gid = lane >> 2, tq = (lane & 3) << 1;
#pragma unroll
    for (int mi = 0; mi < 2; mi++) {
        const int m0 = bm + wm * 32 + mi * 16 + gid;
        const int m1 = m0 + 8;
#pragma unroll
        for (int ni = 0; ni < 8; ni++) {
            const int n = bn + wn * 64 + ni * 8 + tq;
            const float b0 = bias[n], b1 = bias[n + 1];
            size_t off0 = (size_t)m0 * N + n;
            size_t off1 = (size_t)m1 * N + n;
            *(float2*)&C[off0] = make_float2(acc[mi][ni][0] + b0, acc[mi][ni][1] + b1);
            *(float2*)&C[off1] = make_float2(acc[mi][ni][2] + b0, acc[mi][ni][3] + b1);
        }
    }
}

// ---------------- audio k RMS + v -> bf16 hi/lo ----------------
__global__ void akv_kernel(const float* __restrict__ kw) {
    int gwarp = blockIdx.x * 4 + (threadIdx.x >> 5);
    int lane = threadIdx.x & 31;
    int tok = gwarp / HEADSC, head = gwarp % HEADSC;
    const float* p = d_aqkv + (size_t)tok * MODN + HIDC + head * HDC;
    size_t bidx = (size_t)tok * HIDC + head * HDC + lane * 4;
    float4 v = *(const float4*)&p[lane * 4];
    float ss = v.x*v.x + v.y*v.y + v.z*v.z + v.w*v.w;
#pragma unroll
    for (int o = 16; o > 0; o >>= 1) ss += __shfl_xor_sync(0xffffffffu, ss, o);
    float inv = rsqrtf(ss * (1.f / HDC) + 1e-6f);
    float4 ww = *(const float4*)&kw[lane * 4];
    v.x *= inv * ww.x; v.y *= inv * ww.y; v.z *= inv * ww.z; v.w *= inv * ww.w;
    split_store4(d_ak_hi, d_ak_lo, bidx, v);
    float4 vv = *(const float4*)&p[HIDC + lane * 4];
    split_store4(d_av_hi, d_av_lo, bidx, vv);
}

// ---------------- HMMA flash self-attention, 128q x 128k tiles ----------------
__global__ void __launch_bounds__(256, 1) attn_hmma(const int* __restrict__ cu) {
    extern __shared__ __nv_bfloat16 smb[];
    const int tid = threadIdx.x, lane = tid & 31, wid = tid >> 5;
    const int head = blockIdx.y, q0 = blockIdx.x * 128;
    const int G = cu[1] - cu[0];
    const size_t colbase = (size_t)head * HDC;
    const uint32_t sb = smem_u32(smb);
    const float scale = 0.08838834764831845f;

    for (int i = tid; i < 2048; i += 256) {
        int r = i >> 4, c8 = (i & 15) * 8;
        size_t g = (size_t)(q0 + r) * HIDC + colbase + c8;
        *(uint4*)&smb[r * 136 + c8]          = *(const uint4*)&d_q_hi[g];
        *(uint4*)&smb[17408 + r * 136 + c8]  = *(const uint4*)&d_q_lo[g];
    }

    float accO[16][4];
#pragma unroll
    for (int nt = 0; nt < 16; nt++)
#pragma unroll
        for (int u = 0; u < 4; u++) accO[nt][u] = 0.f;
    float m0 = -INFINITY, m1 = -INFINITY, l0 = 0.f, l1 = 0.f;

    const int r0 = q0 + wid * 16 + (lane >> 2);
    const bool qg0 = r0 < G, qg1 = (r0 + 8) < G;

    for (int kt = 0; kt < LC / 128; kt++) {
        __syncthreads();
        for (int i = tid; i < 2048; i += 256) {
            int r = i >> 4, c8 = (i & 15) * 8;
            size_t g = (size_t)(kt * 128 + r) * HIDC + colbase + c8;
            int so = r * 136 + c8;
            *(uint4*)&smb[34816 + so] = *(const uint4*)&d_k_hi[g];
            *(uint4*)&smb[52224 + so] = *(const uint4*)&d_k_lo[g];
            *(uint4*)&smb[69632 + so] = *(const uint4*)&d_v_hi[g];
            *(uint4*)&smb[87040 + so] = *(const uint4*)&d_v_lo[g];
        }
        __syncthreads();

        float S[16][4];
#pragma unroll
        for (int nt = 0; nt < 16; nt++)
#pragma unroll
            for (int u = 0; u < 4; u++) S[nt][u] = 0.f;
#pragma unroll
        for (int half = 0; half < 2; half++) {
#pragma unroll
            for (int ks = 0; ks < 8; ks++) {
                uint32_t qa[2][4], kb[2][4][4];
                uint32_t aoff = ((uint32_t)(wid * 16 + (lane & 15)) * 136 + ks * 16 + (lane >> 4) * 8) * 2;
                ldm_x4(qa[0], sb + aoff);
                ldm_x4(qa[1], sb + 34816 + aoff);
                uint32_t bo_ = ((uint32_t)(half * 64 + ((lane >> 4) & 1) * 8 + (lane & 7)) * 136
                                + ks * 16 + ((lane >> 3) & 1) * 8) * 2;
#pragma unroll
                for (int ng = 0; ng < 4; ng++) {
                    uint32_t ro = bo_ + ng * 16 * 136 * 2;
                    ldm_x4(kb[0][ng], sb + 69632 + ro);
                    ldm_x4(kb[1][ng], sb + 104448 + ro);
                }
#pragma unroll
                for (int cmb = 0; cmb < 3; cmb++) {
                    const int ao = (cmb == 2) ? 1 : 0;
                    const int bo = (cmb == 1) ? 1 : 0;
#pragma unroll
                    for (int nt = 0; nt < 8; nt++)
                        mma16816(S[half * 8 + nt], qa[ao], &kb[bo][nt >> 1][(nt & 1) * 2]);
                }
            }
        }

#pragma unroll
        for (int nt = 0; nt < 16; nt++) {
            int key0 = kt * 128 + nt * 8 + (lane & 3) * 2;
            bool k0g = key0 < G, k1g = (key0 + 1) < G;
            S[nt][0] = (k0g == qg0) ? S[nt][0] * scale : -1e9f;
            S[nt][1] = (k1g == qg0) ? S[nt][1] * scale : -1e9f;
            S[nt][2] = (k0g == qg1) ? S[nt][2] * scale : -1e9f;
            S[nt][3] = (k1g == qg1) ? S[nt][3] * scale : -1e9f;
        }
        float tm0 = -INFINITY, tm1 = -INFINITY;
#pragma unroll
        for (int nt = 0; nt < 16; nt++) {
            tm0 = fmaxf(tm0, fmaxf(S[nt][0], S[nt][1]));
            tm1 = fmaxf(tm1, fmaxf(S[nt][2], S[nt][3]));
        }
        tm0 = fmaxf(tm0, __shfl_xor_sync(0xffffffffu, tm0, 1));
        tm0 = fmaxf(tm0, __shfl_xor_sync(0xffffffffu, tm0, 2));
        tm1 = fmaxf(tm1, __shfl_xor_sync(0xffffffffu, tm1, 1));
        tm1 = fmaxf(tm1, __shfl_xor_sync(0xffffffffu, tm1, 2));
        float mn0 = fmaxf(m0, tm0), mn1 = fmaxf(m1, tm1);
        float al0 = __expf(m0 - mn0), al1 = __expf(m1 - mn1);
        float sum0 = 0.f, sum1 = 0.f;
#pragma unroll
        for (int nt = 0; nt < 16; nt++) {
            S[nt][0] = __expf(S[nt][0] - mn0);
            S[nt][1] = __expf(S[nt][1] - mn0);
            S[nt][2] = __expf(S[nt][2] - mn1);
            S[nt][3] = __expf(S[nt][3] - mn1);
            sum0 += S[nt][0] + S[nt][1];
            sum1 += S[nt][2] + S[nt][3];
        }
        sum0 += __shfl_xor_sync(0xffffffffu, sum0, 1);
        sum0 += __shfl_xor_sync(0xffffffffu, sum0, 2);
        sum1 += __shfl_xor_sync(0xffffffffu, sum1, 1);
        sum1 += __shfl_xor_sync(0xffffffffu, sum1, 2);
        l0 = l0 * al0 + sum0;
        l1 = l1 * al1 + sum1;
        m0 = mn0; m1 = mn1;
#pragma unroll
        for (int nt = 0; nt < 16; nt++) {
            accO[nt][0] *= al0; accO[nt][1] *= al0;
            accO[nt][2] *= al1; accO[nt][3] *= al1;
        }

#pragma unroll
        for (int pk = 0; pk < 8; pk++) {
            uint32_t ph[4], pl[4];
            ph[0] = packbf(S[2*pk][0], S[2*pk][1]);     pl[0] = packlo(S[2*pk][0], S[2*pk][1], ph[0]);
            ph[1] = packbf(S[2*pk][2], S[2*pk][3]);     pl[1] = packlo(S[2*pk][2], S[2*pk][3], ph[1]);
            ph[2] = packbf(S[2*pk+1][0], S[2*pk+1][1]); pl[2] = packlo(S[2*pk+1][0], S[2*pk+1][1], ph[2]);
            ph[3] = packbf(S[2*pk+1][2], S[2*pk+1][3]); pl[3] = packlo(S[2*pk+1][2], S[2*pk+1][3], ph[3]);
            uint32_t vo = ((uint32_t)(pk * 16 + (lane & 15)) * 136 + (lane >> 4) * 8) * 2;
#pragma unroll
            for (int ng4 = 0; ng4 < 8; ng4++) {
                uint32_t co = vo + ng4 * 16 * 2;
                uint32_t vh[4], vl[4];
                ldm_x4_t(vh, sb + 139264 + co);
                ldm_x4_t(vl, sb + 174080 + co);
                mma16816(accO[ng4*2],   ph, &vh[0]);
                mma16816(accO[ng4*2+1], ph, &vh[2]);
                mma16816(accO[ng4*2],   ph, &vl[0]);
                mma16816(accO[ng4*2+1], ph, &vl[2]);
                mma16816(accO[ng4*2],   pl, &vh[0]);
                mma16816(accO[ng4*2+1], pl, &vh[2]);
            }
        }
    }

    float inv0 = 1.f / l0, inv1 = 1.f / l1;
    const bool txt_tile = (blockIdx.x == LC / 128 - 1);   // rows >= LIMGC: final -> split-store
#pragma unroll
    for (int nt = 0; nt < 16; nt++) {
        int col = head * HDC + nt * 8 + (lane & 3) * 2;
        float a0 = accO[nt][0] * inv0, a1 = accO[nt][1] * inv0;
        float b0 = accO[nt][2] * inv1, b1 = accO[nt][3] * inv1;
        if (txt_tile) {
            split_store2(d_cat_hi, d_cat_lo, (size_t)r0 * W2K + col, a0, a1);
            split_store2(d_cat_hi, d_cat_lo, (size_t)(r0 + 8) * W2K + col, b0, b1);
        } else {
            *(float2*)&d_cat[(size_t)r0 * W2K + col]       = make_float2(a0, a1);
            *(float2*)&d_cat[(size_t)(r0 + 8) * W2K + col] = make_float2(b0, b1);
        }
    }
}

// ---------------- HMMA audio cross-attention: 128q x 128 audio keys ----------------
__global__ void __launch_bounds__(256, 1) xattn_hmma(const float* __restrict__ fmask,
                                                     const float* __restrict__ ascale) {
    extern __shared__ __nv_bfloat16 smb[];
    const int tid = threadIdx.x, lane = tid & 31, wid = tid >> 5;
    const int head = blockIdx.y, q0 = blockIdx.x * 128;
    const size_t colbase = (size_t)head * HDC;
    const uint32_t sb = smem_u32(smb);
    const float scale = 0.08838834764831845f;

    for (int i = tid; i < 2048; i += 256) {
        int r = i >> 4, c8 = (i & 15) * 8;
        size_t gq = (size_t)(q0 + r) * HIDC + colbase + c8;
        size_t ga = (size_t)r * HIDC + colbase + c8;
        int so = r * 136 + c8;
        *(uint4*)&smb[so]          = *(const uint4*)&d_q_hi[gq];
        *(uint4*)&smb[17408 + so]  = *(const uint4*)&d_q_lo[gq];
        *(uint4*)&smb[34816 + so]  = *(const uint4*)&d_ak_hi[ga];
        *(uint4*)&smb[52224 + so]  = *(const uint4*)&d_ak_lo[ga];
        *(uint4*)&smb[69632 + so]  = *(const uint4*)&d_av_hi[ga];
        *(uint4*)&smb[87040 + so]  = *(const uint4*)&d_av_lo[ga];
    }
    __syncthreads();

    float S[16][4];
#pragma unroll
    for (int nt = 0; nt < 16; nt++)
#pragma unroll
        for (int u = 0; u < 4; u++) S[nt][u] = 0.f;
#pragma unroll
    for (int half = 0; half < 2; half++) {
#pragma unroll
        for (int ks = 0; ks < 8; ks++) {
            uint32_t qa[2][4], kb[2][4][4];
            uint32_t aoff = ((uint32_t)(wid * 16 + (lane & 15)) * 136 + ks * 16 + (lane >> 4) * 8) * 2;
            ldm_x4(qa[0], sb + aoff);
            ldm_x4(qa[1], sb + 34816 + aoff);
            uint32_t bo_ = ((uint32_t)(half * 64 + ((lane >> 4) & 1) * 8 + (lane & 7)) * 136
                            + ks * 16 + ((lane >> 3) & 1) * 8) * 2;
#pragma unroll
            for (int ng = 0; ng < 4; ng++) {
                uint32_t ro = bo_ + ng * 16 * 136 * 2;
                ldm_x4(kb[0][ng], sb + 69632 + ro);
                ldm_x4(kb[1][ng], sb + 104448 + ro);
            }
#pragma unroll
            for (int cmb = 0; cmb < 3; cmb++) {
                const int ao = (cmb == 2) ? 1 : 0;
                const int bo = (cmb == 1) ? 1 : 0;
#pragma unroll
                for (int nt = 0; nt < 8; nt++)
                    mma16816(S[half * 8 + nt], qa[ao], &kb[bo][nt >> 1][(nt & 1) * 2]);
            }
        }
    }

    float tm0 = -INFINITY, tm1 = -INFINITY;
#pragma unroll
    for (int nt = 0; nt < 16; nt++) {
        S[nt][0] *= scale; S[nt][1] *= scale; S[nt][2] *= scale; S[nt][3] *= scale;
        tm0 = fmaxf(tm0, fmaxf(S[nt][0], S[nt][1]));
        tm1 = fmaxf(tm1, fmaxf(S[nt][2], S[nt][3]));
    }
    tm0 = fmaxf(tm0, __shfl_xor_sync(0xffffffffu, tm0, 1));
    tm0 = fmaxf(tm0, __shfl_xor_sync(0xffffffffu, tm0, 2));
    tm1 = fmaxf(tm1, __shfl_xor_sync(0xffffffffu, tm1, 1));
    tm1 = fmaxf(tm1, __shfl_xor_sync(0xffffffffu, tm1, 2));
    float sum0 = 0.f, sum1 = 0.f;
#pragma unroll
    for (int nt = 0; nt < 16; nt++) {
        S[nt][0] = __expf(S[nt][0] - tm0);
        S[nt][1] = __expf(S[nt][1] - tm0);
        S[nt][2] = __expf(S[nt][2] - tm1);
        S[nt][3] = __expf(S[nt][3] - tm1);
        sum0 += S[nt][0] + S[nt][1];
        sum1 += S[nt][2] + S[nt][3];
    }
    sum0 += __shfl_xor_sync(0xffffffffu, sum0, 1);
    sum0 += __shfl_xor_sync(0xffffffffu, sum0, 2);
    sum1 += __shfl_xor_sync(0xffffffffu, sum1, 1);
    sum1 += __shfl_xor_sync(0xffffffffu, sum1, 2);

    float accO[16][4];
#pragma unroll
    for (int nt = 0; nt < 16; nt++)
#pragma unroll
        for (int u = 0; u < 4; u++) accO[nt][u] = 0.f;
#pragma unroll
    for (int pk = 0; pk < 8; pk++) {
        uint32_t ph[4], pl[4];
        ph[0] = packbf(S[2*pk][0], S[2*pk][1]);     pl[0] = packlo(S[2*pk][0], S[2*pk][1], ph[0]);
        ph[1] = packbf(S[2*pk][2], S[2*pk][3]);     pl[1] = packlo(S[2*pk][2], S[2*pk][3], ph[1]);
        ph[2] = packbf(S[2*pk+1][0], S[2*pk+1][1]); pl[2] = packlo(S[2*pk+1][0], S[2*pk+1][1], ph[2]);
        ph[3] = packbf(S[2*pk+1][2], S[2*pk+1][3]); pl[3] = packlo(S[2*pk+1][2], S[2*pk+1][3], ph[3]);
        uint32_t vo = ((uint32_t)(pk * 16 + (lane & 15)) * 136 + (lane >> 4) * 8) * 2;
#pragma unroll
        for (int ng4 = 0; ng4 < 8; ng4++) {
            uint32_t co = vo + ng4 * 16 * 2;
            uint32_t vh[4], vl[4];
            ldm_x4_t(vh, sb + 139264 + co);
            ldm_x4_t(vl, sb + 174080 + co);
            mma16816(accO[ng4*2],   ph, &vh[0]);
            mma16816(accO[ng4*2+1], ph, &vh[2]);
            mma16816(accO[ng4*2],   ph, &vl[0]);
            mma16816(accO[ng4*2+1], ph, &vl[2]);
            mma16816(accO[ng4*2],   pl, &vh[0]);
            mma16816(accO[ng4*2+1], pl, &vh[2]);
        }
    }

    const float as = fminf(ascale[0], 2.0f);
    const int r0 = q0 + wid * 16 + (lane >> 2);
    const int r1 = r0 + 8;
    int t0 = r0 / 384, rem0 = r0 % 384;
    int t1 = r1 / 384, rem1 = r1 % 384;
    float fm0 = fmask[t0 * 1536 + (rem0 / 16) * 64 + (rem0 % 16) * 2];
    float fm1 = fmask[t1 * 1536 + (rem1 / 16) * 64 + (rem1 % 16) * 2];
    float mf0 = fm0 * as / sum0;
    float mf1 = fm1 * as / sum1;
#pragma unroll
    for (int nt = 0; nt < 16; nt++) {
        int col = head * HDC + nt * 8 + (lane & 3) * 2;
        float2 c0 = *(float2*)&d_cat[(size_t)r0 * W2K + col];
        float2 c1 = *(float2*)&d_cat[(size_t)r1 * W2K + col];
        split_store2(d_cat_hi, d_cat_lo, (size_t)r0 * W2K + col,
                     c0.x + accO[nt][0] * mf0, c0.y + accO[nt][1] * mf0);
        split_store2(d_cat_hi, d_cat_lo, (size_t)r1 * W2K + col,
                     c1.x + accO[nt][2] * mf1, c1.y + accO[nt][3] * mf1);
    }
}

extern "C" void kernel_launch(void* const* d_in, const int* in_sizes, int n_in,
                              void* d_out, int out_size) {
    const float* x     = (const float*)d_in[0];
    const float* vec   = (const float*)d_in[1];
    const float* trv   = (const float*)d_in[2];
    const float* fcos  = (const float*)d_in[3];
    const float* fsin  = (const float*)d_in[4];
    const float* aemb  = (const float*)d_in[5];
    const float* fmask = (const float*)d_in[6];
    const int*   cu    = (const int*)d_in[7];
    const float* mw    = (const float*)d_in[10];
    const float* mb    = (const float*)d_in[11];
    const float* w1    = (const float*)d_in[12];
    const float* b1    = (const float*)d_in[13];
    const float* qnw   = (const float*)d_in[14];
    const float* knw   = (const float*)d_in[15];
    const float* w2    = (const float*)d_in[16];
    const float* b2    = (const float*)d_in[17];
    const float* aqw   = (const float*)d_in[18];
    const float* aqb   = (const float*)d_in[19];
    const float* aknw  = (const float*)d_in[21];
    const float* ascale= (const float*)d_in[22];
    float* out = (float*)d_out;

    float* aqkv = nullptr; cudaGetSymbolAddress((void**)&aqkv, d_aqkv);
    float* gp   = nullptr; cudaGetSymbolAddress((void**)&gp,   d_gp);
    __nv_bfloat16 *ahi, *alo, *anhi, *anlo, *chi, *clo;
    __nv_bfloat16 *w1h, *w1l, *w2h, *w2l, *awh, *awl;
    cudaGetSymbolAddress((void**)&ahi,  d_a_hi);  cudaGetSymbolAddress((void**)&alo,  d_a_lo);
    cudaGetSymbolAddress((void**)&anhi, d_an_hi); cudaGetSymbolAddress((void**)&anlo, d_an_lo);
    cudaGetSymbolAddress((void**)&chi,  d_cat_hi);cudaGetSymbolAddress((void**)&clo,  d_cat_lo);
    cudaGetSymbolAddress((void**)&w1h,  d_w1t_hi);cudaGetSymbolAddress((void**)&w1l,  d_w1t_lo);
    cudaGetSymbolAddress((void**)&w2h,  d_w2t_hi);cudaGetSymbolAddress((void**)&w2l,  d_w2t_lo);
    cudaGetSymbolAddress((void**)&awh,  d_awt_hi);cudaGetSymbolAddress((void**)&awl,  d_awt_lo);

    const int ATTN_SMEM = 208896;
    cudaFuncSetAttribute(attn_hmma,  cudaFuncAttributeMaxDynamicSharedMemorySize, ATTN_SMEM);
    cudaFuncSetAttribute(xattn_hmma, cudaFuncAttributeMaxDynamicSharedMemorySize, ATTN_SMEM);
    const int GEMM_SMEM = 81920;
    cudaFuncSetAttribute(hmma_gemm, cudaFuncAttributeMaxDynamicSharedMemorySize, GEMM_SMEM);
    const int GEMM_SMEM2 = 221184;
    cudaFuncSetAttribute(hmma_gemm_big<2>, cudaFuncAttributeMaxDynamicSharedMemorySize, GEMM_SMEM2);
    cudaFuncSetAttribute(hmma_gemm_big<3>, cudaFuncAttributeMaxDynamicSharedMemorySize, GEMM_SMEM2);

    mod_part<<<dim3(MODN / 128, 8), 512>>>(vec, trv, mw);
    mod_reduce<<<MODN / 256, 256>>>(mb);
    transpose_conv<<<dim3(W1N / 32, HIDC / 32), dim3(8, 32)>>>(w1, w1h, w1l, HIDC, W1N);
    ln_mod_kernel<<<LC, 256>>>(x);
    // GEMM1 with fused bias+rms+rope+split epilogue (q/k), v split, gelu split
    hmma_gemm_big<2><<<dim3(LC / 256, W1N / 128, 1), 256, GEMM_SMEM2>>>(
        ahi, alo, w1h, w1l, b1, gp, LC, W1N, HIDC, qnw, knw, fcos, fsin);
    transpose_conv<<<dim3(HIDC / 32, W2K / 32), dim3(8, 32)>>>(w2, w2h, w2l, W2K, HIDC);
    transpose_conv<<<dim3(MODN / 32, HIDC / 32), dim3(8, 32)>>>(aqw, awh, awl, HIDC, MODN);
    attn_hmma<<<dim3(LC / 128, HEADSC), 256, ATTN_SMEM>>>(cu);
    ln_plain_kernel<<<NAUD, 256>>>(aemb);
    hmma_gemm<<<dim3(NAUD / 128, MODN / 128), 256, GEMM_SMEM>>>(anhi, anlo, awh, awl, aqb, aqkv, NAUD, MODN, HIDC);
    akv_kernel<<<(NAUD * HEADSC) / 4, 128>>>(aknw);
    xattn_hmma<<<dim3(LIMGC / 128, HEADSC), 256, ATTN_SMEM>>>(fmask, ascale);
    hmma_gemm_big<3><<<dim3(LC / 256, HIDC / 128, 3), 256, GEMM_SMEM2>>>(
        chi, clo, w2h, w2l, b2, gp, LC, HIDC, W2K, nullptr, nullptr, nullptr, nullptr);
    gemm2_combine<<<(int)(((size_t)LC * HIDC / 4) / 256), 256>>>(b2, x, out);
}

// round 14
// speedup vs baseline: 1.0689x; 1.0257x over previous
#include <cuda_runtime.h>
#include <cuda_bf16.h>
#include <math.h>
#include <stdint.h>

#define HIDC   3072
#define HEADSC 24
#define HDC    128
#define LC     2048
#define LIMGC  1920
#define FFNC   384
#define MLPDC  12288
#define W1N    21504
#define W2K    15360
#define MODN   9216
#define NAUD   128

// ---------------- scratch ----------------
__device__ float d_mod[MODN];
__device__ float d_trm[MODN];
__device__ float d_modp[8][MODN];
__device__ float d_trmp[8][MODN];
__device__ float d_cat[(size_t)LC * W2K];
__device__ float d_gp[(size_t)3 * LC * HIDC];
__device__ __align__(16) __nv_bfloat16 d_a_hi[(size_t)LC * HIDC];
__device__ __align__(16) __nv_bfloat16 d_a_lo[(size_t)LC * HIDC];
__device__ __align__(16) __nv_bfloat16 d_an_hi[(size_t)NAUD * HIDC];
__device__ __align__(16) __nv_bfloat16 d_an_lo[(size_t)NAUD * HIDC];
__device__ __align__(16) __nv_bfloat16 d_cat_hi[(size_t)LC * W2K];
__device__ __align__(16) __nv_bfloat16 d_cat_lo[(size_t)LC * W2K];
__device__ __align__(16) __nv_bfloat16 d_w1t_hi[(size_t)W1N * HIDC];
__device__ __align__(16) __nv_bfloat16 d_w1t_lo[(size_t)W1N * HIDC];
__device__ __align__(16) __nv_bfloat16 d_w2t_hi[(size_t)HIDC * W2K];
__device__ __align__(16) __nv_bfloat16 d_w2t_lo[(size_t)HIDC * W2K];
__device__ __align__(16) __nv_bfloat16 d_awt_hi[(size_t)MODN * HIDC];
__device__ __align__(16) __nv_bfloat16 d_awt_lo[(size_t)MODN * HIDC];
__device__ __align__(16) __nv_bfloat16 d_q_hi[(size_t)LC * HIDC];
__device__ __align__(16) __nv_bfloat16 d_q_lo[(size_t)LC * HIDC];
__device__ __align__(16) __nv_bfloat16 d_k_hi[(size_t)LC * HIDC];
__device__ __align__(16) __nv_bfloat16 d_k_lo[(size_t)LC * HIDC];
__device__ __align__(16) __nv_bfloat16 d_v_hi[(size_t)LC * HIDC];
__device__ __align__(16) __nv_bfloat16 d_v_lo[(size_t)LC * HIDC];
__device__ __align__(16) __nv_bfloat16 d_ak_hi[(size_t)NAUD * HIDC];
__device__ __align__(16) __nv_bfloat16 d_ak_lo[(size_t)NAUD * HIDC];
__device__ __align__(16) __nv_bfloat16 d_av_hi[(size_t)NAUD * HIDC];
__device__ __align__(16) __nv_bfloat16 d_av_lo[(size_t)NAUD * HIDC];

// ---------------- helpers ----------------
__device__ __forceinline__ uint32_t smem_u32(const void* p) {
    uint32_t a;
    asm("{ .reg .u64 t; cvta.to.shared.u64 t, %1; cvt.u32.u64 %0, t; }" : "=r"(a) : "l"(p));
    return a;
}
__device__ __forceinline__ void ldm_x4(uint32_t* r, uint32_t addr) {
    asm volatile("ldmatrix.sync.aligned.m8n8.x4.shared.b16 {%0,%1,%2,%3}, [%4];"
        : "=r"(r[0]), "=r"(r[1]), "=r"(r[2]), "=r"(r[3]) : "r"(addr));
}
__device__ __forceinline__ void ldm_x4_t(uint32_t* r, uint32_t addr) {
    asm volatile("ldmatrix.sync.aligned.m8n8.x4.trans.shared.b16 {%0,%1,%2,%3}, [%4];"
        : "=r"(r[0]), "=r"(r[1]), "=r"(r[2]), "=r"(r[3]) : "r"(addr));
}
__device__ __forceinline__ void mma16816(float* d, const uint32_t* a, const uint32_t* b) {
    asm volatile("mma.sync.aligned.m16n8k16.row.col.f32.bf16.bf16.f32 "
        "{%0,%1,%2,%3}, {%4,%5,%6,%7}, {%8,%9}, {%0,%1,%2,%3};"
        : "+f"(d[0]), "+f"(d[1]), "+f"(d[2]), "+f"(d[3])
        : "r"(a[0]), "r"(a[1]), "r"(a[2]), "r"(a[3]), "r"(b[0]), "r"(b[1]));
}
__device__ __forceinline__ void cp16(uint32_t dst, const void* src) {
    asm volatile("cp.async.cg.shared.global [%0], [%1], 16;" :: "r"(dst), "l"(src));
}
#define CP_COMMIT() asm volatile("cp.async.commit_group;" ::: "memory")
#define CP_WAIT(n)  asm volatile("cp.async.wait_group %0;" :: "n"(n) : "memory")

__device__ __forceinline__ uint32_t packbf(float a, float b) {
    __nv_bfloat162 t = __floats2bfloat162_rn(a, b);
    return *reinterpret_cast<uint32_t*>(&t);
}
__device__ __forceinline__ uint32_t packlo(float a, float b, uint32_t hi) {
    __nv_bfloat162 h = *reinterpret_cast<__nv_bfloat162*>(&hi);
    return packbf(a - __bfloat162float(h.x), b - __bfloat162float(h.y));
}
__device__ __forceinline__ float gelu_fast(float x) {
    float u2 = 1.5957691216057308f * (x + 0.044715f * x * x * x);
    return x / (1.f + __expf(-u2));
}
__device__ __forceinline__ void block_reduce2(float& s, float& s2, float* buf) {
    int tid = threadIdx.x, lane = tid & 31, w = tid >> 5;
#pragma unroll
    for (int o = 16; o > 0; o >>= 1) {
        s  += __shfl_xor_sync(0xffffffffu, s,  o);
        s2 += __shfl_xor_sync(0xffffffffu, s2, o);
    }
    if (lane == 0) { buf[w] = s; buf[32 + w] = s2; }
    __syncthreads();
    if (tid == 0) {
        float a = 0.f, b = 0.f;
#pragma unroll
        for (int i = 0; i < 8; i++) { a += buf[i]; b += buf[32 + i]; }
        buf[0] = a; buf[32] = b;
    }
    __syncthreads();
    s = buf[0]; s2 = buf[32];
}
__device__ __forceinline__ void split_store4(__nv_bfloat16* hi, __nv_bfloat16* lo, size_t i, float4 v) {
    __nv_bfloat162 h0 = __floats2bfloat162_rn(v.x, v.y);
    __nv_bfloat162 h1 = __floats2bfloat162_rn(v.z, v.w);
    *(uint2*)&hi[i] = make_uint2(*(uint32_t*)&h0, *(uint32_t*)&h1);
    __nv_bfloat162 l0 = __floats2bfloat162_rn(v.x - __bfloat162float(h0.x), v.y - __bfloat162float(h0.y));
    __nv_bfloat162 l1 = __floats2bfloat162_rn(v.z - __bfloat162float(h1.x), v.w - __bfloat162float(h1.y));
    *(uint2*)&lo[i] = make_uint2(*(uint32_t*)&l0, *(uint32_t*)&l1);
}
__device__ __forceinline__ void split_store2(__nv_bfloat16* hi, __nv_bfloat16* lo, size_t i, float a, float b) {
    __nv_bfloat162 h = __floats2bfloat162_rn(a, b);
    *(uint32_t*)&hi[i] = *(uint32_t*)&h;
    __nv_bfloat162 l = __floats2bfloat162_rn(a - __bfloat162float(h.x), b - __bfloat162float(h.y));
    *(uint32_t*)&lo[i] = *(uint32_t*)&l;
}

// ---------------- transpose + bf16 split: W[K,N] -> out[N,K], cols n0_off.. ----------------
__global__ void transpose_conv(const float* __restrict__ W, __nv_bfloat16* __restrict__ hi,
                               __nv_bfloat16* __restrict__ lo, int K, int N, int n_off) {
    __shared__ float t[32][36];
    int n0 = n_off + blockIdx.x * 32, k0 = blockIdx.y * 32;
    int tx = threadIdx.x;
    int ty = threadIdx.y;
    float4 v = *(const float4*)&W[(size_t)(k0 + ty) * N + n0 + tx * 4];
    t[ty][tx * 4 + 0] = v.x; t[ty][tx * 4 + 1] = v.y;
    t[ty][tx * 4 + 2] = v.z; t[ty][tx * 4 + 3] = v.w;
    __syncthreads();
    float4 o = make_float4(t[tx * 4 + 0][ty], t[tx * 4 + 1][ty],
                           t[tx * 4 + 2][ty], t[tx * 4 + 3][ty]);
    split_store4(hi, lo, (size_t)(n0 + ty) * K + k0 + tx * 4, o);
}

// ---------------- mod partials ----------------
__global__ void mod_part(const float* __restrict__ vec, const float* __restrict__ trv,
                         const float* __restrict__ mw) {
    __shared__ float sv[384], st[384];
    __shared__ float part[2][4][128];
    int tid = threadIdx.x, by = blockIdx.y;
    if (tid < 384) {
        int k = by * 384 + tid;
        float a = vec[k]; sv[tid] = a / (1.f + expf(-a));
        float b = trv[k]; st[tid] = b / (1.f + expf(-b));
    }
    __syncthreads();
    int jl = tid & 127, sl = tid >> 7;
    int j = blockIdx.x * 128 + jl;
    float a0 = 0.f, a1 = 0.f;
    int kend = (sl + 1) * 96;
    for (int kl = sl * 96; kl < kend; kl++) {
        float w = mw[(size_t)(by * 384 + kl) * MODN + j];
        a0 = fmaf(sv[kl], w, a0);
        a1 = fmaf(st[kl], w, a1);
    }
    part[0][sl][jl] = a0; part[1][sl][jl] = a1;
    __syncthreads();
    if (tid < 128) {
        int jj = blockIdx.x * 128 + tid;
        d_modp[by][jj] = part[0][0][tid] + part[0][1][tid] + part[0][2][tid] + part[0][3][tid];
    } else if (tid < 256) {
        int t = tid - 128, jj = blockIdx.x * 128 + t;
        d_trmp[by][jj] = part[1][0][t] + part[1][1][t] + part[1][2][t] + part[1][3][t];
    }
}
__global__ void mod_reduce(const float* __restrict__ mb) {
    int j = blockIdx.x * 256 + threadIdx.x;
    float s0 = mb[j], s1 = mb[j];
#pragma unroll
    for (int p = 0; p < 8; p++) { s0 += d_modp[p][j]; s1 += d_trmp[p][j]; }
    d_mod[j] = s0; d_trm[j] = s1;
}

// ---------------- LN + modulate -> bf16 hi/lo ----------------
__global__ void ln_mod_kernel(const float* __restrict__ x) {
    int row = blockIdx.x, tid = threadIdx.x;
    const float* xr = x + (size_t)row * HIDC;
    float s = 0.f, s2 = 0.f;
    for (int j = tid * 4; j < HIDC; j += 1024) {
        float4 v = *(const float4*)&xr[j];
        s  += v.x + v.y + v.z + v.w;
        s2 += v.x*v.x + v.y*v.y + v.z*v.z + v.w*v.w;
    }
    __shared__ float buf[64];
    block_reduce2(s, s2, buf);
    float mean = s * (1.f / HIDC);
    float inv = rsqrtf(s2 * (1.f / HIDC) - mean * mean + 1e-6f);
    const float* mv = (row < FFNC) ? d_trm : d_mod;
    for (int j = tid * 4; j < HIDC; j += 1024) {
        float4 v  = *(const float4*)&xr[j];
        float4 sc = *(const float4*)&mv[HIDC + j];
        float4 sh = *(const float4*)&mv[j];
        float4 o;
        o.x = (v.x - mean) * inv * (1.f + sc.x) + sh.x;
        o.y = (v.y - mean) * inv * (1.f + sc.y) + sh.y;
        o.z = (v.z - mean) * inv * (1.f + sc.z) + sh.z;
        o.w = (v.w - mean) * inv * (1.f + sc.w) + sh.w;
        split_store4(d_a_hi, d_a_lo, (size_t)row * HIDC + j, o);
    }
}

// ---------------- audio LN -> bf16 hi/lo ----------------
__global__ void ln_plain_kernel(const float* __restrict__ a) {
    int row = blockIdx.x, tid = threadIdx.x;
    const float* xr = a + (size_t)row * HIDC;
    float s = 0.f, s2 = 0.f;
    for (int j = tid * 4; j < HIDC; j += 1024) {
        float4 v = *(const float4*)&xr[j];
        s  += v.x + v.y + v.z + v.w;
        s2 += v.x*v.x + v.y*v.y + v.z*v.z + v.w*v.w;
    }
    __shared__ float buf[64];
    block_reduce2(s, s2, buf);
    float mean = s * (1.f / HIDC);
    float inv = rsqrtf(s2 * (1.f / HIDC) - mean * mean + 1e-6f);
    for (int j = tid * 4; j < HIDC; j += 1024) {
        float4 v = *(const float4*)&xr[j];
        float4 o = make_float4((v.x - mean) * inv, (v.y - mean) * inv,
                               (v.z - mean) * inv, (v.w - mean) * inv);
        split_store4(d_an_hi, d_an_lo, (size_t)row * HIDC + j, o);
    }
}

// ---------------- GEMM2 combine ----------------
__global__ void gemm2_combine(const float* __restrict__ bias, const float* __restrict__ resid,
                              float* __restrict__ out) {
    size_t i = ((size_t)blockIdx.x * 256 + threadIdx.x) * 4;
    int m = (int)(i / HIDC), n = (int)(i % HIDC);
    const float* gv = (m < FFNC) ? d_trm : d_mod;
    float4 p0 = *(const float4*)&d_gp[i];
    float4 p1 = *(const float4*)&d_gp[(size_t)LC * HIDC + i];
    float4 p2 = *(const float4*)&d_gp[(size_t)2 * LC * HIDC + i];
    float4 bb = *(const float4*)&bias[n];
    float4 gg = *(const float4*)&gv[2 * HIDC + n];
    float4 rr = *(const float4*)&resid[i];
    float4 o;
    o.x = rr.x + (p0.x + p1.x + p2.x + bb.x) * gg.x;
    o.y = rr.y + (p0.y + p1.y + p2.y + bb.y) * gg.y;
    o.z = rr.z + (p0.z + p1.z + p2.z + bb.z) * gg.z;
    o.w = rr.w + (p0.w + p1.w + p2.w + bb.w) * gg.w;
    *(float4*)&out[i] = o;
}

// ---------------- big HMMA GEMM: 256x128 CTA, 64x64 warp, BK=64, 2 stages ----------------
template<int MODE>
__global__ void __launch_bounds__(256, 1) hmma_gemm_big(
        const __nv_bfloat16* __restrict__ Ahi, const __nv_bfloat16* __restrict__ Alo,
        const __nv_bfloat16* __restrict__ Bhi, const __nv_bfloat16* __restrict__ Blo,
        const float* __restrict__ bias, float* __restrict__ C,
        int M, int N, int K,
        const float* __restrict__ qnw, const float* __restrict__ knw,
        const float* __restrict__ fcos, const float* __restrict__ fsin) {
    extern __shared__ char smraw[];
    const int tid = threadIdx.x;
    const int lane = tid & 31, wid = tid >> 5;
    const int bm = blockIdx.x * 256, bn = blockIdx.y * 128;
    const int wm = wid & 3, wn = wid >> 2;
    const int Kper = K / gridDim.z;
    const int ko = blockIdx.z * Kper;
    const uint32_t sbase = smem_u32(smraw);
    const __nv_bfloat16* srcs[4] = {
        Ahi + (size_t)bm * K + ko, Alo + (size_t)bm * K + ko,
        Bhi + (size_t)bn * K + ko, Blo + (size_t)bn * K + ko };

    float acc[4][8][4];
#pragma unroll
    for (int a = 0; a < 4; a++)
#pragma unroll
        for (int b = 0; b < 8; b++)
#pragma unroll
            for (int c = 0; c < 4; c++) acc[a][b][c] = 0.f;

    const int NC = Kper >> 6;
#pragma unroll
    for (int i = 0; i < 24; i++) {
        int id = tid + i * 256;
        if (id < 4096) {
            int op = id >> 11, rem = id & 2047, r = rem >> 3, q = rem & 7;
            cp16(sbase + op * 36864 + r * 144 + q * 16, srcs[op] + (size_t)r * K + q * 8);
        } else {
            int t = id - 4096, op = t >> 10, rem = t & 1023, r = rem >> 3, q = rem & 7;
            cp16(sbase + 73728 + op * 18432 + r * 144 + q * 16, srcs[2 + op] + (size_t)r * K + q * 8);
        }
    }
    CP_COMMIT();

    for (int c = 0; c < NC; c++) {
        const int stage = c & 1;
        if (c + 1 < NC) {
            const int kc = (c + 1) << 6;
            const uint32_t db = sbase + (stage ^ 1) * 110592;
#pragma unroll
            for (int i = 0; i < 24; i++) {
                int id = tid + i * 256;
                if (id < 4096) {
                    int op = id >> 11, rem = id & 2047, r = rem >> 3, q = rem & 7;
                    cp16(db + op * 36864 + r * 144 + q * 16, srcs[op] + (size_t)r * K + kc + q * 8);
                } else {
                    int t = id - 4096, op = t >> 10, rem = t & 1023, r = rem >> 3, q = rem & 7;
                    cp16(db + 73728 + op * 18432 + r * 144 + q * 16, srcs[2 + op] + (size_t)r * K + kc + q * 8);
                }
            }
            CP_COMMIT();
            CP_WAIT(1);
        } else {
            CP_WAIT(0);
        }
        __syncthreads();
        const uint32_t base = sbase + stage * 110592;
#pragma unroll
        for (int kk = 0; kk < 4; kk++) {
            uint32_t afr[2][4][4];
            uint32_t bfr[2][4][4];
            const uint32_t aoff = (uint32_t)(wm * 64 + (lane & 15)) * 144 + kk * 32 + (lane >> 4) * 16;
#pragma unroll
            for (int op = 0; op < 2; op++)
#pragma unroll
                for (int mi = 0; mi < 4; mi++)
                    ldm_x4(afr[op][mi], base + op * 36864 + aoff + mi * 16 * 144);
            const uint32_t boff = (uint32_t)(wn * 64 + ((lane >> 4) & 1) * 8 + (lane & 7)) * 144
                                  + kk * 32 + ((lane >> 3) & 1) * 16;
#pragma unroll
            for (int op = 0; op < 2; op++)
#pragma unroll
                for (int ng = 0; ng < 4; ng++)
                    ldm_x4(bfr[op][ng], base + 73728 + op * 18432 + boff + ng * 16 * 144);
#pragma unroll
            for (int cmb = 0; cmb < 3; cmb++) {
                const int ao = (cmb == 2) ? 1 : 0;
                const int bo = (cmb == 1) ? 1 : 0;
#pragma unroll
                for (int mi = 0; mi < 4; mi++)
#pragma unroll
                    for (int ng = 0; ng < 4; ng++) {
                        mma16816(acc[mi][ng * 2 + 0], afr[ao][mi], &bfr[bo][ng][0]);
                        mma16816(acc[mi][ng * 2 + 1], afr[ao][mi], &bfr[bo][ng][2]);
                    }
            }
        }
        __syncthreads();
    }
    const int gid = lane >> 2, tq = (lane & 3) << 1;

    if (MODE == 2 && bn < 2 * HIDC) {
        __syncthreads();
        float* red = (float*)smraw;
#pragma unroll
        for (int mi = 0; mi < 4; mi++)
#pragma unroll
            for (int ni = 0; ni < 8; ni++) {
                int n = bn + wn * 64 + ni * 8 + tq;
                float b0 = bias[n], b1 = bias[n + 1];
                acc[mi][ni][0] += b0; acc[mi][ni][1] += b1;
                acc[mi][ni][2] += b0; acc[mi][ni][3] += b1;
            }
#pragma unroll
        for (int mi = 0; mi < 4; mi++)
#pragma unroll
            for (int half = 0; half < 2; half++) {
                float s = 0.f;
#pragma unroll
                for (int ni = 0; ni < 8; ni++) {
                    float v0 = acc[mi][ni][half * 2], v1 = acc[mi][ni][half * 2 + 1];
                    s += v0 * v0 + v1 * v1;
                }
                s += __shfl_xor_sync(0xffffffffu, s, 1);
                s += __shfl_xor_sync(0xffffffffu, s, 2);
                if ((lane & 3) == 0)
                    red[wn * 256 + wm * 64 + mi * 16 + half * 8 + gid] = s;
            }
        __syncthreads();
        const bool isq = bn < HIDC;
        const int head = (isq ? bn : bn - HIDC) >> 7;
        const float* rw = isq ? qnw : knw;
        __nv_bfloat16* ohi = isq ? d_q_hi : d_k_hi;
        __nv_bfloat16* olo = isq ? d_q_lo : d_k_lo;
#pragma unroll
        for (int mi = 0; mi < 4; mi++)
#pragma unroll
            for (int half = 0; half < 2; half++) {
                int rloc = wm * 64 + mi * 16 + half * 8 + gid;
                int m = bm + rloc;
                float rs = rsqrtf((red[rloc] + red[256 + rloc]) * (1.f / HDC) + 1e-6f);
                bool rope = m < LIMGC;
#pragma unroll
                for (int ni = 0; ni < 8; ni++) {
                    int cd = wn * 64 + ni * 8 + tq;
                    float v0 = acc[mi][ni][half * 2]     * rs * rw[cd];
                    float v1 = acc[mi][ni][half * 2 + 1] * rs * rw[cd + 1];
                    if (rope) {
                        float cc = fcos[m * HDC + cd];
                        float sc = fsin[m * HDC + cd];
                        float n0 = v0 * cc - v1 * sc;
                        float n1 = v1 * cc + v0 * sc;
                        v0 = n0; v1 = n1;
                    }
                    split_store2(ohi, olo, (size_t)m * HIDC + head * HDC + cd, v0, v1);
                }
            }
        return;
    }

    float* Cz = (MODE == 3) ? (C + (size_t)blockIdx.z * M * N) : C;
#pragma unroll
    for (int mi = 0; mi < 4; mi++) {
#pragma unroll
        for (int half = 0; half < 2; half++) {
            const int m = bm + wm * 64 + mi * 16 + half * 8 + gid;
#pragma unroll
            for (int ni = 0; ni < 8; ni++) {
                const int n = bn + wn * 64 + ni * 8 + tq;
                if (MODE == 3) {
                    *(float2*)&Cz[(size_t)m * N + n] =
                        make_float2(acc[mi][ni][half * 2 + 0], acc[mi][ni][half * 2 + 1]);
                } else {
                    float v0 = acc[mi][ni][half * 2 + 0] + bias[n];
                    float v1 = acc[mi][ni][half * 2 + 1] + bias[n + 1];
                    if (n < 3 * HIDC) {
                        size_t idx = (size_t)m * HIDC + (n - 2 * HIDC);
                        split_store2(d_v_hi, d_v_lo, idx, v0, v1);
                    } else {
                        size_t idx = (size_t)m * W2K + (n - 2 * HIDC);
                        split_store2(d_cat_hi, d_cat_lo, idx, gelu_fast(v0), gelu_fast(v1));
                    }
                }
            }
        }
    }
}

// ---------------- audio k/v HMMA GEMM (128x128 tile) with fused rms/split epilogue ----------------
// A = audio LN hi/lo [128, K]; B = awt rows [3072, 9216) hi/lo. N relative: [0,HIDC)=k, [HIDC,2H)=v.
__global__ void __launch_bounds__(256, 1) hmma_gemm_akv(
        const __nv_bfloat16* __restrict__ Ahi, const __nv_bfloat16* __restrict__ Alo,
        const __nv_bfloat16* __restrict__ Bhi, const __nv_bfloat16* __restrict__ Blo,
        const float* __restrict__ bias, const float* __restrict__ aknw, int K) {
    extern __shared__ char smraw[];
    const int tid = threadIdx.x;
    const int lane = tid & 31, wid = tid >> 5;
    const int bn = blockIdx.y * 128;
    const int wm = wid & 3, wn = wid >> 2;
    const uint32_t sbase = smem_u32(smraw);
    const __nv_bfloat16* srcs[4] = {
        Ahi, Alo, Bhi + (size_t)bn * K, Blo + (size_t)bn * K };
    float acc[2][8][4];
#pragma unroll
    for (int a = 0; a < 2; a++)
#pragma unroll
        for (int b = 0; b < 8; b++)
#pragma unroll
            for (int c = 0; c < 4; c++) acc[a][b][c] = 0.f;
    const int NC = K >> 5;
    {
#pragma unroll
        for (int i = 0; i < 8; i++) {
            int id = tid + i * 256;
            int op = id >> 9, rem = id & 511;
            int r = rem >> 2, q = rem & 3;
            cp16(sbase + op * 10240 + r * 80 + q * 16, srcs[op] + (size_t)r * K + q * 8);
        }
        CP_COMMIT();
    }
    for (int c = 0; c < NC; c++) {
        const int stage = c & 1;
        if (c + 1 < NC) {
            const int kc = (c + 1) << 5;
            const uint32_t db = sbase + (stage ^ 1) * 40960;
#pragma unroll
            for (int i = 0; i < 8; i++) {
                int id = tid + i * 256;
                int op = id >> 9, rem = id & 511;
                int r = rem >> 2, q = rem & 3;
                cp16(db + op * 10240 + r * 80 + q * 16, srcs[op] + (size_t)r * K + kc + q * 8);
            }
            CP_COMMIT();
            CP_WAIT(1);
        } else {
            CP_WAIT(0);
        }
        __syncthreads();
        const uint32_t base = sbase + stage * 40960;
#pragma unroll
        for (int kk = 0; kk < 2; kk++) {
            uint32_t afr[2][2][4];
            uint32_t bfr[2][4][4];
            const uint32_t aoff = (uint32_t)(wm * 32 + (lane & 15)) * 80 + kk * 32 + (lane >> 4) * 16;
#pragma unroll
            for (int op = 0; op < 2; op++)
#pragma unroll
                for (int mi = 0; mi < 2; mi++)
                    ldm_x4(afr[op][mi], base + op * 10240 + aoff + mi * 16 * 80);
            const uint32_t boff = (uint32_t)(wn * 64 + ((lane >> 4) & 1) * 8 + (lane & 7)) * 80
                                  + kk * 32 + ((lane >> 3) & 1) * 16;
#pragma unroll
            for (int op = 0; op < 2; op++)
#pragma unroll
                for (int ng = 0; ng < 4; ng++)
                    ldm_x4(bfr[op][ng], base + 20480 + op * 10240 + boff + ng * 16 * 80);
#pragma unroll
            for (int cmb = 0; cmb < 3; cmb++) {
                const int ao = (cmb == 2) ? 1 : 0;
                const int bo = (cmb == 1) ? 1 : 0;
#pragma unroll
                for (int mi = 0; mi < 2; mi++)
#pragma unroll
                    for (int ng = 0; ng < 4; ng++) {
                        mma16816(acc[mi][ng * 2 + 0], afr[ao][mi], &bfr[bo][ng][0]);
                        mma16816(acc[mi][ng * 2 + 1], afr[ao][mi], &bfr[bo][ng][2]);
                    }
            }
        }
        __syncthreads();
    }
    const int gid = lane >> 2, tq = (lane & 3) << 1;
    // bias
#pragma unroll
    for (int mi = 0; mi < 2; mi++)
#pragma unroll
        for (int ni = 0; ni < 8; ni++) {
            int n = bn + wn * 64 + ni * 8 + tq;
            float b0 = bias[n], b1 = bias[n + 1];
            acc[mi][ni][0] += b0; acc[mi][ni][1] += b1;
            acc[mi][ni][2] += b0; acc[mi][ni][3] += b1;
        }
    if (bn < HIDC) {
        // k region: fused RMS + split (CTA tile = one head)
        __syncthreads();
        float* red = (float*)smraw;
#pragma unroll
        for (int mi = 0; mi < 2; mi++)
#pragma unroll
            for (int half = 0; half < 2; half++) {
                float s = 0.f;
#pragma unroll
                for (int ni = 0; ni < 8; ni++) {
                    float v0 = acc[mi][ni][half * 2], v1 = acc[mi][ni][half * 2 + 1];
                    s += v0 * v0 + v1 * v1;
                }
                s += __shfl_xor_sync(0xffffffffu, s, 1);
                s += __shfl_xor_sync(0xffffffffu, s, 2);
                if ((lane & 3) == 0)
                    red[wn * 128 + wm * 32 + mi * 16 + half * 8 + gid] = s;
            }
        __syncthreads();
        const int head = bn >> 7;
#pragma unroll
        for (int mi = 0; mi < 2; mi++)
#pragma unroll
            for (int half = 0; half < 2; half++) {
                int rloc = wm * 32 + mi * 16 + half * 8 + gid;
                float rs = rsqrtf((red[rloc] + red[128 + rloc]) * (1.f / HDC) + 1e-6f);
#pragma unroll
                for (int ni = 0; ni < 8; ni++) {
                    int cd = wn * 64 + ni * 8 + tq;
                    float v0 = acc[mi][ni][half * 2]     * rs * aknw[cd];
                    float v1 = acc[mi][ni][half * 2 + 1] * rs * aknw[cd + 1];
                    split_store2(d_ak_hi, d_ak_lo, (size_t)rloc * HIDC + head * HDC + cd, v0, v1);
                }
            }
    } else {
#pragma unroll
        for (int mi = 0; mi < 2; mi++)
#pragma unroll
            for (int half = 0; half < 2; half++) {
                int row = wm * 32 + mi * 16 + half * 8 + gid;
#pragma unroll
                for (int ni = 0; ni < 8; ni++) {
                    int n = bn + wn * 64 + ni * 8 + tq;
                    split_store2(d_av_hi, d_av_lo, (size_t)row * HIDC + (n - HIDC),
                                 acc[mi][ni][half * 2], acc[mi][ni][half * 2 + 1]);
                }
            }
    }
}

// ---------------- HMMA flash self-attention, 128q x 128k tiles, cp.async K/V split ----------------
__global__ void __launch_bounds__(256, 1) attn_hmma(const int* __restrict__ cu) {
    extern __shared__ __nv_bfloat16 smb[];
    const int tid = threadIdx.x, lane = tid & 31, wid = tid >> 5;
    const int head = blockIdx.y, q0 = blockIdx.x * 128;
    const int G = cu[1] - cu[0];
    const size_t colbase = (size_t)head * HDC;
    const uint32_t sb = smem_u32(smb);
    const float scale = 0.08838834764831845f;

    for (int i = tid; i < 2048; i += 256) {
        int r = i >> 4, c8 = (i & 15) * 8;
        size_t g = (size_t)(q0 + r) * HIDC + colbase + c8;
        *(uint4*)&smb[r * 136 + c8]          = *(const uint4*)&d_q_hi[g];
        *(uint4*)&smb[17408 + r * 136 + c8]  = *(const uint4*)&d_q_lo[g];
    }

    float accO[16][4];
#pragma unroll
    for (int nt = 0; nt < 16; nt++)
#pragma unroll
        for (int u = 0; u < 4; u++) accO[nt][u] = 0.f;
    float m0 = -INFINITY, m1 = -INFINITY, l0 = 0.f, l1 = 0.f;

    const int r0 = q0 + wid * 16 + (lane >> 2);
    const bool qg0 = r0 < G, qg1 = (r0 + 8) < G;

    for (int kt = 0; kt < LC / 128; kt++) {
        __syncthreads();   // PV(t-1) done reading V before overwrite
        // K planes (group 1)
        for (int i = tid; i < 2048; i += 256) {
            int r = i >> 4, c8 = (i & 15) * 8;
            size_t g = (size_t)(kt * 128 + r) * HIDC + colbase + c8;
            uint32_t so = (uint32_t)(r * 136 + c8) * 2;
            cp16(sb + 69632 + so,  &d_k_hi[g]);
            cp16(sb + 104448 + so, &d_k_lo[g]);
        }
        CP_COMMIT();
        // V planes (group 2) — hidden under S compute
        for (int i = tid; i < 2048; i += 256) {
            int r = i >> 4, c8 = (i & 15) * 8;
            size_t g = (size_t)(kt * 128 + r) * HIDC + colbase + c8;
            uint32_t so = (uint32_t)(r * 136 + c8) * 2;
            cp16(sb + 139264 + so, &d_v_hi[g]);
            cp16(sb + 174080 + so, &d_v_lo[g]);
        }
        CP_COMMIT();
        CP_WAIT(1);        // K ready (V may still be in flight)
        __syncthreads();

        float S[16][4];
#pragma unroll
        for (int nt = 0; nt < 16; nt++)
#pragma unroll
            for (int u = 0; u < 4; u++) S[nt][u] = 0.f;
#pragma unroll
        for (int half = 0; half < 2; half++) {
#pragma unroll
            for (int ks = 0; ks < 8; ks++) {
                uint32_t qa[2][4], kb[2][4][4];
                uint32_t aoff = ((uint32_t)(wid * 16 + (lane & 15)) * 136 + ks * 16 + (lane >> 4) * 8) * 2;
                ldm_x4(qa[0], sb + aoff);
                ldm_x4(qa[1], sb + 34816 + aoff);
                uint32_t bo_ = ((uint32_t)(half * 64 + ((lane >> 4) & 1) * 8 + (lane & 7)) * 136
                                + ks * 16 + ((lane >> 3) & 1) * 8) * 2;
#pragma unroll
                for (int ng = 0; ng < 4; ng++) {
                    uint32_t ro = bo_ + ng * 16 * 136 * 2;
                    ldm_x4(kb[0][ng], sb + 69632 + ro);
                    ldm_x4(kb[1][ng], sb + 104448 + ro);
                }
#pragma unroll
                for (int cmb = 0; cmb < 3; cmb++) {
                    const int ao = (cmb == 2) ? 1 : 0;
                    const int bo = (cmb == 1) ? 1 : 0;
#pragma unroll
                    for (int nt = 0; nt < 8; nt++)
                        mma16816(S[half * 8 + nt], qa[ao], &kb[bo][nt >> 1][(nt & 1) * 2]);
                }
            }
        }

#pragma unroll
        for (int nt = 0; nt < 16; nt++) {
            int key0 = kt * 128 + nt * 8 + (lane & 3) * 2;
            bool k0g = key0 < G, k1g = (key0 + 1) < G;
            S[nt][0] = (k0g == qg0) ? S[nt][0] * scale : -1e9f;
            S[nt][1] = (k1g == qg0) ? S[nt][1] * scale : -1e9f;
            S[nt][2] = (k0g == qg1) ? S[nt][2] * scale : -1e9f;
            S[nt][3] = (k1g == qg1) ? S[nt][3] * scale : -1e9f;
        }
        float tm0 = -INFINITY, tm1 = -INFINITY;
#pragma unroll
        for (int nt = 0; nt < 16; nt++) {
            tm0 = fmaxf(tm0, fmaxf(S[nt][0], S[nt][1]));
            tm1 = fmaxf(tm1, fmaxf(S[nt][2], S[nt][3]));
        }
        tm0 = fmaxf(tm0, __shfl_xor_sync(0xffffffffu, tm0, 1));
        tm0 = fmaxf(tm0, __shfl_xor_sync(0xffffffffu, tm0, 2));
        tm1 = fmaxf(tm1, __shfl_xor_sync(0xffffffffu, tm1, 1));
        tm1 = fmaxf(tm1, __shfl_xor_sync(0xffffffffu, tm1, 2));
        float mn0 = fmaxf(m0, tm0), mn1 = fmaxf(m1, tm1);
        float al0 = __expf(m0 - mn0), al1 = __expf(m1 - mn1);
        float sum0 = 0.f, sum1 = 0.f;
#pragma unroll
        for (int nt = 0; nt < 16; nt++) {
            S[nt][0] = __expf(S[nt][0] - mn0);
            S[nt][1] = __expf(S[nt][1] - mn0);
            S[nt][2] = __expf(S[nt][2] - mn1);
            S[nt][3] = __expf(S[nt][3] - mn1);
            sum0 += S[nt][0] + S[nt][1];
            sum1 += S[nt][2] + S[nt][3];
        }
        sum0 += __shfl_xor_sync(0xffffffffu, sum0, 1);
        sum0 += __shfl_xor_sync(0xffffffffu, sum0, 2);
        sum1 += __shfl_xor_sync(0xffffffffu, sum1, 1);
        sum1 += __shfl_xor_sync(0xffffffffu, sum1, 2);
        l0 = l0 * al0 + sum0;
        l1 = l1 * al1 + sum1;
        m0 = mn0; m1 = mn1;
#pragma unroll
        for (int nt = 0; nt < 16; nt++) {
            accO[nt][0] *= al0; accO[nt][1] *= al0;
            accO[nt][2] *= al1; accO[nt][3] *= al1;
        }

        CP_WAIT(0);        // V ready
        __syncthreads();

#pragma unroll
        for (int pk = 0; pk < 8; pk++) {
            uint32_t ph[4], pl[4];
            ph[0] = packbf(S[2*pk][0], S[2*pk][1]);     pl[0] = packlo(S[2*pk][0], S[2*pk][1], ph[0]);
            ph[1] = packbf(S[2*pk][2], S[2*pk][3]);     pl[1] = packlo(S[2*pk][2], S[2*pk][3], ph[1]);
            ph[2] = packbf(S[2*pk+1][0], S[2*pk+1][1]); pl[2] = packlo(S[2*pk+1][0], S[2*pk+1][1], ph[2]);
            ph[3] = packbf(S[2*pk+1][2], S[2*pk+1][3]); pl[3] = packlo(S[2*pk+1][2], S[2*pk+1][3], ph[3]);
            uint32_t vo = ((uint32_t)(pk * 16 + (lane & 15)) * 136 + (lane >> 4) * 8) * 2;
#pragma unroll
            for (int ng4 = 0; ng4 < 8; ng4++) {
                uint32_t co = vo + ng4 * 16 * 2;
                uint32_t vh[4], vl[4];
                ldm_x4_t(vh, sb + 139264 + co);
                ldm_x4_t(vl, sb + 174080 + co);
                mma16816(accO[ng4*2],   ph, &vh[0]);
                mma16816(accO[ng4*2+1], ph, &vh[2]);
                mma16816(accO[ng4*2],   ph, &vl[0]);
                mma16816(accO[ng4*2+1], ph, &vl[2]);
                mma16816(accO[ng4*2],   pl, &vh[0]);
                mma16816(accO[ng4*2+1], pl, &vh[2]);
            }
        }
    }

    float inv0 = 1.f / l0, inv1 = 1.f / l1;
    const bool txt_tile = (blockIdx.x == LC / 128 - 1);
#pragma unroll
    for (int nt = 0; nt < 16; nt++) {
        int col = head * HDC + nt * 8 + (lane & 3) * 2;
        float a0 = accO[nt][0] * inv0, a1 = accO[nt][1] * inv0;
        float b0 = accO[nt][2] * inv1, b1 = accO[nt][3] * inv1;
        if (txt_tile) {
            split_store2(d_cat_hi, d_cat_lo, (size_t)r0 * W2K + col, a0, a1);
            split_store2(d_cat_hi, d_cat_lo, (size_t)(r0 + 8) * W2K + col, b0, b1);
        } else {
            *(float2*)&d_cat[(size_t)r0 * W2K + col]       = make_float2(a0, a1);
            *(float2*)&d_cat[(size_t)(r0 + 8) * W2K + col] = make_float2(b0, b1);
        }
    }
}

// ---------------- HMMA audio cross-attention: 128q x 128 audio keys ----------------
__global__ void __launch_bounds__(256, 1) xattn_hmma(const float* __restrict__ fmask,
                                                     const float* __restrict__ ascale) {
    extern __shared__ __nv_bfloat16 smb[];
    const int tid = threadIdx.x, lane = tid & 31, wid = tid >> 5;
    const int head = blockIdx.y, q0 = blockIdx.x * 128;
    const size_t colbase = (size_t)head * HDC;
    const uint32_t sb = smem_u32(smb);
    const float scale = 0.08838834764831845f;

    for (int i = tid; i < 2048; i += 256) {
        int r = i >> 4, c8 = (i & 15) * 8;
        size_t gq = (size_t)(q0 + r) * HIDC + colbase + c8;
        size_t ga = (size_t)r * HIDC + colbase + c8;
        int so = r * 136 + c8;
        *(uint4*)&smb[so]          = *(const uint4*)&d_q_hi[gq];
        *(uint4*)&smb[17408 + so]  = *(const uint4*)&d_q_lo[gq];
        *(uint4*)&smb[34816 + so]  = *(const uint4*)&d_ak_hi[ga];
        *(uint4*)&smb[52224 + so]  = *(const uint4*)&d_ak_lo[ga];
        *(uint4*)&smb[69632 + so]  = *(const uint4*)&d_av_hi[ga];
        *(uint4*)&smb[87040 + so]  = *(const uint4*)&d_av_lo[ga];
    }
    __syncthreads();

    float S[16][4];
#pragma unroll
    for (int nt = 0; nt < 16; nt++)
#pragma unroll
        for (int u = 0; u < 4; u++) S[nt][u] = 0.f;
#pragma unroll
    for (int half = 0; half < 2; half++) {
#pragma unroll
        for (int ks = 0; ks < 8; ks++) {
            uint32_t qa[2][4], kb[2][4][4];
            uint32_t aoff = ((uint32_t)(wid * 16 + (lane & 15)) * 136 + ks * 16 + (lane >> 4) * 8) * 2;
            ldm_x4(qa[0], sb + aoff);
            ldm_x4(qa[1], sb + 34816 + aoff);
            uint32_t bo_ = ((uint32_t)(half * 64 + ((lane >> 4) & 1) * 8 + (lane & 7)) * 136
                            + ks * 16 + ((lane >> 3) & 1) * 8) * 2;
#pragma unroll
            for (int ng = 0; ng < 4; ng++) {
                uint32_t ro = bo_ + ng * 16 * 136 * 2;
                ldm_x4(kb[0][ng], sb + 69632 + ro);
                ldm_x4(kb[1][ng], sb + 104448 + ro);
            }
#pragma unroll
            for (int cmb = 0; cmb < 3; cmb++) {
                const int ao = (cmb == 2) ? 1 : 0;
                const int bo = (cmb == 1) ? 1 : 0;
#pragma unroll
                for (int nt = 0; nt < 8; nt++)
                    mma16816(S[half * 8 + nt], qa[ao], &kb[bo][nt >> 1][(nt & 1) * 2]);
            }
        }
    }

    float tm0 = -INFINITY, tm1 = -INFINITY;
#pragma unroll
    for (int nt = 0; nt < 16; nt++) {
        S[nt][0] *= scale; S[nt][1] *= scale; S[nt][2] *= scale; S[nt][3] *= scale;
        tm0 = fmaxf(tm0, fmaxf(S[nt][0], S[nt][1]));
        tm1 = fmaxf(tm1, fmaxf(S[nt][2], S[nt][3]));
    }
    tm0 = fmaxf(tm0, __shfl_xor_sync(0xffffffffu, tm0, 1));
    tm0 = fmaxf(tm0, __shfl_xor_sync(0xffffffffu, tm0, 2));
    tm1 = fmaxf(tm1, __shfl_xor_sync(0xffffffffu, tm1, 1));
    tm1 = fmaxf(tm1, __shfl_xor_sync(0xffffffffu, tm1, 2));
    float sum0 = 0.f, sum1 = 0.f;
#pragma unroll
    for (int nt = 0; nt < 16; nt++) {
        S[nt][0] = __expf(S[nt][0] - tm0);
        S[nt][1] = __expf(S[nt][1] - tm0);
        S[nt][2] = __expf(S[nt][2] - tm1);
        S[nt][3] = __expf(S[nt][3] - tm1);
        sum0 += S[nt][0] + S[nt][1];
        sum1 += S[nt][2] + S[nt][3];
    }
    sum0 += __shfl_xor_sync(0xffffffffu, sum0, 1);
    sum0 += __shfl_xor_sync(0xffffffffu, sum0, 2);
    sum1 += __shfl_xor_sync(0xffffffffu, sum1, 1);
    sum1 += __shfl_xor_sync(0xffffffffu, sum1, 2);

    float accO[16][4];
#pragma unroll
    for (int nt = 0; nt < 16; nt++)
#pragma unroll
        for (int u = 0; u < 4; u++) accO[nt][u] = 0.f;
#pragma unroll
    for (int pk = 0; pk < 8; pk++) {
        uint32_t ph[4], pl[4];
        ph[0] = packbf(S[2*pk][0], S[2*pk][1]);     pl[0] = packlo(S[2*pk][0], S[2*pk][1], ph[0]);
        ph[1] = packbf(S[2*pk][2], S[2*pk][3]);     pl[1] = packlo(S[2*pk][2], S[2*pk][3], ph[1]);
        ph[2] = packbf(S[2*pk+1][0], S[2*pk+1][1]); pl[2] = packlo(S[2*pk+1][0], S[2*pk+1][1], ph[2]);
        ph[3] = packbf(S[2*pk+1][2], S[2*pk+1][3]); pl[3] = packlo(S[2*pk+1][2], S[2*pk+1][3], ph[3]);
        uint32_t vo = ((uint32_t)(pk * 16 + (lane & 15)) * 136 + (lane >> 4) * 8) * 2;
#pragma unroll
        for (int ng4 = 0; ng4 < 8; ng4++) {
            uint32_t co = vo + ng4 * 16 * 2;
            uint32_t vh[4], vl[4];
            ldm_x4_t(vh, sb + 139264 + co);
            ldm_x4_t(vl, sb + 174080 + co);
            mma16816(accO[ng4*2],   ph, &vh[0]);
            mma16816(accO[ng4*2+1], ph, &vh[2]);
            mma16816(accO[ng4*2],   ph, &vl[0]);
            mma16816(accO[ng4*2+1], ph, &vl[2]);
            mma16816(accO[ng4*2],   pl, &vh[0]);
            mma16816(accO[ng4*2+1], pl, &vh[2]);
        }
    }

    const float as = fminf(ascale[0], 2.0f);
    const int r0 = q0 + wid * 16 + (lane >> 2);
    const int r1 = r0 + 8;
    int t0 = r0 / 384, rem0 = r0 % 384;
    int t1 = r1 / 384, rem1 = r1 % 384;
    float fm0 = fmask[t0 * 1536 + (rem0 / 16) * 64 + (rem0 % 16) * 2];
    float fm1 = fmask[t1 * 1536 + (rem1 / 16) * 64 + (rem1 % 16) * 2];
    float mf0 = fm0 * as / sum0;
    float mf1 = fm1 * as / sum1;
#pragma unroll
    for (int nt = 0; nt < 16; nt++) {
        int col = head * HDC + nt * 8 + (lane & 3) * 2;
        float2 c0 = *(float2*)&d_cat[(size_t)r0 * W2K + col];
        float2 c1 = *(float2*)&d_cat[(size_t)r1 * W2K + col];
        split_store2(d_cat_hi, d_cat_lo, (size_t)r0 * W2K + col,
                     c0.x + accO[nt][0] * mf0, c0.y + accO[nt][1] * mf0);
        split_store2(d_cat_hi, d_cat_lo, (size_t)r1 * W2K + col,
                     c1.x + accO[nt][2] * mf1, c1.y + accO[nt][3] * mf1);
    }
}

extern "C" void kernel_launch(void* const* d_in, const int* in_sizes, int n_in,
                              void* d_out, int out_size) {
    const float* x     = (const float*)d_in[0];
    const float* vec   = (const float*)d_in[1];
    const float* trv   = (const float*)d_in[2];
    const float* fcos  = (const float*)d_in[3];
    const float* fsin  = (const float*)d_in[4];
    const float* aemb  = (const float*)d_in[5];
    const float* fmask = (const float*)d_in[6];
    const int*   cu    = (const int*)d_in[7];
    const float* mw    = (const float*)d_in[10];
    const float* mb    = (const float*)d_in[11];
    const float* w1    = (const float*)d_in[12];
    const float* b1    = (const float*)d_in[13];
    const float* qnw   = (const float*)d_in[14];
    const float* knw   = (const float*)d_in[15];
    const float* w2    = (const float*)d_in[16];
    const float* b2    = (const float*)d_in[17];
    const float* aqw   = (const float*)d_in[18];
    const float* aqb   = (const float*)d_in[19];
    const float* aknw  = (const float*)d_in[21];
    const float* ascale= (const float*)d_in[22];
    float* out = (float*)d_out;

    float* gp   = nullptr; cudaGetSymbolAddress((void**)&gp,   d_gp);
    __nv_bfloat16 *ahi, *alo, *anhi, *anlo, *chi, *clo;
    __nv_bfloat16 *w1h, *w1l, *w2h, *w2l, *awh, *awl;
    cudaGetSymbolAddress((void**)&ahi,  d_a_hi);  cudaGetSymbolAddress((void**)&alo,  d_a_lo);
    cudaGetSymbolAddress((void**)&anhi, d_an_hi); cudaGetSymbolAddress((void**)&anlo, d_an_lo);
    cudaGetSymbolAddress((void**)&chi,  d_cat_hi);cudaGetSymbolAddress((void**)&clo,  d_cat_lo);
    cudaGetSymbolAddress((void**)&w1h,  d_w1t_hi);cudaGetSymbolAddress((void**)&w1l,  d_w1t_lo);
    cudaGetSymbolAddress((void**)&w2h,  d_w2t_hi);cudaGetSymbolAddress((void**)&w2l,  d_w2t_lo);
    cudaGetSymbolAddress((void**)&awh,  d_awt_hi);cudaGetSymbolAddress((void**)&awl,  d_awt_lo);

    const int ATTN_SMEM = 208896;
    cudaFuncSetAttribute(attn_hmma,  cudaFuncAttributeMaxDynamicSharedMemorySize, ATTN_SMEM);
    cudaFuncSetAttribute(xattn_hmma, cudaFuncAttributeMaxDynamicSharedMemorySize, ATTN_SMEM);
    const int GEMM_SMEM = 81920;
    cudaFuncSetAttribute(hmma_gemm_akv, cudaFuncAttributeMaxDynamicSharedMemorySize, GEMM_SMEM);
    const int GEMM_SMEM2 = 221184;
    cudaFuncSetAttribute(hmma_gemm_big<2>, cudaFuncAttributeMaxDynamicSharedMemorySize, GEMM_SMEM2);
    cudaFuncSetAttribute(hmma_gemm_big<3>, cudaFuncAttributeMaxDynamicSharedMemorySize, GEMM_SMEM2);

    mod_part<<<dim3(MODN / 128, 8), 512>>>(vec, trv, mw);
    mod_reduce<<<MODN / 256, 256>>>(mb);
    transpose_conv<<<dim3(W1N / 32, HIDC / 32), dim3(8, 32)>>>(w1, w1h, w1l, HIDC, W1N, 0);
    ln_mod_kernel<<<LC, 256>>>(x);
    hmma_gemm_big<2><<<dim3(LC / 256, W1N / 128, 1), 256, GEMM_SMEM2>>>(
        ahi, alo, w1h, w1l, b1, gp, LC, W1N, HIDC, qnw, knw, fcos, fsin);
    transpose_conv<<<dim3(HIDC / 32, W2K / 32), dim3(8, 32)>>>(w2, w2h, w2l, W2K, HIDC, 0);
    // only k/v region of audio qkv weight (cols 3072..9215)
    transpose_conv<<<dim3((2 * HIDC) / 32, HIDC / 32), dim3(8, 32)>>>(aqw, awh, awl, HIDC, MODN, HIDC);
    attn_hmma<<<dim3(LC / 128, HEADSC), 256, ATTN_SMEM>>>(cu);
    ln_plain_kernel<<<NAUD, 256>>>(aemb);
    hmma_gemm_akv<<<dim3(1, (2 * HIDC) / 128), 256, GEMM_SMEM>>>(
        anhi, anlo, awh + (size_t)HIDC * HIDC, awl + (size_t)HIDC * HIDC, aqb + HIDC, aknw, HIDC);
    xattn_hmma<<<dim3(LIMGC / 128, HEADSC), 256, ATTN_SMEM>>>(fmask, ascale);
    hmma_gemm_big<3><<<dim3(LC / 256, HIDC / 128, 3), 256, GEMM_SMEM2>>>(
        chi, clo, w2h, w2l, b2, gp, LC, HIDC, W2K, nullptr, nullptr, nullptr, nullptr);
    gemm2_combine<<<(int)(((size_t)LC * HIDC / 4) / 256), 256>>>(b2, x, out);
}

// round 15
// speedup vs baseline: 1.0764x; 1.0071x over previous
#include <cuda_runtime.h>
#include <cuda_bf16.h>
#include <math.h>
#include <stdint.h>

#define HIDC   3072
#define HEADSC 24
#define HDC    128
#define LC     2048
#define LIMGC  1920
#define FFNC   384
#define MLPDC  12288
#define W1N    21504
#define W2K    15360
#define MODN   9216
#define NAUD   128

// ---------------- scratch ----------------
__device__ float d_mod[MODN];
__device__ float d_trm[MODN];
__device__ float d_modp[8][MODN];
__device__ float d_trmp[8][MODN];
__device__ float d_gp[(size_t)3 * LC * HIDC];
__device__ __align__(16) __nv_bfloat16 d_a_hi[(size_t)LC * HIDC];
__device__ __align__(16) __nv_bfloat16 d_a_lo[(size_t)LC * HIDC];
__device__ __align__(16) __nv_bfloat16 d_an_hi[(size_t)NAUD * HIDC];
__device__ __align__(16) __nv_bfloat16 d_an_lo[(size_t)NAUD * HIDC];
__device__ __align__(16) __nv_bfloat16 d_cat_hi[(size_t)LC * W2K];
__device__ __align__(16) __nv_bfloat16 d_cat_lo[(size_t)LC * W2K];
__device__ __align__(16) __nv_bfloat16 d_w1t_hi[(size_t)W1N * HIDC];
__device__ __align__(16) __nv_bfloat16 d_w1t_lo[(size_t)W1N * HIDC];
__device__ __align__(16) __nv_bfloat16 d_w2t_hi[(size_t)HIDC * W2K];
__device__ __align__(16) __nv_bfloat16 d_w2t_lo[(size_t)HIDC * W2K];
__device__ __align__(16) __nv_bfloat16 d_awt_hi[(size_t)MODN * HIDC];
__device__ __align__(16) __nv_bfloat16 d_awt_lo[(size_t)MODN * HIDC];
__device__ __align__(16) __nv_bfloat16 d_q_hi[(size_t)LC * HIDC];
__device__ __align__(16) __nv_bfloat16 d_q_lo[(size_t)LC * HIDC];
__device__ __align__(16) __nv_bfloat16 d_k_hi[(size_t)LC * HIDC];
__device__ __align__(16) __nv_bfloat16 d_k_lo[(size_t)LC * HIDC];
__device__ __align__(16) __nv_bfloat16 d_v_hi[(size_t)LC * HIDC];
__device__ __align__(16) __nv_bfloat16 d_v_lo[(size_t)LC * HIDC];
__device__ __align__(16) __nv_bfloat16 d_ak_hi[(size_t)NAUD * HIDC];
__device__ __align__(16) __nv_bfloat16 d_ak_lo[(size_t)NAUD * HIDC];
__device__ __align__(16) __nv_bfloat16 d_av_hi[(size_t)NAUD * HIDC];
__device__ __align__(16) __nv_bfloat16 d_av_lo[(size_t)NAUD * HIDC];

// ---------------- helpers ----------------
__device__ __forceinline__ uint32_t smem_u32(const void* p) {
    uint32_t a;
    asm("{ .reg .u64 t; cvta.to.shared.u64 t, %1; cvt.u32.u64 %0, t; }" : "=r"(a) : "l"(p));
    return a;
}
__device__ __forceinline__ void ldm_x4(uint32_t* r, uint32_t addr) {
    asm volatile("ldmatrix.sync.aligned.m8n8.x4.shared.b16 {%0,%1,%2,%3}, [%4];"
        : "=r"(r[0]), "=r"(r[1]), "=r"(r[2]), "=r"(r[3]) : "r"(addr));
}
__device__ __forceinline__ void ldm_x4_t(uint32_t* r, uint32_t addr) {
    asm volatile("ldmatrix.sync.aligned.m8n8.x4.trans.shared.b16 {%0,%1,%2,%3}, [%4];"
        : "=r"(r[0]), "=r"(r[1]), "=r"(r[2]), "=r"(r[3]) : "r"(addr));
}
__device__ __forceinline__ void mma16816(float* d, const uint32_t* a, const uint32_t* b) {
    asm volatile("mma.sync.aligned.m16n8k16.row.col.f32.bf16.bf16.f32 "
        "{%0,%1,%2,%3}, {%4,%5,%6,%7}, {%8,%9}, {%0,%1,%2,%3};"
        : "+f"(d[0]), "+f"(d[1]), "+f"(d[2]), "+f"(d[3])
        : "r"(a[0]), "r"(a[1]), "r"(a[2]), "r"(a[3]), "r"(b[0]), "r"(b[1]));
}
__device__ __forceinline__ void cp16(uint32_t dst, const void* src) {
    asm volatile("cp.async.cg.shared.global [%0], [%1], 16;" :: "r"(dst), "l"(src));
}
#define CP_COMMIT() asm volatile("cp.async.commit_group;" ::: "memory")
#define CP_WAIT(n)  asm volatile("cp.async.wait_group %0;" :: "n"(n) : "memory")

__device__ __forceinline__ uint32_t packbf(float a, float b) {
    __nv_bfloat162 t = __floats2bfloat162_rn(a, b);
    return *reinterpret_cast<uint32_t*>(&t);
}
__device__ __forceinline__ uint32_t packlo(float a, float b, uint32_t hi) {
    __nv_bfloat162 h = *reinterpret_cast<__nv_bfloat162*>(&hi);
    return packbf(a - __bfloat162float(h.x), b - __bfloat162float(h.y));
}
__device__ __forceinline__ float gelu_fast(float x) {
    float u2 = 1.5957691216057308f * (x + 0.044715f * x * x * x);
    return x / (1.f + __expf(-u2));
}
__device__ __forceinline__ void block_reduce2(float& s, float& s2, float* buf) {
    int tid = threadIdx.x, lane = tid & 31, w = tid >> 5;
#pragma unroll
    for (int o = 16; o > 0; o >>= 1) {
        s  += __shfl_xor_sync(0xffffffffu, s,  o);
        s2 += __shfl_xor_sync(0xffffffffu, s2, o);
    }
    if (lane == 0) { buf[w] = s; buf[32 + w] = s2; }
    __syncthreads();
    if (tid == 0) {
        float a = 0.f, b = 0.f;
#pragma unroll
        for (int i = 0; i < 8; i++) { a += buf[i]; b += buf[32 + i]; }
        buf[0] = a; buf[32] = b;
    }
    __syncthreads();
    s = buf[0]; s2 = buf[32];
}
__device__ __forceinline__ void split_store4(__nv_bfloat16* hi, __nv_bfloat16* lo, size_t i, float4 v) {
    __nv_bfloat162 h0 = __floats2bfloat162_rn(v.x, v.y);
    __nv_bfloat162 h1 = __floats2bfloat162_rn(v.z, v.w);
    *(uint2*)&hi[i] = make_uint2(*(uint32_t*)&h0, *(uint32_t*)&h1);
    __nv_bfloat162 l0 = __floats2bfloat162_rn(v.x - __bfloat162float(h0.x), v.y - __bfloat162float(h0.y));
    __nv_bfloat162 l1 = __floats2bfloat162_rn(v.z - __bfloat162float(h1.x), v.w - __bfloat162float(h1.y));
    *(uint2*)&lo[i] = make_uint2(*(uint32_t*)&l0, *(uint32_t*)&l1);
}
__device__ __forceinline__ void split_store2(__nv_bfloat16* hi, __nv_bfloat16* lo, size_t i, float a, float b) {
    __nv_bfloat162 h = __floats2bfloat162_rn(a, b);
    *(uint32_t*)&hi[i] = *(uint32_t*)&h;
    __nv_bfloat162 l = __floats2bfloat162_rn(a - __bfloat162float(h.x), b - __bfloat162float(h.y));
    *(uint32_t*)&lo[i] = *(uint32_t*)&l;
}

// ---------------- transpose + bf16 split: W[K,N] -> out[N,K], cols n_off.. ----------------
__global__ void transpose_conv(const float* __restrict__ W, __nv_bfloat16* __restrict__ hi,
                               __nv_bfloat16* __restrict__ lo, int K, int N, int n_off) {
    __shared__ float t[32][36];
    int n0 = n_off + blockIdx.x * 32, k0 = blockIdx.y * 32;
    int tx = threadIdx.x;
    int ty = threadIdx.y;
    float4 v = *(const float4*)&W[(size_t)(k0 + ty) * N + n0 + tx * 4];
    t[ty][tx * 4 + 0] = v.x; t[ty][tx * 4 + 1] = v.y;
    t[ty][tx * 4 + 2] = v.z; t[ty][tx * 4 + 3] = v.w;
    __syncthreads();
    float4 o = make_float4(t[tx * 4 + 0][ty], t[tx * 4 + 1][ty],
                           t[tx * 4 + 2][ty], t[tx * 4 + 3][ty]);
    split_store4(hi, lo, (size_t)(n0 + ty) * K + k0 + tx * 4, o);
}

// ---------------- mod partials ----------------
__global__ void mod_part(const float* __restrict__ vec, const float* __restrict__ trv,
                         const float* __restrict__ mw) {
    __shared__ float sv[384], st[384];
    __shared__ float part[2][4][128];
    int tid = threadIdx.x, by = blockIdx.y;
    if (tid < 384) {
        int k = by * 384 + tid;
        float a = vec[k]; sv[tid] = a / (1.f + expf(-a));
        float b = trv[k]; st[tid] = b / (1.f + expf(-b));
    }
    __syncthreads();
    int jl = tid & 127, sl = tid >> 7;
    int j = blockIdx.x * 128 + jl;
    float a0 = 0.f, a1 = 0.f;
    int kend = (sl + 1) * 96;
    for (int kl = sl * 96; kl < kend; kl++) {
        float w = mw[(size_t)(by * 384 + kl) * MODN + j];
        a0 = fmaf(sv[kl], w, a0);
        a1 = fmaf(st[kl], w, a1);
    }
    part[0][sl][jl] = a0; part[1][sl][jl] = a1;
    __syncthreads();
    if (tid < 128) {
        int jj = blockIdx.x * 128 + tid;
        d_modp[by][jj] = part[0][0][tid] + part[0][1][tid] + part[0][2][tid] + part[0][3][tid];
    } else if (tid < 256) {
        int t = tid - 128, jj = blockIdx.x * 128 + t;
        d_trmp[by][jj] = part[1][0][t] + part[1][1][t] + part[1][2][t] + part[1][3][t];
    }
}
__global__ void mod_reduce(const float* __restrict__ mb) {
    int j = blockIdx.x * 256 + threadIdx.x;
    float s0 = mb[j], s1 = mb[j];
#pragma unroll
    for (int p = 0; p < 8; p++) { s0 += d_modp[p][j]; s1 += d_trmp[p][j]; }
    d_mod[j] = s0; d_trm[j] = s1;
}

// ---------------- LN + modulate -> bf16 hi/lo ----------------
__global__ void ln_mod_kernel(const float* __restrict__ x) {
    int row = blockIdx.x, tid = threadIdx.x;
    const float* xr = x + (size_t)row * HIDC;
    float s = 0.f, s2 = 0.f;
    for (int j = tid * 4; j < HIDC; j += 1024) {
        float4 v = *(const float4*)&xr[j];
        s  += v.x + v.y + v.z + v.w;
        s2 += v.x*v.x + v.y*v.y + v.z*v.z + v.w*v.w;
    }
    __shared__ float buf[64];
    block_reduce2(s, s2, buf);
    float mean = s * (1.f / HIDC);
    float inv = rsqrtf(s2 * (1.f / HIDC) - mean * mean + 1e-6f);
    const float* mv = (row < FFNC) ? d_trm : d_mod;
    for (int j = tid * 4; j < HIDC; j += 1024) {
        float4 v  = *(const float4*)&xr[j];
        float4 sc = *(const float4*)&mv[HIDC + j];
        float4 sh = *(const float4*)&mv[j];
        float4 o;
        o.x = (v.x - mean) * inv * (1.f + sc.x) + sh.x;
        o.y = (v.y - mean) * inv * (1.f + sc.y) + sh.y;
        o.z = (v.z - mean) * inv * (1.f + sc.z) + sh.z;
        o.w = (v.w - mean) * inv * (1.f + sc.w) + sh.w;
        split_store4(d_a_hi, d_a_lo, (size_t)row * HIDC + j, o);
    }
}

// ---------------- audio LN -> bf16 hi/lo ----------------
__global__ void ln_plain_kernel(const float* __restrict__ a) {
    int row = blockIdx.x, tid = threadIdx.x;
    const float* xr = a + (size_t)row * HIDC;
    float s = 0.f, s2 = 0.f;
    for (int j = tid * 4; j < HIDC; j += 1024) {
        float4 v = *(const float4*)&xr[j];
        s  += v.x + v.y + v.z + v.w;
        s2 += v.x*v.x + v.y*v.y + v.z*v.z + v.w*v.w;
    }
    __shared__ float buf[64];
    block_reduce2(s, s2, buf);
    float mean = s * (1.f / HIDC);
    float inv = rsqrtf(s2 * (1.f / HIDC) - mean * mean + 1e-6f);
    for (int j = tid * 4; j < HIDC; j += 1024) {
        float4 v = *(const float4*)&xr[j];
        float4 o = make_float4((v.x - mean) * inv, (v.y - mean) * inv,
                               (v.z - mean) * inv, (v.w - mean) * inv);
        split_store4(d_an_hi, d_an_lo, (size_t)row * HIDC + j, o);
    }
}

// ---------------- GEMM2 combine ----------------
__global__ void gemm2_combine(const float* __restrict__ bias, const float* __restrict__ resid,
                              float* __restrict__ out) {
    size_t i = ((size_t)blockIdx.x * 256 + threadIdx.x) * 4;
    int m = (int)(i / HIDC), n = (int)(i % HIDC);
    const float* gv = (m < FFNC) ? d_trm : d_mod;
    float4 p0 = *(const float4*)&d_gp[i];
    float4 p1 = *(const float4*)&d_gp[(size_t)LC * HIDC + i];
    float4 p2 = *(const float4*)&d_gp[(size_t)2 * LC * HIDC + i];
    float4 bb = *(const float4*)&bias[n];
    float4 gg = *(const float4*)&gv[2 * HIDC + n];
    float4 rr = *(const float4*)&resid[i];
    float4 o;
    o.x = rr.x + (p0.x + p1.x + p2.x + bb.x) * gg.x;
    o.y = rr.y + (p0.y + p1.y + p2.y + bb.y) * gg.y;
    o.z = rr.z + (p0.z + p1.z + p2.z + bb.z) * gg.z;
    o.w = rr.w + (p0.w + p1.w + p2.w + bb.w) * gg.w;
    *(float4*)&out[i] = o;
}

// ---------------- big HMMA GEMM: 256x128 CTA, 64x64 warp, BK=64, 2 stages ----------------
template<int MODE>
__global__ void __launch_bounds__(256, 1) hmma_gemm_big(
        const __nv_bfloat16* __restrict__ Ahi, const __nv_bfloat16* __restrict__ Alo,
        const __nv_bfloat16* __restrict__ Bhi, const __nv_bfloat16* __restrict__ Blo,
        const float* __restrict__ bias, float* __restrict__ C,
        int M, int N, int K,
        const float* __restrict__ qnw, const float* __restrict__ knw,
        const float* __restrict__ fcos, const float* __restrict__ fsin) {
    extern __shared__ char smraw[];
    const int tid = threadIdx.x;
    const int lane = tid & 31, wid = tid >> 5;
    const int bm = blockIdx.x * 256, bn = blockIdx.y * 128;
    const int wm = wid & 3, wn = wid >> 2;
    const int Kper = K / gridDim.z;
    const int ko = blockIdx.z * Kper;
    const uint32_t sbase = smem_u32(smraw);
    const __nv_bfloat16* srcs[4] = {
        Ahi + (size_t)bm * K + ko, Alo + (size_t)bm * K + ko,
        Bhi + (size_t)bn * K + ko, Blo + (size_t)bn * K + ko };

    float acc[4][8][4];
#pragma unroll
    for (int a = 0; a < 4; a++)
#pragma unroll
        for (int b = 0; b < 8; b++)
#pragma unroll
            for (int c = 0; c < 4; c++) acc[a][b][c] = 0.f;

    const int NC = Kper >> 6;
#pragma unroll
    for (int i = 0; i < 24; i++) {
        int id = tid + i * 256;
        if (id < 4096) {
            int op = id >> 11, rem = id & 2047, r = rem >> 3, q = rem & 7;
            cp16(sbase + op * 36864 + r * 144 + q * 16, srcs[op] + (size_t)r * K + q * 8);
        } else {
            int t = id - 4096, op = t >> 10, rem = t & 1023, r = rem >> 3, q = rem & 7;
            cp16(sbase + 73728 + op * 18432 + r * 144 + q * 16, srcs[2 + op] + (size_t)r * K + q * 8);
        }
    }
    CP_COMMIT();

    for (int c = 0; c < NC; c++) {
        const int stage = c & 1;
        if (c + 1 < NC) {
            const int kc = (c + 1) << 6;
            const uint32_t db = sbase + (stage ^ 1) * 110592;
#pragma unroll
            for (int i = 0; i < 24; i++) {
                int id = tid + i * 256;
                if (id < 4096) {
                    int op = id >> 11, rem = id & 2047, r = rem >> 3, q = rem & 7;
                    cp16(db + op * 36864 + r * 144 + q * 16, srcs[op] + (size_t)r * K + kc + q * 8);
                } else {
                    int t = id - 4096, op = t >> 10, rem = t & 1023, r = rem >> 3, q = rem & 7;
                    cp16(db + 73728 + op * 18432 + r * 144 + q * 16, srcs[2 + op] + (size_t)r * K + kc + q * 8);
                }
            }
            CP_COMMIT();
            CP_WAIT(1);
        } else {
            CP_WAIT(0);
        }
        __syncthreads();
        const uint32_t base = sbase + stage * 110592;
#pragma unroll
        for (int kk = 0; kk < 4; kk++) {
            uint32_t afr[2][4][4];
            uint32_t bfr[2][4][4];
            const uint32_t aoff = (uint32_t)(wm * 64 + (lane & 15)) * 144 + kk * 32 + (lane >> 4) * 16;
#pragma unroll
            for (int op = 0; op < 2; op++)
#pragma unroll
                for (int mi = 0; mi < 4; mi++)
                    ldm_x4(afr[op][mi], base + op * 36864 + aoff + mi * 16 * 144);
            const uint32_t boff = (uint32_t)(wn * 64 + ((lane >> 4) & 1) * 8 + (lane & 7)) * 144
                                  + kk * 32 + ((lane >> 3) & 1) * 16;
#pragma unroll
            for (int op = 0; op < 2; op++)
#pragma unroll
                for (int ng = 0; ng < 4; ng++)
                    ldm_x4(bfr[op][ng], base + 73728 + op * 18432 + boff + ng * 16 * 144);
#pragma unroll
            for (int cmb = 0; cmb < 3; cmb++) {
                const int ao = (cmb == 2) ? 1 : 0;
                const int bo = (cmb == 1) ? 1 : 0;
#pragma unroll
                for (int mi = 0; mi < 4; mi++)
#pragma unroll
                    for (int ng = 0; ng < 4; ng++) {
                        mma16816(acc[mi][ng * 2 + 0], afr[ao][mi], &bfr[bo][ng][0]);
                        mma16816(acc[mi][ng * 2 + 1], afr[ao][mi], &bfr[bo][ng][2]);
                    }
            }
        }
        __syncthreads();
    }
    const int gid = lane >> 2, tq = (lane & 3) << 1;

    if (MODE == 2 && bn < 2 * HIDC) {
        __syncthreads();
        float* red = (float*)smraw;
#pragma unroll
        for (int mi = 0; mi < 4; mi++)
#pragma unroll
            for (int ni = 0; ni < 8; ni++) {
                int n = bn + wn * 64 + ni * 8 + tq;
                float b0 = bias[n], b1 = bias[n + 1];
                acc[mi][ni][0] += b0; acc[mi][ni][1] += b1;
                acc[mi][ni][2] += b0; acc[mi][ni][3] += b1;
            }
#pragma unroll
        for (int mi = 0; mi < 4; mi++)
#pragma unroll
            for (int half = 0; half < 2; half++) {
                float s = 0.f;
#pragma unroll
                for (int ni = 0; ni < 8; ni++) {
                    float v0 = acc[mi][ni][half * 2], v1 = acc[mi][ni][half * 2 + 1];
                    s += v0 * v0 + v1 * v1;
                }
                s += __shfl_xor_sync(0xffffffffu, s, 1);
                s += __shfl_xor_sync(0xffffffffu, s, 2);
                if ((lane & 3) == 0)
                    red[wn * 256 + wm * 64 + mi * 16 + half * 8 + gid] = s;
            }
        __syncthreads();
        const bool isq = bn < HIDC;
        const int head = (isq ? bn : bn - HIDC) >> 7;
        const float* rw = isq ? qnw : knw;
        __nv_bfloat16* ohi = isq ? d_q_hi : d_k_hi;
        __nv_bfloat16* olo = isq ? d_q_lo : d_k_lo;
#pragma unroll
        for (int mi = 0; mi < 4; mi++)
#pragma unroll
            for (int half = 0; half < 2; half++) {
                int rloc = wm * 64 + mi * 16 + half * 8 + gid;
                int m = bm + rloc;
                float rs = rsqrtf((red[rloc] + red[256 + rloc]) * (1.f / HDC) + 1e-6f);
                bool rope = m < LIMGC;
#pragma unroll
                for (int ni = 0; ni < 8; ni++) {
                    int cd = wn * 64 + ni * 8 + tq;
                    float v0 = acc[mi][ni][half * 2]     * rs * rw[cd];
                    float v1 = acc[mi][ni][half * 2 + 1] * rs * rw[cd + 1];
                    if (rope) {
                        float cc = fcos[m * HDC + cd];
                        float sc = fsin[m * HDC + cd];
                        float n0 = v0 * cc - v1 * sc;
                        float n1 = v1 * cc + v0 * sc;
                        v0 = n0; v1 = n1;
                    }
                    split_store2(ohi, olo, (size_t)m * HIDC + head * HDC + cd, v0, v1);
                }
            }
        return;
    }

    float* Cz = (MODE == 3) ? (C + (size_t)blockIdx.z * M * N) : C;
#pragma unroll
    for (int mi = 0; mi < 4; mi++) {
#pragma unroll
        for (int half = 0; half < 2; half++) {
            const int m = bm + wm * 64 + mi * 16 + half * 8 + gid;
#pragma unroll
            for (int ni = 0; ni < 8; ni++) {
                const int n = bn + wn * 64 + ni * 8 + tq;
                if (MODE == 3) {
                    *(float2*)&Cz[(size_t)m * N + n] =
                        make_float2(acc[mi][ni][half * 2 + 0], acc[mi][ni][half * 2 + 1]);
                } else {
                    float v0 = acc[mi][ni][half * 2 + 0] + bias[n];
                    float v1 = acc[mi][ni][half * 2 + 1] + bias[n + 1];
                    if (n < 3 * HIDC) {
                        size_t idx = (size_t)m * HIDC + (n - 2 * HIDC);
                        split_store2(d_v_hi, d_v_lo, idx, v0, v1);
                    } else {
                        size_t idx = (size_t)m * W2K + (n - 2 * HIDC);
                        split_store2(d_cat_hi, d_cat_lo, idx, gelu_fast(v0), gelu_fast(v1));
                    }
                }
            }
        }
    }
}

// ---------------- audio k/v HMMA GEMM (128x128 tile) with fused rms/split epilogue ----------------
__global__ void __launch_bounds__(256, 1) hmma_gemm_akv(
        const __nv_bfloat16* __restrict__ Ahi, const __nv_bfloat16* __restrict__ Alo,
        const __nv_bfloat16* __restrict__ Bhi, const __nv_bfloat16* __restrict__ Blo,
        const float* __restrict__ bias, const float* __restrict__ aknw, int K) {
    extern __shared__ char smraw[];
    const int tid = threadIdx.x;
    const int lane = tid & 31, wid = tid >> 5;
    const int bn = blockIdx.y * 128;
    const int wm = wid & 3, wn = wid >> 2;
    const uint32_t sbase = smem_u32(smraw);
    const __nv_bfloat16* srcs[4] = {
        Ahi, Alo, Bhi + (size_t)bn * K, Blo + (size_t)bn * K };
    float acc[2][8][4];
#pragma unroll
    for (int a = 0; a < 2; a++)
#pragma unroll
        for (int b = 0; b < 8; b++)
#pragma unroll
            for (int c = 0; c < 4; c++) acc[a][b][c] = 0.f;
    const int NC = K >> 5;
    {
#pragma unroll
        for (int i = 0; i < 8; i++) {
            int id = tid + i * 256;
            int op = id >> 9, rem = id & 511;
            int r = rem >> 2, q = rem & 3;
            cp16(sbase + op * 10240 + r * 80 + q * 16, srcs[op] + (size_t)r * K + q * 8);
        }
        CP_COMMIT();
    }
    for (int c = 0; c < NC; c++) {
        const int stage = c & 1;
        if (c + 1 < NC) {
            const int kc = (c + 1) << 5;
            const uint32_t db = sbase + (stage ^ 1) * 40960;
#pragma unroll
            for (int i = 0; i < 8; i++) {
                int id = tid + i * 256;
                int op = id >> 9, rem = id & 511;
                int r = rem >> 2, q = rem & 3;
                cp16(db + op * 10240 + r * 80 + q * 16, srcs[op] + (size_t)r * K + kc + q * 8);
            }
            CP_COMMIT();
            CP_WAIT(1);
        } else {
            CP_WAIT(0);
        }
        __syncthreads();
        const uint32_t base = sbase + stage * 40960;
#pragma unroll
        for (int kk = 0; kk < 2; kk++) {
            uint32_t afr[2][2][4];
            uint32_t bfr[2][4][4];
            const uint32_t aoff = (uint32_t)(wm * 32 + (lane & 15)) * 80 + kk * 32 + (lane >> 4) * 16;
#pragma unroll
            for (int op = 0; op < 2; op++)
#pragma unroll
                for (int mi = 0; mi < 2; mi++)
                    ldm_x4(afr[op][mi], base + op * 10240 + aoff + mi * 16 * 80);
            const uint32_t boff = (uint32_t)(wn * 64 + ((lane >> 4) & 1) * 8 + (lane & 7)) * 80
                                  + kk * 32 + ((lane >> 3) & 1) * 16;
#pragma unroll
            for (int op = 0; op < 2; op++)
#pragma unroll
                for (int ng = 0; ng < 4; ng++)
                    ldm_x4(bfr[op][ng], base + 20480 + op * 10240 + boff + ng * 16 * 80);
#pragma unroll
            for (int cmb = 0; cmb < 3; cmb++) {
                const int ao = (cmb == 2) ? 1 : 0;
                const int bo = (cmb == 1) ? 1 : 0;
#pragma unroll
                for (int mi = 0; mi < 2; mi++)
#pragma unroll
                    for (int ng = 0; ng < 4; ng++) {
                        mma16816(acc[mi][ng * 2 + 0], afr[ao][mi], &bfr[bo][ng][0]);
                        mma16816(acc[mi][ng * 2 + 1], afr[ao][mi], &bfr[bo][ng][2]);
                    }
            }
        }
        __syncthreads();
    }
    const int gid = lane >> 2, tq = (lane & 3) << 1;
#pragma unroll
    for (int mi = 0; mi < 2; mi++)
#pragma unroll
        for (int ni = 0; ni < 8; ni++) {
            int n = bn + wn * 64 + ni * 8 + tq;
            float b0 = bias[n], b1 = bias[n + 1];
            acc[mi][ni][0] += b0; acc[mi][ni][1] += b1;
            acc[mi][ni][2] += b0; acc[mi][ni][3] += b1;
        }
    if (bn < HIDC) {
        __syncthreads();
        float* red = (float*)smraw;
#pragma unroll
        for (int mi = 0; mi < 2; mi++)
#pragma unroll
            for (int half = 0; half < 2; half++) {
                float s = 0.f;
#pragma unroll
                for (int ni = 0; ni < 8; ni++) {
                    float v0 = acc[mi][ni][half * 2], v1 = acc[mi][ni][half * 2 + 1];
                    s += v0 * v0 + v1 * v1;
                }
                s += __shfl_xor_sync(0xffffffffu, s, 1);
                s += __shfl_xor_sync(0xffffffffu, s, 2);
                if ((lane & 3) == 0)
                    red[wn * 128 + wm * 32 + mi * 16 + half * 8 + gid] = s;
            }
        __syncthreads();
        const int head = bn >> 7;
#pragma unroll
        for (int mi = 0; mi < 2; mi++)
#pragma unroll
            for (int half = 0; half < 2; half++) {
                int rloc = wm * 32 + mi * 16 + half * 8 + gid;
                float rs = rsqrtf((red[rloc] + red[128 + rloc]) * (1.f / HDC) + 1e-6f);
#pragma unroll
                for (int ni = 0; ni < 8; ni++) {
                    int cd = wn * 64 + ni * 8 + tq;
                    float v0 = acc[mi][ni][half * 2]     * rs * aknw[cd];
                    float v1 = acc[mi][ni][half * 2 + 1] * rs * aknw[cd + 1];
                    split_store2(d_ak_hi, d_ak_lo, (size_t)rloc * HIDC + head * HDC + cd, v0, v1);
                }
            }
    } else {
#pragma unroll
        for (int mi = 0; mi < 2; mi++)
#pragma unroll
            for (int half = 0; half < 2; half++) {
                int row = wm * 32 + mi * 16 + half * 8 + gid;
#pragma unroll
                for (int ni = 0; ni < 8; ni++) {
                    int n = bn + wn * 64 + ni * 8 + tq;
                    split_store2(d_av_hi, d_av_lo, (size_t)row * HIDC + (n - HIDC),
                                 acc[mi][ni][half * 2], acc[mi][ni][half * 2 + 1]);
                }
            }
    }
}

// ---------------- HMMA flash self-attention + fused audio cross-attention ----------------
__global__ void __launch_bounds__(256, 1) attn_hmma(const int* __restrict__ cu,
                                                    const float* __restrict__ fmask,
                                                    const float* __restrict__ ascale) {
    extern __shared__ __nv_bfloat16 smb[];
    const int tid = threadIdx.x, lane = tid & 31, wid = tid >> 5;
    const int head = blockIdx.y, q0 = blockIdx.x * 128;
    const int G = cu[1] - cu[0];
    const size_t colbase = (size_t)head * HDC;
    const uint32_t sb = smem_u32(smb);
    const float scale = 0.08838834764831845f;

    for (int i = tid; i < 2048; i += 256) {
        int r = i >> 4, c8 = (i & 15) * 8;
        size_t g = (size_t)(q0 + r) * HIDC + colbase + c8;
        *(uint4*)&smb[r * 136 + c8]          = *(const uint4*)&d_q_hi[g];
        *(uint4*)&smb[17408 + r * 136 + c8]  = *(const uint4*)&d_q_lo[g];
    }

    float accO[16][4];
#pragma unroll
    for (int nt = 0; nt < 16; nt++)
#pragma unroll
        for (int u = 0; u < 4; u++) accO[nt][u] = 0.f;
    float m0 = -INFINITY, m1 = -INFINITY, l0 = 0.f, l1 = 0.f;

    const int r0 = q0 + wid * 16 + (lane >> 2);
    const bool qg0 = r0 < G, qg1 = (r0 + 8) < G;

    for (int kt = 0; kt < LC / 128; kt++) {
        __syncthreads();
        for (int i = tid; i < 2048; i += 256) {
            int r = i >> 4, c8 = (i & 15) * 8;
            size_t g = (size_t)(kt * 128 + r) * HIDC + colbase + c8;
            uint32_t so = (uint32_t)(r * 136 + c8) * 2;
            cp16(sb + 69632 + so,  &d_k_hi[g]);
            cp16(sb + 104448 + so, &d_k_lo[g]);
        }
        CP_COMMIT();
        for (int i = tid; i < 2048; i += 256) {
            int r = i >> 4, c8 = (i & 15) * 8;
            size_t g = (size_t)(kt * 128 + r) * HIDC + colbase + c8;
            uint32_t so = (uint32_t)(r * 136 + c8) * 2;
            cp16(sb + 139264 + so, &d_v_hi[g]);
            cp16(sb + 174080 + so, &d_v_lo[g]);
        }
        CP_COMMIT();
        CP_WAIT(1);
        __syncthreads();

        float S[16][4];
#pragma unroll
        for (int nt = 0; nt < 16; nt++)
#pragma unroll
            for (int u = 0; u < 4; u++) S[nt][u] = 0.f;
#pragma unroll
        for (int half = 0; half < 2; half++) {
#pragma unroll
            for (int ks = 0; ks < 8; ks++) {
                uint32_t qa[2][4], kb[2][4][4];
                uint32_t aoff = ((uint32_t)(wid * 16 + (lane & 15)) * 136 + ks * 16 + (lane >> 4) * 8) * 2;
                ldm_x4(qa[0], sb + aoff);
                ldm_x4(qa[1], sb + 34816 + aoff);
                uint32_t bo_ = ((uint32_t)(half * 64 + ((lane >> 4) & 1) * 8 + (lane & 7)) * 136
                                + ks * 16 + ((lane >> 3) & 1) * 8) * 2;
#pragma unroll
                for (int ng = 0; ng < 4; ng++) {
                    uint32_t ro = bo_ + ng * 16 * 136 * 2;
                    ldm_x4(kb[0][ng], sb + 69632 + ro);
                    ldm_x4(kb[1][ng], sb + 104448 + ro);
                }
#pragma unroll
                for (int cmb = 0; cmb < 3; cmb++) {
                    const int ao = (cmb == 2) ? 1 : 0;
                    const int bo = (cmb == 1) ? 1 : 0;
#pragma unroll
                    for (int nt = 0; nt < 8; nt++)
                        mma16816(S[half * 8 + nt], qa[ao], &kb[bo][nt >> 1][(nt & 1) * 2]);
                }
            }
        }

#pragma unroll
        for (int nt = 0; nt < 16; nt++) {
            int key0 = kt * 128 + nt * 8 + (lane & 3) * 2;
            bool k0g = key0 < G, k1g = (key0 + 1) < G;
            S[nt][0] = (k0g == qg0) ? S[nt][0] * scale : -1e9f;
            S[nt][1] = (k1g == qg0) ? S[nt][1] * scale : -1e9f;
            S[nt][2] = (k0g == qg1) ? S[nt][2] * scale : -1e9f;
            S[nt][3] = (k1g == qg1) ? S[nt][3] * scale : -1e9f;
        }
        float tm0 = -INFINITY, tm1 = -INFINITY;
#pragma unroll
        for (int nt = 0; nt < 16; nt++) {
            tm0 = fmaxf(tm0, fmaxf(S[nt][0], S[nt][1]));
            tm1 = fmaxf(tm1, fmaxf(S[nt][2], S[nt][3]));
        }
        tm0 = fmaxf(tm0, __shfl_xor_sync(0xffffffffu, tm0, 1));
        tm0 = fmaxf(tm0, __shfl_xor_sync(0xffffffffu, tm0, 2));
        tm1 = fmaxf(tm1, __shfl_xor_sync(0xffffffffu, tm1, 1));
        tm1 = fmaxf(tm1, __shfl_xor_sync(0xffffffffu, tm1, 2));
        float mn0 = fmaxf(m0, tm0), mn1 = fmaxf(m1, tm1);
        float al0 = __expf(m0 - mn0), al1 = __expf(m1 - mn1);
        float sum0 = 0.f, sum1 = 0.f;
#pragma unroll
        for (int nt = 0; nt < 16; nt++) {
            S[nt][0] = __expf(S[nt][0] - mn0);
            S[nt][1] = __expf(S[nt][1] - mn0);
            S[nt][2] = __expf(S[nt][2] - mn1);
            S[nt][3] = __expf(S[nt][3] - mn1);
            sum0 += S[nt][0] + S[nt][1];
            sum1 += S[nt][2] + S[nt][3];
        }
        sum0 += __shfl_xor_sync(0xffffffffu, sum0, 1);
        sum0 += __shfl_xor_sync(0xffffffffu, sum0, 2);
        sum1 += __shfl_xor_sync(0xffffffffu, sum1, 1);
        sum1 += __shfl_xor_sync(0xffffffffu, sum1, 2);
        l0 = l0 * al0 + sum0;
        l1 = l1 * al1 + sum1;
        m0 = mn0; m1 = mn1;
#pragma unroll
        for (int nt = 0; nt < 16; nt++) {
            accO[nt][0] *= al0; accO[nt][1] *= al0;
            accO[nt][2] *= al1; accO[nt][3] *= al1;
        }

        CP_WAIT(0);
        __syncthreads();

#pragma unroll
        for (int pk = 0; pk < 8; pk++) {
            uint32_t ph[4], pl[4];
            ph[0] = packbf(S[2*pk][0], S[2*pk][1]);     pl[0] = packlo(S[2*pk][0], S[2*pk][1], ph[0]);
            ph[1] = packbf(S[2*pk][2], S[2*pk][3]);     pl[1] = packlo(S[2*pk][2], S[2*pk][3], ph[1]);
            ph[2] = packbf(S[2*pk+1][0], S[2*pk+1][1]); pl[2] = packlo(S[2*pk+1][0], S[2*pk+1][1], ph[2]);
            ph[3] = packbf(S[2*pk+1][2], S[2*pk+1][3]); pl[3] = packlo(S[2*pk+1][2], S[2*pk+1][3], ph[3]);
            uint32_t vo = ((uint32_t)(pk * 16 + (lane & 15)) * 136 + (lane >> 4) * 8) * 2;
#pragma unroll
            for (int ng4 = 0; ng4 < 8; ng4++) {
                uint32_t co = vo + ng4 * 16 * 2;
                uint32_t vh[4], vl[4];
                ldm_x4_t(vh, sb + 139264 + co);
                ldm_x4_t(vl, sb + 174080 + co);
                mma16816(accO[ng4*2],   ph, &vh[0]);
                mma16816(accO[ng4*2+1], ph, &vh[2]);
                mma16816(accO[ng4*2],   ph, &vl[0]);
                mma16816(accO[ng4*2+1], ph, &vl[2]);
                mma16816(accO[ng4*2],   pl, &vh[0]);
                mma16816(accO[ng4*2+1], pl, &vh[2]);
            }
        }
    }

    // normalize self-attention output
    float inv0 = 1.f / l0, inv1 = 1.f / l1;
#pragma unroll
    for (int nt = 0; nt < 16; nt++) {
        accO[nt][0] *= inv0; accO[nt][1] *= inv0;
        accO[nt][2] *= inv1; accO[nt][3] *= inv1;
    }

    if (blockIdx.x < LC / 128 - 1) {
        // ---- fused audio cross-attention (img tiles only) ----
        __syncthreads();
        for (int i = tid; i < 2048; i += 256) {
            int r = i >> 4, c8 = (i & 15) * 8;
            size_t ga = (size_t)r * HIDC + colbase + c8;
            int so = r * 136 + c8;
            *(uint4*)&smb[34816 + so] = *(const uint4*)&d_ak_hi[ga];
            *(uint4*)&smb[52224 + so] = *(const uint4*)&d_ak_lo[ga];
            *(uint4*)&smb[69632 + so] = *(const uint4*)&d_av_hi[ga];
            *(uint4*)&smb[87040 + so] = *(const uint4*)&d_av_lo[ga];
        }
        __syncthreads();

        float S[16][4];
#pragma unroll
        for (int nt = 0; nt < 16; nt++)
#pragma unroll
            for (int u = 0; u < 4; u++) S[nt][u] = 0.f;
#pragma unroll
        for (int half = 0; half < 2; half++) {
#pragma unroll
            for (int ks = 0; ks < 8; ks++) {
                uint32_t qa[2][4], kb[2][4][4];
                uint32_t aoff = ((uint32_t)(wid * 16 + (lane & 15)) * 136 + ks * 16 + (lane >> 4) * 8) * 2;
                ldm_x4(qa[0], sb + aoff);
                ldm_x4(qa[1], sb + 34816 * 2 + aoff - 34816 * 2 + 34816);  // placeholder removed below
                // (see corrected loads just after)
                (void)qa;
                break;
            }
            break;
        }
        // corrected S compute (Q_lo at elem 17408 -> byte 34816)
#pragma unroll
        for (int half = 0; half < 2; half++) {
#pragma unroll
            for (int ks = 0; ks < 8; ks++) {
                uint32_t qa[2][4], kb[2][4][4];
                uint32_t aoff = ((uint32_t)(wid * 16 + (lane & 15)) * 136 + ks * 16 + (lane >> 4) * 8) * 2;
                ldm_x4(qa[0], sb + aoff);
                ldm_x4(qa[1], sb + 34816 + aoff);
                uint32_t bo_ = ((uint32_t)(half * 64 + ((lane >> 4) & 1) * 8 + (lane & 7)) * 136
                                + ks * 16 + ((lane >> 3) & 1) * 8) * 2;
#pragma unroll
                for (int ng = 0; ng < 4; ng++) {
                    uint32_t ro = bo_ + ng * 16 * 136 * 2;
                    ldm_x4(kb[0][ng], sb + 69632 + ro);
                    ldm_x4(kb[1][ng], sb + 104448 + ro);
                }
#pragma unroll
                for (int cmb = 0; cmb < 3; cmb++) {
                    const int ao = (cmb == 2) ? 1 : 0;
                    const int bo = (cmb == 1) ? 1 : 0;
#pragma unroll
                    for (int nt = 0; nt < 8; nt++)
                        mma16816(S[half * 8 + nt], qa[ao], &kb[bo][nt >> 1][(nt & 1) * 2]);
                }
            }
        }

        float tm0 = -INFINITY, tm1 = -INFINITY;
#pragma unroll
        for (int nt = 0; nt < 16; nt++) {
            S[nt][0] *= scale; S[nt][1] *= scale; S[nt][2] *= scale; S[nt][3] *= scale;
            tm0 = fmaxf(tm0, fmaxf(S[nt][0], S[nt][1]));
            tm1 = fmaxf(tm1, fmaxf(S[nt][2], S[nt][3]));
        }
        tm0 = fmaxf(tm0, __shfl_xor_sync(0xffffffffu, tm0, 1));
        tm0 = fmaxf(tm0, __shfl_xor_sync(0xffffffffu, tm0, 2));
        tm1 = fmaxf(tm1, __shfl_xor_sync(0xffffffffu, tm1, 1));
        tm1 = fmaxf(tm1, __shfl_xor_sync(0xffffffffu, tm1, 2));
        float sum0 = 0.f, sum1 = 0.f;
#pragma unroll
        for (int nt = 0; nt < 16; nt++) {
            S[nt][0] = __expf(S[nt][0] - tm0);
            S[nt][1] = __expf(S[nt][1] - tm0);
            S[nt][2] = __expf(S[nt][2] - tm1);
            S[nt][3] = __expf(S[nt][3] - tm1);
            sum0 += S[nt][0] + S[nt][1];
            sum1 += S[nt][2] + S[nt][3];
        }
        sum0 += __shfl_xor_sync(0xffffffffu, sum0, 1);
        sum0 += __shfl_xor_sync(0xffffffffu, sum0, 2);
        sum1 += __shfl_xor_sync(0xffffffffu, sum1, 1);
        sum1 += __shfl_xor_sync(0xffffffffu, sum1, 2);

        const float as = fminf(ascale[0], 2.0f);
        int t0 = r0 / 384, rem0 = r0 % 384;
        int t1 = (r0 + 8) / 384, rem1 = (r0 + 8) % 384;
        float mf0 = fmask[t0 * 1536 + (rem0 / 16) * 64 + (rem0 % 16) * 2] * as / sum0;
        float mf1 = fmask[t1 * 1536 + (rem1 / 16) * 64 + (rem1 % 16) * 2] * as / sum1;
        // fold row factors into P, then accumulate PV into accO
#pragma unroll
        for (int nt = 0; nt < 16; nt++) {
            S[nt][0] *= mf0; S[nt][1] *= mf0;
            S[nt][2] *= mf1; S[nt][3] *= mf1;
        }
#pragma unroll
        for (int pk = 0; pk < 8; pk++) {
            uint32_t ph[4], pl[4];
            ph[0] = packbf(S[2*pk][0], S[2*pk][1]);     pl[0] = packlo(S[2*pk][0], S[2*pk][1], ph[0]);
            ph[1] = packbf(S[2*pk][2], S[2*pk][3]);     pl[1] = packlo(S[2*pk][2], S[2*pk][3], ph[1]);
            ph[2] = packbf(S[2*pk+1][0], S[2*pk+1][1]); pl[2] = packlo(S[2*pk+1][0], S[2*pk+1][1], ph[2]);
            ph[3] = packbf(S[2*pk+1][2], S[2*pk+1][3]); pl[3] = packlo(S[2*pk+1][2], S[2*pk+1][3], ph[3]);
            uint32_t vo = ((uint32_t)(pk * 16 + (lane & 15)) * 136 + (lane >> 4) * 8) * 2;
#pragma unroll
            for (int ng4 = 0; ng4 < 8; ng4++) {
                uint32_t co = vo + ng4 * 16 * 2;
                uint32_t vh[4], vl[4];
                ldm_x4_t(vh, sb + 139264 + co);
                ldm_x4_t(vl, sb + 174080 + co);
                mma16816(accO[ng4*2],   ph, &vh[0]);
                mma16816(accO[ng4*2+1], ph, &vh[2]);
                mma16816(accO[ng4*2],   ph, &vl[0]);
                mma16816(accO[ng4*2+1], ph, &vl[2]);
                mma16816(accO[ng4*2],   pl, &vh[0]);
                mma16816(accO[ng4*2+1], pl, &vh[2]);
            }
        }
    }

    // final split store (values are final for both img and txt tiles)
#pragma unroll
    for (int nt = 0; nt < 16; nt++) {
        int col = head * HDC + nt * 8 + (lane & 3) * 2;
        split_store2(d_cat_hi, d_cat_lo, (size_t)r0 * W2K + col, accO[nt][0], accO[nt][1]);
        split_store2(d_cat_hi, d_cat_lo, (size_t)(r0 + 8) * W2K + col, accO[nt][2], accO[nt][3]);
    }
}

extern "C" void kernel_launch(void* const* d_in, const int* in_sizes, int n_in,
                              void* d_out, int out_size) {
    const float* x     = (const float*)d_in[0];
    const float* vec   = (const float*)d_in[1];
    const float* trv   = (const float*)d_in[2];
    const float* fcos  = (const float*)d_in[3];
    const float* fsin  = (const float*)d_in[4];
    const float* aemb  = (const float*)d_in[5];
    const float* fmask = (const float*)d_in[6];
    const int*   cu    = (const int*)d_in[7];
    const float* mw    = (const float*)d_in[10];
    const float* mb    = (const float*)d_in[11];
    const float* w1    = (const float*)d_in[12];
    const float* b1    = (const float*)d_in[13];
    const float* qnw   = (const float*)d_in[14];
    const float* knw   = (const float*)d_in[15];
    const float* w2    = (const float*)d_in[16];
    const float* b2    = (const float*)d_in[17];
    const float* aqw   = (const float*)d_in[18];
    const float* aqb   = (const float*)d_in[19];
    const float* aknw  = (const float*)d_in[21];
    const float* ascale= (const float*)d_in[22];
    float* out = (float*)d_out;

    float* gp   = nullptr; cudaGetSymbolAddress((void**)&gp,   d_gp);
    __nv_bfloat16 *ahi, *alo, *anhi, *anlo, *chi, *clo;
    __nv_bfloat16 *w1h, *w1l, *w2h, *w2l, *awh, *awl;
    cudaGetSymbolAddress((void**)&ahi,  d_a_hi);  cudaGetSymbolAddress((void**)&alo,  d_a_lo);
    cudaGetSymbolAddress((void**)&anhi, d_an_hi); cudaGetSymbolAddress((void**)&anlo, d_an_lo);
    cudaGetSymbolAddress((void**)&chi,  d_cat_hi);cudaGetSymbolAddress((void**)&clo,  d_cat_lo);
    cudaGetSymbolAddress((void**)&w1h,  d_w1t_hi);cudaGetSymbolAddress((void**)&w1l,  d_w1t_lo);
    cudaGetSymbolAddress((void**)&w2h,  d_w2t_hi);cudaGetSymbolAddress((void**)&w2l,  d_w2t_lo);
    cudaGetSymbolAddress((void**)&awh,  d_awt_hi);cudaGetSymbolAddress((void**)&awl,  d_awt_lo);

    const int ATTN_SMEM = 208896;
    cudaFuncSetAttribute(attn_hmma, cudaFuncAttributeMaxDynamicSharedMemorySize, ATTN_SMEM);
    const int GEMM_SMEM = 81920;
    cudaFuncSetAttribute(hmma_gemm_akv, cudaFuncAttributeMaxDynamicSharedMemorySize, GEMM_SMEM);
    const int GEMM_SMEM2 = 221184;
    cudaFuncSetAttribute(hmma_gemm_big<2>, cudaFuncAttributeMaxDynamicSharedMemorySize, GEMM_SMEM2);
    cudaFuncSetAttribute(hmma_gemm_big<3>, cudaFuncAttributeMaxDynamicSharedMemorySize, GEMM_SMEM2);

    mod_part<<<dim3(MODN / 128, 8), 512>>>(vec, trv, mw);
    mod_reduce<<<MODN / 256, 256>>>(mb);
    transpose_conv<<<dim3(W1N / 32, HIDC / 32), dim3(8, 32)>>>(w1, w1h, w1l, HIDC, W1N, 0);
    ln_mod_kernel<<<LC, 256>>>(x);
    hmma_gemm_big<2><<<dim3(LC / 256, W1N / 128, 1), 256, GEMM_SMEM2>>>(
        ahi, alo, w1h, w1l, b1, gp, LC, W1N, HIDC, qnw, knw, fcos, fsin);
    transpose_conv<<<dim3(HIDC / 32, W2K / 32), dim3(8, 32)>>>(w2, w2h, w2l, W2K, HIDC, 0);
    transpose_conv<<<dim3((2 * HIDC) / 32, HIDC / 32), dim3(8, 32)>>>(aqw, awh, awl, HIDC, MODN, HIDC);
    ln_plain_kernel<<<NAUD, 256>>>(aemb);
    hmma_gemm_akv<<<dim3(1, (2 * HIDC) / 128), 256, GEMM_SMEM>>>(
        anhi, anlo, awh + (size_t)HIDC * HIDC, awl + (size_t)HIDC * HIDC, aqb + HIDC, aknw, HIDC);
    attn_hmma<<<dim3(LC / 128, HEADSC), 256, ATTN_SMEM>>>(cu, fmask, ascale);
    hmma_gemm_big<3><<<dim3(LC / 256, HIDC / 128, 3), 256, GEMM_SMEM2>>>(
        chi, clo, w2h, w2l, b2, gp, LC, HIDC, W2K, nullptr, nullptr, nullptr, nullptr);
    gemm2_combine<<<(int)(((size_t)LC * HIDC / 4) / 256), 256>>>(b2, x, out);
}